// round 1
// baseline (speedup 1.0000x reference)
#include <cuda_runtime.h>

// Problem dims (fixed by the dataset)
#define NB   4
#define SEQ  2048
#define EDIM 1024
#define H3   3072     // 3*EDIM
#define NH   16
#define DH   64       // head dim
#define NTOK (NB*SEQ) // 8192

// Scratch (device globals: allocation-free, graph-capture safe)
__device__ float g_H[(size_t)NTOK * H3];    // QKV projections  (~100.7 MB)
__device__ float g_ATT[(size_t)NTOK * EDIM]; // attention output (~33.5 MB)

// ---------------------------------------------------------------------------
// SGEMM: C[M,N] = A[M,K] @ B[K,N] + bias[N]
// A,B,C row-major. M%128==0, N%128==0, K%8==0 (true for all our calls).
// 128x128 block tile, BK=8, 256 threads, 8x8 per-thread microtile (2x2 of 4x4).
// ---------------------------------------------------------------------------
__global__ __launch_bounds__(256, 2)
void sgemm_bias(const float* __restrict__ A,
                const float* __restrict__ B,
                const float* __restrict__ bias,
                float* __restrict__ C,
                int M, int N, int K)
{
    __shared__ float As[8][128];
    __shared__ float Bs[8][128];

    const int tid = threadIdx.x;
    const int bm  = blockIdx.y;
    const int bn  = blockIdx.x;

    // A-tile load mapping: 128 rows x 8 cols, one float4 per thread
    const int aRow = tid >> 1;          // 0..127
    const int aCol = (tid & 1) << 2;    // 0 or 4
    // B-tile load mapping: 8 rows x 128 cols, one float4 per thread
    const int bRow = tid >> 5;          // 0..7
    const int bCol = (tid & 31) << 2;   // 0..124

    const float* Abase = A + (size_t)(bm * 128 + aRow) * K + aCol;
    const float* Bbase = B + (size_t)bn * 128 + bCol;

    const int tx = tid & 15;            // 0..15 (cols)
    const int ty = tid >> 4;            // 0..15 (rows)

    float acc[8][8];
    #pragma unroll
    for (int i = 0; i < 8; i++)
        #pragma unroll
        for (int j = 0; j < 8; j++) acc[i][j] = 0.f;

    for (int k0 = 0; k0 < K; k0 += 8) {
        // load A tile (transposed into As[k][m])
        float4 av = *(const float4*)(Abase + k0);
        As[aCol + 0][aRow] = av.x;
        As[aCol + 1][aRow] = av.y;
        As[aCol + 2][aRow] = av.z;
        As[aCol + 3][aRow] = av.w;
        // load B tile
        float4 bv = *(const float4*)(Bbase + (size_t)(k0 + bRow) * N);
        *(float4*)&Bs[bRow][bCol] = bv;
        __syncthreads();

        #pragma unroll
        for (int kk = 0; kk < 8; kk++) {
            float4 a0 = *(const float4*)&As[kk][ty * 4];
            float4 a1 = *(const float4*)&As[kk][64 + ty * 4];
            float4 b0 = *(const float4*)&Bs[kk][tx * 4];
            float4 b1 = *(const float4*)&Bs[kk][64 + tx * 4];
            float ar[8] = {a0.x, a0.y, a0.z, a0.w, a1.x, a1.y, a1.z, a1.w};
            float br[8] = {b0.x, b0.y, b0.z, b0.w, b1.x, b1.y, b1.z, b1.w};
            #pragma unroll
            for (int i = 0; i < 8; i++)
                #pragma unroll
                for (int j = 0; j < 8; j++)
                    acc[i][j] += ar[i] * br[j];
        }
        __syncthreads();
    }

    // epilogue with bias
    const int c0 = bn * 128 + tx * 4;
    float4 biasA = *(const float4*)(bias + c0);
    float4 biasB = *(const float4*)(bias + c0 + 64);
    #pragma unroll
    for (int i = 0; i < 8; i++) {
        int row = bm * 128 + ((i < 4) ? (ty * 4 + i) : (64 + ty * 4 + i - 4));
        float* crow = C + (size_t)row * N + c0;
        float4 va, vb;
        va.x = acc[i][0] + biasA.x;
        va.y = acc[i][1] + biasA.y;
        va.z = acc[i][2] + biasA.z;
        va.w = acc[i][3] + biasA.w;
        vb.x = acc[i][4] + biasB.x;
        vb.y = acc[i][5] + biasB.y;
        vb.z = acc[i][6] + biasB.z;
        vb.w = acc[i][7] + biasB.w;
        *(float4*)crow        = va;
        *(float4*)(crow + 64) = vb;
    }
}

// ---------------------------------------------------------------------------
// Flash-style attention (fp32, streaming softmax).
// grid = (SEQ/128, NH, NB), block = 128 threads; 1 thread = 1 query row.
// K/V tiles of 64 rows cached in smem; 8-key online-softmax chunks.
// g_H layout per token: [h*192 + 0:64]=q, [+64:128]=k, [+128:192]=v
// ---------------------------------------------------------------------------
__global__ __launch_bounds__(128)
void attn_kernel(const float* __restrict__ Hqkv, float* __restrict__ Out)
{
    const int qb  = blockIdx.x;   // query block
    const int h   = blockIdx.y;   // head
    const int n   = blockIdx.z;   // batch
    const int tid = threadIdx.x;
    const int qi  = qb * 128 + tid;

    const float* base = Hqkv + (size_t)n * SEQ * H3;
    const float* qptr = base + (size_t)qi * H3 + h * 192;

    __shared__ float4 Ks[64 * 16];   // 64 keys x 64 dims
    __shared__ float4 Vs[64 * 16];

    float4 q4[16];
    #pragma unroll
    for (int c = 0; c < 16; c++) q4[c] = *(const float4*)(qptr + c * 4);

    float4 o4[16];
    #pragma unroll
    for (int c = 0; c < 16; c++) o4[c] = make_float4(0.f, 0.f, 0.f, 0.f);

    float m = -1e30f, l = 0.f;
    const float scale = 0.125f;   // 1/sqrt(64)

    for (int t = 0; t < SEQ; t += 64) {
        // cooperative K/V tile load: 1024 float4 each, 8 per thread
        #pragma unroll
        for (int r = 0; r < 8; r++) {
            int idx = r * 128 + tid;       // 0..1023
            int row = idx >> 4;            // 0..63
            int c   = idx & 15;            // 0..15
            const float* kp = base + (size_t)(t + row) * H3 + h * 192 + 64 + c * 4;
            Ks[idx] = *(const float4*)kp;
            Vs[idx] = *(const float4*)(kp + 64);
        }
        __syncthreads();

        #pragma unroll 1
        for (int j0 = 0; j0 < 64; j0 += 8) {
            float s[8];
            #pragma unroll
            for (int jj = 0; jj < 8; jj++) {
                const float4* kr = &Ks[(j0 + jj) * 16];
                float acc = 0.f;
                #pragma unroll
                for (int c = 0; c < 16; c++) {
                    float4 kv = kr[c];
                    acc += q4[c].x * kv.x + q4[c].y * kv.y
                         + q4[c].z * kv.z + q4[c].w * kv.w;
                }
                s[jj] = acc * scale;
            }
            float cm = s[0];
            #pragma unroll
            for (int jj = 1; jj < 8; jj++) cm = fmaxf(cm, s[jj]);
            float mn = fmaxf(m, cm);
            float alpha = __expf(m - mn);
            m = mn;
            l *= alpha;
            #pragma unroll
            for (int c = 0; c < 16; c++) {
                o4[c].x *= alpha; o4[c].y *= alpha;
                o4[c].z *= alpha; o4[c].w *= alpha;
            }
            #pragma unroll
            for (int jj = 0; jj < 8; jj++) {
                float p = __expf(s[jj] - mn);
                l += p;
                const float4* vr = &Vs[(j0 + jj) * 16];
                #pragma unroll
                for (int c = 0; c < 16; c++) {
                    float4 vv = vr[c];
                    o4[c].x += p * vv.x; o4[c].y += p * vv.y;
                    o4[c].z += p * vv.z; o4[c].w += p * vv.w;
                }
            }
        }
        __syncthreads();
    }

    const float inv = 1.f / l;
    float* op = Out + (size_t)(n * SEQ + qi) * EDIM + h * DH;
    #pragma unroll
    for (int c = 0; c < 16; c++) {
        float4 v = o4[c];
        v.x *= inv; v.y *= inv; v.z *= inv; v.w *= inv;
        *(float4*)(op + c * 4) = v;
    }
}

// ---------------------------------------------------------------------------
extern "C" void kernel_launch(void* const* d_in, const int* in_sizes, int n_in,
                              void* d_out, int out_size)
{
    const float* x  = (const float*)d_in[0];   // (4,2048,1024)
    const float* W1 = (const float*)d_in[1];   // (1024,3072)
    const float* b1 = (const float*)d_in[2];   // (3072,)
    const float* W2 = (const float*)d_in[3];   // (1024,1024)
    const float* b2 = (const float*)d_in[4];   // (1024,)
    float* out = (float*)d_out;                // (4,2048,1024)

    float *Hbuf = nullptr, *Abuf = nullptr;
    cudaGetSymbolAddress((void**)&Hbuf, g_H);
    cudaGetSymbolAddress((void**)&Abuf, g_ATT);

    // 1) QKV projection: g_H = x @ W1 + b1   [8192, 3072]
    sgemm_bias<<<dim3(H3 / 128, NTOK / 128), 256>>>(x, W1, b1, Hbuf,
                                                    NTOK, H3, EDIM);
    // 2) multi-head attention -> g_ATT  [8192, 1024]
    attn_kernel<<<dim3(SEQ / 128, NH, NB), 128>>>(Hbuf, Abuf);
    // 3) output projection: out = g_ATT @ W2 + b2  [8192, 1024]
    sgemm_bias<<<dim3(EDIM / 128, NTOK / 128), 256>>>(Abuf, W2, b2, out,
                                                      NTOK, EDIM, EDIM);
}

// round 2
// speedup vs baseline: 3.2997x; 3.2997x over previous
#include <cuda_runtime.h>
#include <cstdint>

// Problem dims (fixed by the dataset)
#define NB   4
#define SEQ  2048
#define EDIM 1024
#define H3   3072
#define NH   16
#define NTOK (NB*SEQ)

// Scratch (device globals: allocation-free, graph-capture safe)
__device__ float g_H[(size_t)NTOK * H3];     // QKV projections
__device__ float g_ATT[(size_t)NTOK * EDIM]; // attention output

// Round fp32 -> tf32 (round-to-nearest; mma itself truncates, which biases)
__device__ __forceinline__ float to_tf32(float x) {
    uint32_t u;
    asm("cvt.rna.tf32.f32 %0, %1;" : "=r"(u) : "f"(x));
    return __uint_as_float(u);
}

__device__ __forceinline__ void mma_tf32(float d[4],
                                         uint32_t a0, uint32_t a1, uint32_t a2, uint32_t a3,
                                         uint32_t b0, uint32_t b1) {
    asm volatile(
        "mma.sync.aligned.m16n8k8.row.col.f32.tf32.tf32.f32 "
        "{%0,%1,%2,%3}, {%4,%5,%6,%7}, {%8,%9}, {%0,%1,%2,%3};"
        : "+f"(d[0]), "+f"(d[1]), "+f"(d[2]), "+f"(d[3])
        : "r"(a0), "r"(a1), "r"(a2), "r"(a3), "r"(b0), "r"(b1));
}

// ---------------------------------------------------------------------------
// TF32 GEMM: C[M,N] = A[M,K] @ B[K,N] + bias[N]
// 128x128x32 block tile, 256 threads (8 warps), warp tile 64x32 via m16n8k8.
// ---------------------------------------------------------------------------
__global__ __launch_bounds__(256, 2)
void gemm_tf32(const float* __restrict__ A, const float* __restrict__ B,
               const float* __restrict__ bias, float* __restrict__ C,
               int M, int N, int K)
{
    __shared__ float As[128][36];   // row-major A tile [m][k], pad 36 (conflict-free frags)
    __shared__ float Bs[32][136];   // row-major B tile [k][n], pad 136

    const int tid  = threadIdx.x;
    const int bm   = blockIdx.y, bn = blockIdx.x;
    const int warp = tid >> 5, lane = tid & 31;
    const int wm   = (warp >> 2) * 64;   // warp m origin (2 rows of warps)
    const int wn   = (warp & 3) * 32;    // warp n origin (4 cols of warps)
    const int lr   = lane >> 2, lc = lane & 3;

    float d[4][4][4];
    #pragma unroll
    for (int mt = 0; mt < 4; mt++)
        #pragma unroll
        for (int nt = 0; nt < 4; nt++)
            #pragma unroll
            for (int r = 0; r < 4; r++) d[mt][nt][r] = 0.f;

    for (int k0 = 0; k0 < K; k0 += 32) {
        // A tile: 128 rows x 32 cols, float4 per thread x4
        #pragma unroll
        for (int i = 0; i < 4; i++) {
            int idx = i * 256 + tid;
            int r = idx >> 3, kc = idx & 7;
            float4 v = *(const float4*)(A + (size_t)(bm * 128 + r) * K + k0 + kc * 4);
            float4 w;
            w.x = to_tf32(v.x); w.y = to_tf32(v.y);
            w.z = to_tf32(v.z); w.w = to_tf32(v.w);
            *(float4*)&As[r][kc * 4] = w;
        }
        // B tile: 32 rows x 128 cols
        #pragma unroll
        for (int i = 0; i < 4; i++) {
            int idx = i * 256 + tid;
            int r = idx >> 5, nc = idx & 31;
            float4 v = *(const float4*)(B + (size_t)(k0 + r) * N + bn * 128 + nc * 4);
            float4 w;
            w.x = to_tf32(v.x); w.y = to_tf32(v.y);
            w.z = to_tf32(v.z); w.w = to_tf32(v.w);
            *(float4*)&Bs[r][nc * 4] = w;
        }
        __syncthreads();

        #pragma unroll
        for (int ks = 0; ks < 4; ks++) {
            uint32_t a[4][4], b[4][2];
            #pragma unroll
            for (int mt = 0; mt < 4; mt++) {
                int r = wm + mt * 16 + lr, c = ks * 8 + lc;
                a[mt][0] = __float_as_uint(As[r][c]);
                a[mt][1] = __float_as_uint(As[r + 8][c]);
                a[mt][2] = __float_as_uint(As[r][c + 4]);
                a[mt][3] = __float_as_uint(As[r + 8][c + 4]);
            }
            #pragma unroll
            for (int nt = 0; nt < 4; nt++) {
                int nn = wn + nt * 8 + lr, kk = ks * 8 + lc;
                b[nt][0] = __float_as_uint(Bs[kk][nn]);
                b[nt][1] = __float_as_uint(Bs[kk + 4][nn]);
            }
            #pragma unroll
            for (int mt = 0; mt < 4; mt++)
                #pragma unroll
                for (int nt = 0; nt < 4; nt++)
                    mma_tf32(d[mt][nt], a[mt][0], a[mt][1], a[mt][2], a[mt][3],
                             b[nt][0], b[nt][1]);
        }
        __syncthreads();
    }

    // epilogue with bias
    #pragma unroll
    for (int mt = 0; mt < 4; mt++) {
        #pragma unroll
        for (int nt = 0; nt < 4; nt++) {
            int row = bm * 128 + wm + mt * 16 + lr;
            int col = bn * 128 + wn + nt * 8 + 2 * lc;
            float2 bv = *(const float2*)(bias + col);
            float2 v0 = make_float2(d[mt][nt][0] + bv.x, d[mt][nt][1] + bv.y);
            float2 v1 = make_float2(d[mt][nt][2] + bv.x, d[mt][nt][3] + bv.y);
            *(float2*)(C + (size_t)row * N + col)       = v0;
            *(float2*)(C + (size_t)(row + 8) * N + col) = v1;
        }
    }
}

// ---------------------------------------------------------------------------
// Flash attention, TF32 tensor cores.
// grid=(SEQ/64, NH, NB), block=128 (4 warps x 16 query rows).
// smem (dynamic): Qs[64][68] Ks[64][68] Vs[64][72] Ps[64][68]
// ---------------------------------------------------------------------------
__global__ __launch_bounds__(128)
void attn_tf32(const float* __restrict__ Hqkv, float* __restrict__ Out)
{
    extern __shared__ float smp[];
    float* Qs = smp;                 // [64][68]
    float* Ks = Qs + 64 * 68;        // [64][68]
    float* Vs = Ks + 64 * 68;        // [64][72]
    float* Ps = Vs + 64 * 72;        // [64][68]

    const int qb = blockIdx.x, h = blockIdx.y, n = blockIdx.z;
    const int tid = threadIdx.x, warp = tid >> 5, lane = tid & 31;
    const int lr = lane >> 2, lc = lane & 3;
    const float* base = Hqkv + (size_t)n * SEQ * H3 + h * 192;

    // stage Q tile (pre-scaled by 1/sqrt(64), tf32-rounded)
    #pragma unroll
    for (int i = 0; i < 8; i++) {
        int idx = i * 128 + tid;
        int r = idx >> 4, c = idx & 15;
        float4 v = *(const float4*)(base + (size_t)(qb * 64 + r) * H3 + c * 4);
        float4 w;
        w.x = to_tf32(0.125f * v.x); w.y = to_tf32(0.125f * v.y);
        w.z = to_tf32(0.125f * v.z); w.w = to_tf32(0.125f * v.w);
        *(float4*)&Qs[r * 68 + c * 4] = w;
    }
    __syncthreads();

    // hoist Q fragments (constant over key loop)
    const int qr = warp * 16 + lr;
    uint32_t aq[8][4];
    #pragma unroll
    for (int kt = 0; kt < 8; kt++) {
        int c = kt * 8 + lc;
        aq[kt][0] = __float_as_uint(Qs[qr * 68 + c]);
        aq[kt][1] = __float_as_uint(Qs[(qr + 8) * 68 + c]);
        aq[kt][2] = __float_as_uint(Qs[qr * 68 + c + 4]);
        aq[kt][3] = __float_as_uint(Qs[(qr + 8) * 68 + c + 4]);
    }

    float o[8][4];
    #pragma unroll
    for (int nt = 0; nt < 8; nt++)
        #pragma unroll
        for (int r = 0; r < 4; r++) o[nt][r] = 0.f;
    float m0 = -1e30f, m1 = -1e30f, l0 = 0.f, l1 = 0.f;

    for (int t = 0; t < SEQ; t += 64) {
        __syncthreads();   // previous tile's K/V reads done
        #pragma unroll
        for (int i = 0; i < 8; i++) {
            int idx = i * 128 + tid;
            int r = idx >> 4, c = idx & 15;
            const float* kp = base + (size_t)(t + r) * H3 + 64 + c * 4;
            float4 kv = *(const float4*)kp;
            float4 vv = *(const float4*)(kp + 64);
            float4 kw, vw;
            kw.x = to_tf32(kv.x); kw.y = to_tf32(kv.y);
            kw.z = to_tf32(kv.z); kw.w = to_tf32(kv.w);
            vw.x = to_tf32(vv.x); vw.y = to_tf32(vv.y);
            vw.z = to_tf32(vv.z); vw.w = to_tf32(vv.w);
            *(float4*)&Ks[r * 68 + c * 4] = kw;
            *(float4*)&Vs[r * 72 + c * 4] = vw;
        }
        __syncthreads();

        // S = Q @ K^T  (warp: 16 x 64)
        float s[8][4];
        #pragma unroll
        for (int nt = 0; nt < 8; nt++)
            #pragma unroll
            for (int r = 0; r < 4; r++) s[nt][r] = 0.f;
        #pragma unroll
        for (int kt = 0; kt < 8; kt++) {
            #pragma unroll
            for (int nt = 0; nt < 8; nt++) {
                uint32_t b0 = __float_as_uint(Ks[(nt * 8 + lr) * 68 + kt * 8 + lc]);
                uint32_t b1 = __float_as_uint(Ks[(nt * 8 + lr) * 68 + kt * 8 + lc + 4]);
                mma_tf32(s[nt], aq[kt][0], aq[kt][1], aq[kt][2], aq[kt][3], b0, b1);
            }
        }

        // online softmax (rows qr and qr+8; stats shared across lane quads)
        float mx0 = s[0][0], mx1 = s[0][2];
        #pragma unroll
        for (int nt = 0; nt < 8; nt++) {
            mx0 = fmaxf(mx0, fmaxf(s[nt][0], s[nt][1]));
            mx1 = fmaxf(mx1, fmaxf(s[nt][2], s[nt][3]));
        }
        mx0 = fmaxf(mx0, __shfl_xor_sync(0xffffffffu, mx0, 1));
        mx0 = fmaxf(mx0, __shfl_xor_sync(0xffffffffu, mx0, 2));
        mx1 = fmaxf(mx1, __shfl_xor_sync(0xffffffffu, mx1, 1));
        mx1 = fmaxf(mx1, __shfl_xor_sync(0xffffffffu, mx1, 2));
        float nm0 = fmaxf(m0, mx0), nm1 = fmaxf(m1, mx1);
        float al0 = __expf(m0 - nm0), al1 = __expf(m1 - nm1);
        m0 = nm0; m1 = nm1;
        float sum0 = 0.f, sum1 = 0.f;
        #pragma unroll
        for (int nt = 0; nt < 8; nt++) {
            s[nt][0] = __expf(s[nt][0] - m0);
            s[nt][1] = __expf(s[nt][1] - m0);
            s[nt][2] = __expf(s[nt][2] - m1);
            s[nt][3] = __expf(s[nt][3] - m1);
            sum0 += s[nt][0] + s[nt][1];
            sum1 += s[nt][2] + s[nt][3];
            o[nt][0] *= al0; o[nt][1] *= al0;
            o[nt][2] *= al1; o[nt][3] *= al1;
        }
        sum0 += __shfl_xor_sync(0xffffffffu, sum0, 1);
        sum0 += __shfl_xor_sync(0xffffffffu, sum0, 2);
        sum1 += __shfl_xor_sync(0xffffffffu, sum1, 1);
        sum1 += __shfl_xor_sync(0xffffffffu, sum1, 2);
        l0 = l0 * al0 + sum0;
        l1 = l1 * al1 + sum1;

        // P -> smem (C-frag layout != A-frag layout for tf32)
        #pragma unroll
        for (int nt = 0; nt < 8; nt++) {
            int col = nt * 8 + 2 * lc;
            float2 p0 = make_float2(to_tf32(s[nt][0]), to_tf32(s[nt][1]));
            float2 p1 = make_float2(to_tf32(s[nt][2]), to_tf32(s[nt][3]));
            *(float2*)&Ps[qr * 68 + col]       = p0;
            *(float2*)&Ps[(qr + 8) * 68 + col] = p1;
        }
        __syncwarp();

        // O += P @ V
        #pragma unroll
        for (int kt = 0; kt < 8; kt++) {
            uint32_t a0 = __float_as_uint(Ps[qr * 68 + kt * 8 + lc]);
            uint32_t a1 = __float_as_uint(Ps[(qr + 8) * 68 + kt * 8 + lc]);
            uint32_t a2 = __float_as_uint(Ps[qr * 68 + kt * 8 + lc + 4]);
            uint32_t a3 = __float_as_uint(Ps[(qr + 8) * 68 + kt * 8 + lc + 4]);
            #pragma unroll
            for (int nt = 0; nt < 8; nt++) {
                uint32_t b0 = __float_as_uint(Vs[(kt * 8 + lc) * 72 + nt * 8 + lr]);
                uint32_t b1 = __float_as_uint(Vs[(kt * 8 + lc + 4) * 72 + nt * 8 + lr]);
                mma_tf32(o[nt], a0, a1, a2, a3, b0, b1);
            }
        }
    }

    // epilogue
    float inv0 = 1.f / l0, inv1 = 1.f / l1;
    float* op0 = Out + (size_t)(n * SEQ + qb * 64 + qr) * EDIM + h * 64;
    float* op1 = op0 + (size_t)8 * EDIM;
    #pragma unroll
    for (int nt = 0; nt < 8; nt++) {
        int col = nt * 8 + 2 * lc;
        float2 v0 = make_float2(o[nt][0] * inv0, o[nt][1] * inv0);
        float2 v1 = make_float2(o[nt][2] * inv1, o[nt][3] * inv1);
        *(float2*)(op0 + col) = v0;
        *(float2*)(op1 + col) = v1;
    }
}

// ---------------------------------------------------------------------------
extern "C" void kernel_launch(void* const* d_in, const int* in_sizes, int n_in,
                              void* d_out, int out_size)
{
    const float* x  = (const float*)d_in[0];
    const float* W1 = (const float*)d_in[1];
    const float* b1 = (const float*)d_in[2];
    const float* W2 = (const float*)d_in[3];
    const float* b2 = (const float*)d_in[4];
    float* out = (float*)d_out;

    float *Hbuf = nullptr, *Abuf = nullptr;
    cudaGetSymbolAddress((void**)&Hbuf, g_H);
    cudaGetSymbolAddress((void**)&Abuf, g_ATT);

    const int attn_smem = (64 * 68 * 3 + 64 * 72) * 4;   // 70656 B
    cudaFuncSetAttribute(attn_tf32, cudaFuncAttributeMaxDynamicSharedMemorySize,
                         attn_smem);

    // 1) QKV projection: g_H = x @ W1 + b1   [8192, 3072]
    gemm_tf32<<<dim3(H3 / 128, NTOK / 128), 256>>>(x, W1, b1, Hbuf,
                                                   NTOK, H3, EDIM);
    // 2) attention -> g_ATT  [8192, 1024]
    attn_tf32<<<dim3(SEQ / 64, NH, NB), 128, attn_smem>>>(Hbuf, Abuf);
    // 3) output projection: out = g_ATT @ W2 + b2  [8192, 1024]
    gemm_tf32<<<dim3(EDIM / 128, NTOK / 128), 256>>>(Abuf, W2, b2, out,
                                                     NTOK, EDIM, EDIM);
}

// round 3
// speedup vs baseline: 3.8219x; 1.1583x over previous
#include <cuda_runtime.h>
#include <cstdint>

#define NB   4
#define SEQ  2048
#define EDIM 1024
#define H3   3072
#define NH   16
#define NTOK (NB*SEQ)

// Scratch (device globals: allocation-free, graph-capture safe)
__device__ float g_H[(size_t)NTOK * H3];      // QKV projections (tf32-rounded)
__device__ float g_ATT[(size_t)NTOK * EDIM];  // attention out  (tf32-rounded)
__device__ float g_X[(size_t)NTOK * EDIM];    // tf32-rounded x
__device__ float g_W1[(size_t)EDIM * H3];     // tf32-rounded W1
__device__ float g_W2[(size_t)EDIM * EDIM];   // tf32-rounded W2

__device__ __forceinline__ float to_tf32(float x) {
    uint32_t u;
    asm("cvt.rna.tf32.f32 %0, %1;" : "=r"(u) : "f"(x));
    return __uint_as_float(u);
}

__device__ __forceinline__ void mma_tf32(float d[4],
                                         uint32_t a0, uint32_t a1, uint32_t a2, uint32_t a3,
                                         uint32_t b0, uint32_t b1) {
    asm volatile(
        "mma.sync.aligned.m16n8k8.row.col.f32.tf32.tf32.f32 "
        "{%0,%1,%2,%3}, {%4,%5,%6,%7}, {%8,%9}, {%0,%1,%2,%3};"
        : "+f"(d[0]), "+f"(d[1]), "+f"(d[2]), "+f"(d[3])
        : "r"(a0), "r"(a1), "r"(a2), "r"(a3), "r"(b0), "r"(b1));
}

__device__ __forceinline__ void cp16(uint32_t dst, const void* src) {
    asm volatile("cp.async.cg.shared.global [%0], [%1], 16;\n" :: "r"(dst), "l"(src));
}
#define CP_COMMIT()  asm volatile("cp.async.commit_group;\n" ::: "memory")
#define CP_WAIT(n)   asm volatile("cp.async.wait_group %0;\n" :: "n"(n) : "memory")

// ---------------------------------------------------------------------------
// Elementwise tf32 pre-round
// ---------------------------------------------------------------------------
__global__ void round_tf32_k(const float4* __restrict__ in,
                             float4* __restrict__ out, int n4)
{
    int i = blockIdx.x * blockDim.x + threadIdx.x;
    if (i < n4) {
        float4 v = in[i];
        float4 w;
        w.x = to_tf32(v.x); w.y = to_tf32(v.y);
        w.z = to_tf32(v.z); w.w = to_tf32(v.w);
        out[i] = w;
    }
}

// ---------------------------------------------------------------------------
// TF32 GEMM (inputs pre-rounded): C = A@B + bias. 128x128x32, 256 thr,
// 2-stage cp.async double buffer. ROUND: round output to tf32.
// ---------------------------------------------------------------------------
template<bool ROUND>
__global__ __launch_bounds__(256, 2)
void gemm_tf32(const float* __restrict__ A, const float* __restrict__ B,
               const float* __restrict__ bias, float* __restrict__ C,
               int M, int N, int K)
{
    extern __shared__ float sm[];
    float (*As)[128][36] = (float (*)[128][36])sm;                  // 2 x 128 x 36
    float (*Bs)[32][136] = (float (*)[32][136])(sm + 2 * 128 * 36); // 2 x 32 x 136

    const int tid  = threadIdx.x;
    const int bm   = blockIdx.y, bn = blockIdx.x;
    const int warp = tid >> 5, lane = tid & 31;
    const int wm   = (warp >> 2) * 64;
    const int wn   = (warp & 3) * 32;
    const int lr   = lane >> 2, lc = lane & 3;

    // cp.async chunk mappings
    const int ar = tid >> 1;                 // x4 iters: idx = i*256+tid
    const int ntiles = K >> 5;

    float d[4][4][4];
    #pragma unroll
    for (int mt = 0; mt < 4; mt++)
        #pragma unroll
        for (int nt = 0; nt < 4; nt++)
            #pragma unroll
            for (int r = 0; r < 4; r++) d[mt][nt][r] = 0.f;

    auto prefetch = [&](int t, int buf) {
        int k0 = t << 5;
        #pragma unroll
        for (int i = 0; i < 4; i++) {
            int idx = i * 256 + tid;
            int r = idx >> 3, c = idx & 7;
            cp16((uint32_t)__cvta_generic_to_shared(&As[buf][r][c * 4]),
                 A + (size_t)(bm * 128 + r) * K + k0 + c * 4);
        }
        #pragma unroll
        for (int i = 0; i < 4; i++) {
            int idx = i * 256 + tid;
            int r = idx >> 5, c = idx & 31;
            cp16((uint32_t)__cvta_generic_to_shared(&Bs[buf][r][c * 4]),
                 B + (size_t)(k0 + r) * N + bn * 128 + c * 4);
        }
        CP_COMMIT();
    };

    prefetch(0, 0);

    for (int t = 0; t < ntiles; t++) {
        int cur = t & 1;
        if (t + 1 < ntiles) { prefetch(t + 1, cur ^ 1); CP_WAIT(1); }
        else                { CP_WAIT(0); }
        __syncthreads();

        #pragma unroll
        for (int ks = 0; ks < 4; ks++) {
            uint32_t a[4][4], b[4][2];
            #pragma unroll
            for (int mt = 0; mt < 4; mt++) {
                int r = wm + mt * 16 + lr, c = ks * 8 + lc;
                a[mt][0] = __float_as_uint(As[cur][r][c]);
                a[mt][1] = __float_as_uint(As[cur][r + 8][c]);
                a[mt][2] = __float_as_uint(As[cur][r][c + 4]);
                a[mt][3] = __float_as_uint(As[cur][r + 8][c + 4]);
            }
            #pragma unroll
            for (int nt = 0; nt < 4; nt++) {
                int nn = wn + nt * 8 + lr, kk = ks * 8 + lc;
                b[nt][0] = __float_as_uint(Bs[cur][kk][nn]);
                b[nt][1] = __float_as_uint(Bs[cur][kk + 4][nn]);
            }
            #pragma unroll
            for (int mt = 0; mt < 4; mt++)
                #pragma unroll
                for (int nt = 0; nt < 4; nt++)
                    mma_tf32(d[mt][nt], a[mt][0], a[mt][1], a[mt][2], a[mt][3],
                             b[nt][0], b[nt][1]);
        }
        __syncthreads();
    }

    #pragma unroll
    for (int mt = 0; mt < 4; mt++) {
        #pragma unroll
        for (int nt = 0; nt < 4; nt++) {
            int row = bm * 128 + wm + mt * 16 + lr;
            int col = bn * 128 + wn + nt * 8 + 2 * lc;
            float2 bv = *(const float2*)(bias + col);
            float2 v0, v1;
            if (ROUND) {
                v0 = make_float2(to_tf32(d[mt][nt][0] + bv.x), to_tf32(d[mt][nt][1] + bv.y));
                v1 = make_float2(to_tf32(d[mt][nt][2] + bv.x), to_tf32(d[mt][nt][3] + bv.y));
            } else {
                v0 = make_float2(d[mt][nt][0] + bv.x, d[mt][nt][1] + bv.y);
                v1 = make_float2(d[mt][nt][2] + bv.x, d[mt][nt][3] + bv.y);
            }
            *(float2*)(C + (size_t)row * N + col)       = v0;
            *(float2*)(C + (size_t)(row + 8) * N + col) = v1;
        }
    }
}

// ---------------------------------------------------------------------------
// Flash attention, TF32 mma, cp.async double-buffered K/V.
// grid=(SEQ/64, NH, NB), block=128 (4 warps x 16 q rows). Inputs pre-rounded.
// smem: Qs[64][68] | Ks[2][64][68] | Vs[2][64][72] | Ps[64][68]  = 104 KB
// ---------------------------------------------------------------------------
__global__ __launch_bounds__(128)
void attn_tf32(const float* __restrict__ Hqkv, float* __restrict__ Out)
{
    extern __shared__ float smp[];
    float* Qs = smp;                        // [64][68]
    float (*Ks)[64][68] = (float (*)[64][68])(Qs + 64 * 68);
    float (*Vs)[64][72] = (float (*)[64][72])(Qs + 64 * 68 + 2 * 64 * 68);
    float* Ps = Qs + 64 * 68 + 2 * 64 * 68 + 2 * 64 * 72;  // [64][68]

    const int qb = blockIdx.x, h = blockIdx.y, n = blockIdx.z;
    const int tid = threadIdx.x, warp = tid >> 5, lane = tid & 31;
    const int lr = lane >> 2, lc = lane & 3;
    const float* base = Hqkv + (size_t)n * SEQ * H3 + h * 192;

    auto prefetch_kv = [&](int t, int buf) {
        #pragma unroll
        for (int i = 0; i < 8; i++) {
            int idx = i * 128 + tid;
            int r = idx >> 4, c = idx & 15;
            const float* kp = base + (size_t)(t * 64 + r) * H3 + 64 + c * 4;
            cp16((uint32_t)__cvta_generic_to_shared(&Ks[buf][r][c * 4]), kp);
            cp16((uint32_t)__cvta_generic_to_shared(&Vs[buf][r][c * 4]), kp + 64);
        }
        CP_COMMIT();
    };

    prefetch_kv(0, 0);

    // stage Q (scale by 1/8 — exact power of two, stays tf32)
    #pragma unroll
    for (int i = 0; i < 8; i++) {
        int idx = i * 128 + tid;
        int r = idx >> 4, c = idx & 15;
        float4 v = *(const float4*)(base + (size_t)(qb * 64 + r) * H3 + c * 4);
        float4 w = make_float4(0.125f * v.x, 0.125f * v.y, 0.125f * v.z, 0.125f * v.w);
        *(float4*)&Qs[r * 68 + c * 4] = w;
    }
    __syncthreads();

    const int qr = warp * 16 + lr;
    uint32_t aq[8][4];
    #pragma unroll
    for (int kt = 0; kt < 8; kt++) {
        int c = kt * 8 + lc;
        aq[kt][0] = __float_as_uint(Qs[qr * 68 + c]);
        aq[kt][1] = __float_as_uint(Qs[(qr + 8) * 68 + c]);
        aq[kt][2] = __float_as_uint(Qs[qr * 68 + c + 4]);
        aq[kt][3] = __float_as_uint(Qs[(qr + 8) * 68 + c + 4]);
    }

    float o[8][4];
    #pragma unroll
    for (int nt = 0; nt < 8; nt++)
        #pragma unroll
        for (int r = 0; r < 4; r++) o[nt][r] = 0.f;
    float m0 = -1e30f, m1 = -1e30f, l0 = 0.f, l1 = 0.f;

    const int NT = SEQ / 64;
    for (int t = 0; t < NT; t++) {
        int cur = t & 1;
        if (t + 1 < NT) { prefetch_kv(t + 1, cur ^ 1); CP_WAIT(1); }
        else            { CP_WAIT(0); }
        __syncthreads();

        // S = Q @ K^T
        float s[8][4];
        #pragma unroll
        for (int nt = 0; nt < 8; nt++)
            #pragma unroll
            for (int r = 0; r < 4; r++) s[nt][r] = 0.f;
        #pragma unroll
        for (int kt = 0; kt < 8; kt++) {
            #pragma unroll
            for (int nt = 0; nt < 8; nt++) {
                uint32_t b0 = __float_as_uint(Ks[cur][nt * 8 + lr][kt * 8 + lc]);
                uint32_t b1 = __float_as_uint(Ks[cur][nt * 8 + lr][kt * 8 + lc + 4]);
                mma_tf32(s[nt], aq[kt][0], aq[kt][1], aq[kt][2], aq[kt][3], b0, b1);
            }
        }

        // online softmax
        float mx0 = s[0][0], mx1 = s[0][2];
        #pragma unroll
        for (int nt = 0; nt < 8; nt++) {
            mx0 = fmaxf(mx0, fmaxf(s[nt][0], s[nt][1]));
            mx1 = fmaxf(mx1, fmaxf(s[nt][2], s[nt][3]));
        }
        mx0 = fmaxf(mx0, __shfl_xor_sync(0xffffffffu, mx0, 1));
        mx0 = fmaxf(mx0, __shfl_xor_sync(0xffffffffu, mx0, 2));
        mx1 = fmaxf(mx1, __shfl_xor_sync(0xffffffffu, mx1, 1));
        mx1 = fmaxf(mx1, __shfl_xor_sync(0xffffffffu, mx1, 2));
        float nm0 = fmaxf(m0, mx0), nm1 = fmaxf(m1, mx1);
        float al0 = __expf(m0 - nm0), al1 = __expf(m1 - nm1);
        m0 = nm0; m1 = nm1;
        float sum0 = 0.f, sum1 = 0.f;
        #pragma unroll
        for (int nt = 0; nt < 8; nt++) {
            s[nt][0] = __expf(s[nt][0] - m0);
            s[nt][1] = __expf(s[nt][1] - m0);
            s[nt][2] = __expf(s[nt][2] - m1);
            s[nt][3] = __expf(s[nt][3] - m1);
            sum0 += s[nt][0] + s[nt][1];
            sum1 += s[nt][2] + s[nt][3];
            o[nt][0] *= al0; o[nt][1] *= al0;
            o[nt][2] *= al1; o[nt][3] *= al1;
        }
        sum0 += __shfl_xor_sync(0xffffffffu, sum0, 1);
        sum0 += __shfl_xor_sync(0xffffffffu, sum0, 2);
        sum1 += __shfl_xor_sync(0xffffffffu, sum1, 1);
        sum1 += __shfl_xor_sync(0xffffffffu, sum1, 2);
        l0 = l0 * al0 + sum0;
        l1 = l1 * al1 + sum1;

        // P -> smem (C-frag -> A-frag relayout), tf32-rounded
        #pragma unroll
        for (int nt = 0; nt < 8; nt++) {
            int col = nt * 8 + 2 * lc;
            *(float2*)&Ps[qr * 68 + col] =
                make_float2(to_tf32(s[nt][0]), to_tf32(s[nt][1]));
            *(float2*)&Ps[(qr + 8) * 68 + col] =
                make_float2(to_tf32(s[nt][2]), to_tf32(s[nt][3]));
        }
        __syncwarp();

        // O += P @ V
        #pragma unroll
        for (int kt = 0; kt < 8; kt++) {
            uint32_t a0 = __float_as_uint(Ps[qr * 68 + kt * 8 + lc]);
            uint32_t a1 = __float_as_uint(Ps[(qr + 8) * 68 + kt * 8 + lc]);
            uint32_t a2 = __float_as_uint(Ps[qr * 68 + kt * 8 + lc + 4]);
            uint32_t a3 = __float_as_uint(Ps[(qr + 8) * 68 + kt * 8 + lc + 4]);
            #pragma unroll
            for (int nt = 0; nt < 8; nt++) {
                uint32_t b0 = __float_as_uint(Vs[cur][kt * 8 + lc][nt * 8 + lr]);
                uint32_t b1 = __float_as_uint(Vs[cur][kt * 8 + lc + 4][nt * 8 + lr]);
                mma_tf32(o[nt], a0, a1, a2, a3, b0, b1);
            }
        }
        __syncthreads();
    }

    // epilogue: normalized, tf32-rounded (feeds proj GEMM)
    float inv0 = 1.f / l0, inv1 = 1.f / l1;
    float* op0 = Out + (size_t)(n * SEQ + qb * 64 + qr) * EDIM + h * 64;
    float* op1 = op0 + (size_t)8 * EDIM;
    #pragma unroll
    for (int nt = 0; nt < 8; nt++) {
        int col = nt * 8 + 2 * lc;
        *(float2*)(op0 + col) =
            make_float2(to_tf32(o[nt][0] * inv0), to_tf32(o[nt][1] * inv0));
        *(float2*)(op1 + col) =
            make_float2(to_tf32(o[nt][2] * inv1), to_tf32(o[nt][3] * inv1));
    }
}

// ---------------------------------------------------------------------------
extern "C" void kernel_launch(void* const* d_in, const int* in_sizes, int n_in,
                              void* d_out, int out_size)
{
    const float* x  = (const float*)d_in[0];
    const float* W1 = (const float*)d_in[1];
    const float* b1 = (const float*)d_in[2];
    const float* W2 = (const float*)d_in[3];
    const float* b2 = (const float*)d_in[4];
    float* out = (float*)d_out;

    float *Hbuf, *Abuf, *Xbuf, *W1buf, *W2buf;
    cudaGetSymbolAddress((void**)&Hbuf, g_H);
    cudaGetSymbolAddress((void**)&Abuf, g_ATT);
    cudaGetSymbolAddress((void**)&Xbuf, g_X);
    cudaGetSymbolAddress((void**)&W1buf, g_W1);
    cudaGetSymbolAddress((void**)&W2buf, g_W2);

    const int gemm_smem = (2 * 128 * 36 + 2 * 32 * 136) * 4;          // 70656 B
    const int attn_smem = (64 * 68 + 2 * 64 * 68 + 2 * 64 * 72 + 64 * 68) * 4; // 106496 B
    static bool attr_done = false;
    if (!attr_done) {
        cudaFuncSetAttribute(gemm_tf32<true>,
                             cudaFuncAttributeMaxDynamicSharedMemorySize, gemm_smem);
        cudaFuncSetAttribute(gemm_tf32<false>,
                             cudaFuncAttributeMaxDynamicSharedMemorySize, gemm_smem);
        cudaFuncSetAttribute(attn_tf32,
                             cudaFuncAttributeMaxDynamicSharedMemorySize, attn_smem);
        attr_done = true;
    }

    // pre-round inputs to tf32
    round_tf32_k<<<(NTOK * EDIM / 4 + 255) / 256, 256>>>((const float4*)x,
                                                         (float4*)Xbuf, NTOK * EDIM / 4);
    round_tf32_k<<<(EDIM * H3 / 4 + 255) / 256, 256>>>((const float4*)W1,
                                                       (float4*)W1buf, EDIM * H3 / 4);
    round_tf32_k<<<(EDIM * EDIM / 4 + 255) / 256, 256>>>((const float4*)W2,
                                                         (float4*)W2buf, EDIM * EDIM / 4);

    // 1) QKV projection (output tf32-rounded for attention)
    gemm_tf32<true><<<dim3(H3 / 128, NTOK / 128), 256, gemm_smem>>>(
        Xbuf, W1buf, b1, Hbuf, NTOK, H3, EDIM);
    // 2) attention (output tf32-rounded for proj GEMM)
    attn_tf32<<<dim3(SEQ / 64, NH, NB), 128, attn_smem>>>(Hbuf, Abuf);
    // 3) output projection (full fp32 out)
    gemm_tf32<false><<<dim3(EDIM / 128, NTOK / 128), 256, gemm_smem>>>(
        Abuf, W2buf, b2, out, NTOK, EDIM, EDIM);
}

// round 4
// speedup vs baseline: 4.1942x; 1.0974x over previous
#include <cuda_runtime.h>
#include <cstdint>

#define NB   4
#define SEQ  2048
#define EDIM 1024
#define H3   3072
#define NH   16
#define NTOK (NB*SEQ)

// Scratch (device globals: allocation-free, graph-capture safe)
__device__ float g_QK [(size_t)NTOK * 2048];   // [token][ Qall(1024) | Kall(1024) ]
__device__ float g_VT [(size_t)EDIM * NTOK];   // [h*64+d][token]  (V transposed)
__device__ float g_ATT[(size_t)NTOK * EDIM];   // attention out (tf32-rounded)
__device__ float g_X  [(size_t)NTOK * EDIM];   // tf32-rounded x
__device__ float g_W1T[(size_t)H3   * EDIM];   // W1^T, rows permuted [Q|K|V]
__device__ float g_W2T[(size_t)EDIM * EDIM];   // W2^T
__device__ float g_B1P[H3];                    // permuted b1

__device__ __forceinline__ float to_tf32(float x) {
    uint32_t u;
    asm("cvt.rna.tf32.f32 %0, %1;" : "=r"(u) : "f"(x));
    return __uint_as_float(u);
}
__device__ __forceinline__ void mma_tf32(float d[4],
                                         uint32_t a0, uint32_t a1, uint32_t a2, uint32_t a3,
                                         uint32_t b0, uint32_t b1) {
    asm volatile(
        "mma.sync.aligned.m16n8k8.row.col.f32.tf32.tf32.f32 "
        "{%0,%1,%2,%3}, {%4,%5,%6,%7}, {%8,%9}, {%0,%1,%2,%3};"
        : "+f"(d[0]), "+f"(d[1]), "+f"(d[2]), "+f"(d[3])
        : "r"(a0), "r"(a1), "r"(a2), "r"(a3), "r"(b0), "r"(b1));
}
__device__ __forceinline__ uint32_t smaddr(const void* p) {
    return (uint32_t)__cvta_generic_to_shared(p);
}
__device__ __forceinline__ void ldsm_x4(uint32_t r[4], uint32_t addr) {
    asm volatile("ldmatrix.sync.aligned.m8n8.x4.shared.b16 {%0,%1,%2,%3}, [%4];"
                 : "=r"(r[0]), "=r"(r[1]), "=r"(r[2]), "=r"(r[3]) : "r"(addr));
}
__device__ __forceinline__ void cp16(uint32_t dst, const void* src) {
    asm volatile("cp.async.cg.shared.global [%0], [%1], 16;\n" :: "r"(dst), "l"(src));
}
#define CP_COMMIT()  asm volatile("cp.async.commit_group;\n" ::: "memory")
#define CP_WAIT(n)   asm volatile("cp.async.wait_group %0;\n" :: "n"(n) : "memory")

// ---------------------------------------------------------------------------
// Pre-pass kernels
// ---------------------------------------------------------------------------
__global__ void round_tf32_k(const float4* __restrict__ in, float4* __restrict__ out, int n4) {
    int i = blockIdx.x * blockDim.x + threadIdx.x;
    if (i < n4) {
        float4 v = in[i];
        out[i] = make_float4(to_tf32(v.x), to_tf32(v.y), to_tf32(v.z), to_tf32(v.w));
    }
}

// W [K][NC] -> WT [NC][K], tf32-rounded. PERM: reorder rows h*192+p*64+d -> p*1024+h*64+d
template<bool PERM>
__global__ void round_transpose(const float* __restrict__ W, float* __restrict__ WT,
                                int K, int NC)
{
    __shared__ float t[32][33];
    int c0 = blockIdx.x * 32, k0 = blockIdx.y * 32;
    #pragma unroll
    for (int i = 0; i < 32; i += 8)
        t[threadIdx.y + i][threadIdx.x] =
            W[(size_t)(k0 + threadIdx.y + i) * NC + c0 + threadIdx.x];
    __syncthreads();
    int cbase = PERM ? ((c0 % 192) / 64) * 1024 + (c0 / 192) * 64 + (c0 % 64) : c0;
    #pragma unroll
    for (int i = 0; i < 32; i += 8) {
        int j = threadIdx.y + i;
        WT[(size_t)(cbase + j) * K + k0 + threadIdx.x] = to_tf32(t[threadIdx.x][j]);
    }
}

__global__ void permute_b1(const float* __restrict__ b, float* __restrict__ bp) {
    int i = blockIdx.x * 256 + threadIdx.x;
    if (i < H3) bp[i] = b[((i & 1023) >> 6) * 192 + (i >> 10) * 64 + (i & 63)];
}

// ---------------------------------------------------------------------------
// TF32 GEMM: C = A @ Bt^T + bias. A [M][K] row-major, Bt [N][K] row-major.
// 128x128x32 tile, 256 thr, 2-stage cp.async, ldmatrix fragment loads.
// Columns >= nsplit are stored transposed (tf32-rounded) into Cvt[col-nsplit][row].
// ---------------------------------------------------------------------------
template<bool ROUND>
__global__ __launch_bounds__(256, 2)
void gemm_tf32(const float* __restrict__ A, const float* __restrict__ Bt,
               const float* __restrict__ bias, float* __restrict__ C,
               float* __restrict__ Cvt, int nsplit,
               int M, int N, int K)
{
    extern __shared__ float sm[];
    float (*As)[128][36] = (float (*)[128][36])sm;
    float (*Bs)[128][36] = (float (*)[128][36])(sm + 2 * 128 * 36);

    const int tid  = threadIdx.x;
    const int bm   = blockIdx.y, bn = blockIdx.x;
    const int warp = tid >> 5, lane = tid & 31;
    const int wm   = (warp >> 2) * 64;
    const int wn   = (warp & 3) * 32;
    const int lr   = lane >> 2, lc = lane & 3;

    // ldmatrix address components
    const int arow = wm + ((lane >> 3) & 1) * 8 + (lane & 7);   // + mt*16
    const int acol = (lane >> 4) * 4;                           // + ks*8
    const int brow = wn + ((lane >> 4) & 1) * 8 + (lane & 7);   // + ntp*16
    const int bcol = ((lane >> 3) & 1) * 4;                     // + ks*8

    const int ntiles = K >> 5;

    float d[4][4][4];
    #pragma unroll
    for (int mt = 0; mt < 4; mt++)
        #pragma unroll
        for (int nt = 0; nt < 4; nt++)
            #pragma unroll
            for (int r = 0; r < 4; r++) d[mt][nt][r] = 0.f;

    auto prefetch = [&](int t, int buf) {
        int k0 = t << 5;
        #pragma unroll
        for (int i = 0; i < 4; i++) {
            int idx = i * 256 + tid;
            int r = idx >> 3, c = idx & 7;
            cp16(smaddr(&As[buf][r][c * 4]), A  + (size_t)(bm * 128 + r) * K + k0 + c * 4);
        }
        #pragma unroll
        for (int i = 0; i < 4; i++) {
            int idx = i * 256 + tid;
            int r = idx >> 3, c = idx & 7;
            cp16(smaddr(&Bs[buf][r][c * 4]), Bt + (size_t)(bn * 128 + r) * K + k0 + c * 4);
        }
        CP_COMMIT();
    };

    prefetch(0, 0);

    for (int t = 0; t < ntiles; t++) {
        int cur = t & 1;
        if (t + 1 < ntiles) { prefetch(t + 1, cur ^ 1); CP_WAIT(1); }
        else                { CP_WAIT(0); }
        __syncthreads();

        #pragma unroll
        for (int ks = 0; ks < 4; ks++) {
            uint32_t a[4][4], b[4][2];
            #pragma unroll
            for (int mt = 0; mt < 4; mt++)
                ldsm_x4(a[mt], smaddr(&As[cur][arow + mt * 16][ks * 8 + acol]));
            #pragma unroll
            for (int ntp = 0; ntp < 2; ntp++) {
                uint32_t t4[4];
                ldsm_x4(t4, smaddr(&Bs[cur][brow + ntp * 16][ks * 8 + bcol]));
                b[2 * ntp][0] = t4[0]; b[2 * ntp][1] = t4[1];
                b[2 * ntp + 1][0] = t4[2]; b[2 * ntp + 1][1] = t4[3];
            }
            #pragma unroll
            for (int mt = 0; mt < 4; mt++)
                #pragma unroll
                for (int nt = 0; nt < 4; nt++)
                    mma_tf32(d[mt][nt], a[mt][0], a[mt][1], a[mt][2], a[mt][3],
                             b[nt][0], b[nt][1]);
        }
        __syncthreads();
    }

    const bool vmode = (bn * 128 >= nsplit);
    #pragma unroll
    for (int mt = 0; mt < 4; mt++) {
        #pragma unroll
        for (int nt = 0; nt < 4; nt++) {
            int row = bm * 128 + wm + mt * 16 + lr;
            int col = bn * 128 + wn + nt * 8 + 2 * lc;
            float2 bv = *(const float2*)(bias + col);
            float e0 = d[mt][nt][0] + bv.x, e1 = d[mt][nt][1] + bv.y;
            float e2 = d[mt][nt][2] + bv.x, e3 = d[mt][nt][3] + bv.y;
            if (vmode) {
                float* p0 = Cvt + (size_t)(col - nsplit) * M;
                float* p1 = p0 + M;
                p0[row]     = to_tf32(e0);
                p1[row]     = to_tf32(e1);
                p0[row + 8] = to_tf32(e2);
                p1[row + 8] = to_tf32(e3);
            } else if (ROUND) {
                *(float2*)(C + (size_t)row * N + col) =
                    make_float2(to_tf32(e0), to_tf32(e1));
                *(float2*)(C + (size_t)(row + 8) * N + col) =
                    make_float2(to_tf32(e2), to_tf32(e3));
            } else {
                *(float2*)(C + (size_t)row * N + col)       = make_float2(e0, e1);
                *(float2*)(C + (size_t)(row + 8) * N + col) = make_float2(e2, e3);
            }
        }
    }
}

// ---------------------------------------------------------------------------
// Flash attention, TF32 mma + ldmatrix frags, cp.async double-buffered K/V.
// grid=(SEQ/64, NH, NB), block=128 (4 warps x 16 q rows).
// smem: Qs[64][68] | Ks[2][64][68] | Vst[2][64][68] | Ps[64][68] = 104448 B
// ---------------------------------------------------------------------------
__global__ __launch_bounds__(128, 2)
void attn_tf32(const float* __restrict__ Qk, const float* __restrict__ Vt,
               float* __restrict__ Out)
{
    extern __shared__ float smp[];
    float* Qs = smp;                                            // [64][68]
    float (*Ks )[64][68] = (float (*)[64][68])(smp + 64 * 68);
    float (*Vst)[64][68] = (float (*)[64][68])(smp + 64 * 68 * 3);
    float* Ps = smp + 64 * 68 * 5;                              // [64][68]

    const int qb = blockIdx.x, h = blockIdx.y, n = blockIdx.z;
    const int tid = threadIdx.x, warp = tid >> 5, lane = tid & 31;
    const int lr = lane >> 2, lc = lane & 3;

    const float* Qbase = Qk + (size_t)(n * SEQ) * 2048 + h * 64;
    const float* Kbase = Qbase + 1024;
    const float* Vbase = Vt + (size_t)(h * 64) * NTOK + n * SEQ;

    // ldmatrix address components
    const int ar = warp * 16 + ((lane >> 3) & 1) * 8 + (lane & 7);  // A-type row
    const int ac = (lane >> 4) * 4;                                 // A-type col off
    const int br = ((lane >> 4) & 1) * 8 + (lane & 7);              // B-type row (+ntp*16)
    const int bc = ((lane >> 3) & 1) * 4;                           // B-type col off

    auto prefetch_kv = [&](int t, int buf) {
        #pragma unroll
        for (int i = 0; i < 8; i++) {
            int idx = i * 128 + tid;
            int r = idx >> 4, c = idx & 15;
            cp16(smaddr(&Ks[buf][r][c * 4]),  Kbase + (size_t)(t * 64 + r) * 2048 + c * 4);
            cp16(smaddr(&Vst[buf][r][c * 4]), Vbase + (size_t)r * NTOK + t * 64 + c * 4);
        }
        CP_COMMIT();
    };

    prefetch_kv(0, 0);

    // stage Q scaled by 1/8 (exact pow2: stays tf32)
    #pragma unroll
    for (int i = 0; i < 8; i++) {
        int idx = i * 128 + tid;
        int r = idx >> 4, c = idx & 15;
        float4 v = *(const float4*)(Qbase + (size_t)(qb * 64 + r) * 2048 + c * 4);
        *(float4*)&Qs[r * 68 + c * 4] =
            make_float4(0.125f * v.x, 0.125f * v.y, 0.125f * v.z, 0.125f * v.w);
    }
    __syncthreads();

    uint32_t aq[8][4];
    #pragma unroll
    for (int kt = 0; kt < 8; kt++)
        ldsm_x4(aq[kt], smaddr(&Qs[ar * 68 + kt * 8 + ac]));

    float o[8][4];
    #pragma unroll
    for (int nt = 0; nt < 8; nt++)
        #pragma unroll
        for (int r = 0; r < 4; r++) o[nt][r] = 0.f;
    float m0 = -1e30f, m1 = -1e30f, l0 = 0.f, l1 = 0.f;
    const int qr = warp * 16 + lr;

    const int NT = SEQ / 64;
    for (int t = 0; t < NT; t++) {
        int cur = t & 1;
        if (t + 1 < NT) { prefetch_kv(t + 1, cur ^ 1); CP_WAIT(1); }
        else            { CP_WAIT(0); }
        __syncthreads();

        // S = Q @ K^T
        float s[8][4];
        #pragma unroll
        for (int nt = 0; nt < 8; nt++)
            #pragma unroll
            for (int r = 0; r < 4; r++) s[nt][r] = 0.f;
        #pragma unroll
        for (int kt = 0; kt < 8; kt++) {
            uint32_t bb[8][2];
            #pragma unroll
            for (int ntp = 0; ntp < 4; ntp++) {
                uint32_t t4[4];
                ldsm_x4(t4, smaddr(&Ks[cur][br + ntp * 16][kt * 8 + bc]));
                bb[2 * ntp][0] = t4[0]; bb[2 * ntp][1] = t4[1];
                bb[2 * ntp + 1][0] = t4[2]; bb[2 * ntp + 1][1] = t4[3];
            }
            #pragma unroll
            for (int nt = 0; nt < 8; nt++)
                mma_tf32(s[nt], aq[kt][0], aq[kt][1], aq[kt][2], aq[kt][3],
                         bb[nt][0], bb[nt][1]);
        }

        // online softmax
        float mx0 = s[0][0], mx1 = s[0][2];
        #pragma unroll
        for (int nt = 0; nt < 8; nt++) {
            mx0 = fmaxf(mx0, fmaxf(s[nt][0], s[nt][1]));
            mx1 = fmaxf(mx1, fmaxf(s[nt][2], s[nt][3]));
        }
        mx0 = fmaxf(mx0, __shfl_xor_sync(0xffffffffu, mx0, 1));
        mx0 = fmaxf(mx0, __shfl_xor_sync(0xffffffffu, mx0, 2));
        mx1 = fmaxf(mx1, __shfl_xor_sync(0xffffffffu, mx1, 1));
        mx1 = fmaxf(mx1, __shfl_xor_sync(0xffffffffu, mx1, 2));
        float nm0 = fmaxf(m0, mx0), nm1 = fmaxf(m1, mx1);
        float al0 = __expf(m0 - nm0), al1 = __expf(m1 - nm1);
        m0 = nm0; m1 = nm1;
        float sum0 = 0.f, sum1 = 0.f;
        #pragma unroll
        for (int nt = 0; nt < 8; nt++) {
            s[nt][0] = __expf(s[nt][0] - m0);
            s[nt][1] = __expf(s[nt][1] - m0);
            s[nt][2] = __expf(s[nt][2] - m1);
            s[nt][3] = __expf(s[nt][3] - m1);
            sum0 += s[nt][0] + s[nt][1];
            sum1 += s[nt][2] + s[nt][3];
            o[nt][0] *= al0; o[nt][1] *= al0;
            o[nt][2] *= al1; o[nt][3] *= al1;
        }
        sum0 += __shfl_xor_sync(0xffffffffu, sum0, 1);
        sum0 += __shfl_xor_sync(0xffffffffu, sum0, 2);
        sum1 += __shfl_xor_sync(0xffffffffu, sum1, 1);
        sum1 += __shfl_xor_sync(0xffffffffu, sum1, 2);
        l0 = l0 * al0 + sum0;
        l1 = l1 * al1 + sum1;

        // P -> smem (C-frag -> A-frag relayout), tf32-rounded
        #pragma unroll
        for (int nt = 0; nt < 8; nt++) {
            int col = nt * 8 + 2 * lc;
            *(float2*)&Ps[qr * 68 + col] =
                make_float2(to_tf32(s[nt][0]), to_tf32(s[nt][1]));
            *(float2*)&Ps[(qr + 8) * 68 + col] =
                make_float2(to_tf32(s[nt][2]), to_tf32(s[nt][3]));
        }
        __syncwarp();

        // O += P @ V
        #pragma unroll
        for (int kt = 0; kt < 8; kt++) {
            uint32_t pa[4];
            ldsm_x4(pa, smaddr(&Ps[ar * 68 + kt * 8 + ac]));
            uint32_t bb[8][2];
            #pragma unroll
            for (int ntp = 0; ntp < 4; ntp++) {
                uint32_t t4[4];
                ldsm_x4(t4, smaddr(&Vst[cur][br + ntp * 16][kt * 8 + bc]));
                bb[2 * ntp][0] = t4[0]; bb[2 * ntp][1] = t4[1];
                bb[2 * ntp + 1][0] = t4[2]; bb[2 * ntp + 1][1] = t4[3];
            }
            #pragma unroll
            for (int nt = 0; nt < 8; nt++)
                mma_tf32(o[nt], pa[0], pa[1], pa[2], pa[3], bb[nt][0], bb[nt][1]);
        }
        __syncthreads();
    }

    // epilogue (tf32-rounded; feeds proj GEMM)
    float inv0 = 1.f / l0, inv1 = 1.f / l1;
    float* op0 = Out + (size_t)(n * SEQ + qb * 64 + qr) * EDIM + h * 64;
    float* op1 = op0 + (size_t)8 * EDIM;
    #pragma unroll
    for (int nt = 0; nt < 8; nt++) {
        int col = nt * 8 + 2 * lc;
        *(float2*)(op0 + col) = make_float2(to_tf32(o[nt][0] * inv0), to_tf32(o[nt][1] * inv0));
        *(float2*)(op1 + col) = make_float2(to_tf32(o[nt][2] * inv1), to_tf32(o[nt][3] * inv1));
    }
}

// ---------------------------------------------------------------------------
extern "C" void kernel_launch(void* const* d_in, const int* in_sizes, int n_in,
                              void* d_out, int out_size)
{
    const float* x  = (const float*)d_in[0];
    const float* W1 = (const float*)d_in[1];
    const float* b1 = (const float*)d_in[2];
    const float* W2 = (const float*)d_in[3];
    const float* b2 = (const float*)d_in[4];
    float* out = (float*)d_out;

    float *QKbuf, *VTbuf, *Abuf, *Xbuf, *W1Tbuf, *W2Tbuf, *B1Pbuf;
    cudaGetSymbolAddress((void**)&QKbuf,  g_QK);
    cudaGetSymbolAddress((void**)&VTbuf,  g_VT);
    cudaGetSymbolAddress((void**)&Abuf,   g_ATT);
    cudaGetSymbolAddress((void**)&Xbuf,   g_X);
    cudaGetSymbolAddress((void**)&W1Tbuf, g_W1T);
    cudaGetSymbolAddress((void**)&W2Tbuf, g_W2T);
    cudaGetSymbolAddress((void**)&B1Pbuf, g_B1P);

    const int gemm_smem = 2 * 2 * 128 * 36 * 4;   // 73728 B
    const int attn_smem = 64 * 68 * 6 * 4;        // 104448 B
    static bool attr_done = false;
    if (!attr_done) {
        cudaFuncSetAttribute(gemm_tf32<true>,
                             cudaFuncAttributeMaxDynamicSharedMemorySize, gemm_smem);
        cudaFuncSetAttribute(gemm_tf32<false>,
                             cudaFuncAttributeMaxDynamicSharedMemorySize, gemm_smem);
        cudaFuncSetAttribute(attn_tf32,
                             cudaFuncAttributeMaxDynamicSharedMemorySize, attn_smem);
        attr_done = true;
    }

    // pre-pass: round x; round+transpose(+permute) weights; permute bias
    round_tf32_k<<<(NTOK * EDIM / 4 + 255) / 256, 256>>>((const float4*)x,
                                                         (float4*)Xbuf, NTOK * EDIM / 4);
    round_transpose<true ><<<dim3(H3 / 32, EDIM / 32), dim3(32, 8)>>>(W1, W1Tbuf, EDIM, H3);
    round_transpose<false><<<dim3(EDIM / 32, EDIM / 32), dim3(32, 8)>>>(W2, W2Tbuf, EDIM, EDIM);
    permute_b1<<<(H3 + 255) / 256, 256>>>(b1, B1Pbuf);

    // 1) QKV projection: Q,K -> g_QK (rounded), V -> g_VT transposed (rounded)
    gemm_tf32<true><<<dim3(H3 / 128, NTOK / 128), 256, gemm_smem>>>(
        Xbuf, W1Tbuf, B1Pbuf, QKbuf, VTbuf, 2048, NTOK, 2048, EDIM);
    // 2) attention -> g_ATT (rounded)
    attn_tf32<<<dim3(SEQ / 64, NH, NB), 128, attn_smem>>>(QKbuf, VTbuf, Abuf);
    // 3) output projection (full fp32 out)
    gemm_tf32<false><<<dim3(EDIM / 128, NTOK / 128), 256, gemm_smem>>>(
        Abuf, W2Tbuf, b2, out, nullptr, 1 << 30, NTOK, EDIM, EDIM);
}

// round 6
// speedup vs baseline: 7.4547x; 1.7774x over previous
#include <cuda_runtime.h>
#include <cuda_fp16.h>
#include <cstdint>

#define NB   4
#define SEQ  2048
#define EDIM 1024
#define H3   3072
#define NH   16
#define NTOK (NB*SEQ)

// Scratch (device globals: allocation-free, graph-capture safe)
__device__ __half g_QK [(size_t)NTOK * 2048];  // [token][Qall(scaled)|Kall]
__device__ __half g_VT [(size_t)EDIM * NTOK];  // [h*64+d][token] (V transposed)
__device__ __half g_ATT[(size_t)NTOK * EDIM];  // attention out
__device__ __half g_X  [(size_t)NTOK * EDIM];  // x in half
__device__ __half g_W1T[(size_t)H3   * EDIM];  // W1^T, rows permuted [Q|K|V]
__device__ __half g_W2T[(size_t)EDIM * EDIM];  // W2^T
__device__ float  g_B1P[H3];                   // permuted b1 (fp32)

__device__ __forceinline__ void mma_f16(float d[4],
                                        uint32_t a0, uint32_t a1, uint32_t a2, uint32_t a3,
                                        uint32_t b0, uint32_t b1) {
    asm volatile(
        "mma.sync.aligned.m16n8k16.row.col.f32.f16.f16.f32 "
        "{%0,%1,%2,%3}, {%4,%5,%6,%7}, {%8,%9}, {%0,%1,%2,%3};"
        : "+f"(d[0]), "+f"(d[1]), "+f"(d[2]), "+f"(d[3])
        : "r"(a0), "r"(a1), "r"(a2), "r"(a3), "r"(b0), "r"(b1));
}
__device__ __forceinline__ uint32_t smaddr(const void* p) {
    return (uint32_t)__cvta_generic_to_shared(p);
}
__device__ __forceinline__ void ldsm_x4(uint32_t r[4], uint32_t addr) {
    asm volatile("ldmatrix.sync.aligned.m8n8.x4.shared.b16 {%0,%1,%2,%3}, [%4];"
                 : "=r"(r[0]), "=r"(r[1]), "=r"(r[2]), "=r"(r[3]) : "r"(addr));
}
__device__ __forceinline__ void cp16(uint32_t dst, const void* src) {
    asm volatile("cp.async.cg.shared.global [%0], [%1], 16;\n" :: "r"(dst), "l"(src));
}
#define CP_COMMIT()  asm volatile("cp.async.commit_group;\n" ::: "memory")
#define CP_WAIT(n)   asm volatile("cp.async.wait_group %0;\n" :: "n"(n) : "memory")

__device__ __forceinline__ uint32_t h2u(__half2 h) {
    union { __half2 h; uint32_t u; } c; c.h = h; return c.u;
}

// ---------------------------------------------------------------------------
// Pre-pass kernels
// ---------------------------------------------------------------------------
__global__ void cvt_half_k(const float4* __restrict__ in, uint2* __restrict__ out, int n4) {
    int i = blockIdx.x * blockDim.x + threadIdx.x;
    if (i < n4) {
        float4 v = in[i];
        uint2 o;
        o.x = h2u(__floats2half2_rn(v.x, v.y));
        o.y = h2u(__floats2half2_rn(v.z, v.w));
        out[i] = o;
    }
}

// W [K][NC] fp32 -> WT [NC][K] half. PERM: rows h*192+p*64+d -> p*1024+h*64+d
template<bool PERM>
__global__ void trans_half(const float* __restrict__ W, __half* __restrict__ WT,
                           int K, int NC)
{
    __shared__ float t[32][33];
    int c0 = blockIdx.x * 32, k0 = blockIdx.y * 32;
    #pragma unroll
    for (int i = 0; i < 32; i += 8)
        t[threadIdx.y + i][threadIdx.x] =
            W[(size_t)(k0 + threadIdx.y + i) * NC + c0 + threadIdx.x];
    __syncthreads();
    int cbase = PERM ? ((c0 % 192) / 64) * 1024 + (c0 / 192) * 64 + (c0 % 64) : c0;
    #pragma unroll
    for (int i = 0; i < 32; i += 8) {
        int j = threadIdx.y + i;
        WT[(size_t)(cbase + j) * K + k0 + threadIdx.x] = __float2half_rn(t[threadIdx.x][j]);
    }
}

__global__ void permute_b1(const float* __restrict__ b, float* __restrict__ bp) {
    int i = blockIdx.x * 256 + threadIdx.x;
    if (i < H3) bp[i] = b[((i & 1023) >> 6) * 192 + (i >> 10) * 64 + (i & 63)];
}

// ---------------------------------------------------------------------------
// FP16 GEMM: C = A @ Bt^T + bias. A [M][K], Bt [N][K] half, row-major.
// 128x128x32 tile, 256 thr, 2-stage cp.async, ldmatrix, m16n8k16 mma.
// MODE 0: fp32 C.  MODE 1: half C (cols<1024 scaled x0.125 = Q); cols>=nsplit
//         stored transposed into Cvt[col-nsplit][row] (half).
// ---------------------------------------------------------------------------
template<int MODE>
__global__ __launch_bounds__(256, 2)
void gemm_f16(const __half* __restrict__ A, const __half* __restrict__ Bt,
              const float* __restrict__ bias, void* __restrict__ Cout,
              __half* __restrict__ Cvt, int nsplit,
              int M, int Nstride, int K)
{
    extern __shared__ __half sh[];
    __half (*As)[128][40] = (__half (*)[128][40])sh;
    __half (*Bs)[128][40] = (__half (*)[128][40])(sh + 2 * 128 * 40);

    const int tid  = threadIdx.x;
    const int bm   = blockIdx.y, bn = blockIdx.x;
    const int warp = tid >> 5, lane = tid & 31;
    const int wm   = (warp >> 2) * 64;
    const int wn   = (warp & 3) * 32;
    const int lr   = lane >> 2, lc = lane & 3;

    const int arow = wm + ((lane >> 3) & 1) * 8 + (lane & 7);   // + mt*16
    const int ach  = ((lane >> 4) & 1) * 8;                     // + kt*16
    const int brow = wn + ((lane >> 4) & 1) * 8 + (lane & 7);   // + ntp*16
    const int bch  = ((lane >> 3) & 1) * 8;                     // + kt*16

    const int ntiles = K >> 5;

    float d[4][4][4];
    #pragma unroll
    for (int mt = 0; mt < 4; mt++)
        #pragma unroll
        for (int nt = 0; nt < 4; nt++)
            #pragma unroll
            for (int r = 0; r < 4; r++) d[mt][nt][r] = 0.f;

    auto prefetch = [&](int t, int buf) {
        int k0 = t << 5;
        #pragma unroll
        for (int i = 0; i < 2; i++) {
            int idx = i * 256 + tid;
            int r = idx >> 2, c = idx & 3;
            cp16(smaddr(&As[buf][r][c * 8]), A  + (size_t)(bm * 128 + r) * K + k0 + c * 8);
        }
        #pragma unroll
        for (int i = 0; i < 2; i++) {
            int idx = i * 256 + tid;
            int r = idx >> 2, c = idx & 3;
            cp16(smaddr(&Bs[buf][r][c * 8]), Bt + (size_t)(bn * 128 + r) * K + k0 + c * 8);
        }
        CP_COMMIT();
    };

    prefetch(0, 0);

    for (int t = 0; t < ntiles; t++) {
        int cur = t & 1;
        if (t + 1 < ntiles) { prefetch(t + 1, cur ^ 1); CP_WAIT(1); }
        else                { CP_WAIT(0); }
        __syncthreads();

        #pragma unroll
        for (int kt = 0; kt < 2; kt++) {
            uint32_t a[4][4], b[4][2];
            #pragma unroll
            for (int mt = 0; mt < 4; mt++)
                ldsm_x4(a[mt], smaddr(&As[cur][arow + mt * 16][kt * 16 + ach]));
            #pragma unroll
            for (int ntp = 0; ntp < 2; ntp++) {
                uint32_t t4[4];
                ldsm_x4(t4, smaddr(&Bs[cur][brow + ntp * 16][kt * 16 + bch]));
                b[2 * ntp][0] = t4[0]; b[2 * ntp][1] = t4[1];
                b[2 * ntp + 1][0] = t4[2]; b[2 * ntp + 1][1] = t4[3];
            }
            #pragma unroll
            for (int mt = 0; mt < 4; mt++)
                #pragma unroll
                for (int nt = 0; nt < 4; nt++)
                    mma_f16(d[mt][nt], a[mt][0], a[mt][1], a[mt][2], a[mt][3],
                            b[nt][0], b[nt][1]);
        }
        __syncthreads();
    }

    #pragma unroll
    for (int mt = 0; mt < 4; mt++) {
        #pragma unroll
        for (int nt = 0; nt < 4; nt++) {
            int row  = bm * 128 + wm + mt * 16 + lr;
            int colg = bn * 128 + wn + nt * 8 + 2 * lc;
            float2 bv = *(const float2*)(bias + colg);
            float e0 = d[mt][nt][0] + bv.x, e1 = d[mt][nt][1] + bv.y;
            float e2 = d[mt][nt][2] + bv.x, e3 = d[mt][nt][3] + bv.y;
            if (MODE == 0) {
                float* C = (float*)Cout;
                *(float2*)(C + (size_t)row * Nstride + colg)       = make_float2(e0, e1);
                *(float2*)(C + (size_t)(row + 8) * Nstride + colg) = make_float2(e2, e3);
            } else {
                if (colg >= nsplit) {   // V third -> transposed half
                    __half* p0 = Cvt + (size_t)(colg - nsplit) * M;
                    __half* p1 = p0 + M;
                    p0[row]     = __float2half_rn(e0);
                    p1[row]     = __float2half_rn(e1);
                    p0[row + 8] = __float2half_rn(e2);
                    p1[row + 8] = __float2half_rn(e3);
                } else {
                    float s = (colg < 1024) ? 0.125f : 1.0f;   // pre-scale Q
                    __half* C = (__half*)Cout;
                    *(__half2*)(C + (size_t)row * Nstride + colg) =
                        __floats2half2_rn(e0 * s, e1 * s);
                    *(__half2*)(C + (size_t)(row + 8) * Nstride + colg) =
                        __floats2half2_rn(e2 * s, e3 * s);
                }
            }
        }
    }
}

// ---------------------------------------------------------------------------
// Flash attention, fp16 mma (m16n8k16) + ldmatrix, cp.async double-buffered.
// grid=(SEQ/64, NH, NB), block=128 (4 warps x 16 q rows).
// smem halves: Qs[64][72] | Ks[2][64][72] | Vst[2][64][72] | Ps[64][72] = 55296 B
// ---------------------------------------------------------------------------
__global__ __launch_bounds__(128, 3)
void attn_f16(const __half* __restrict__ Qk, const __half* __restrict__ Vt,
              __half* __restrict__ Out)
{
    extern __shared__ __half smp[];
    __half* Qs = smp;                                        // [64][72]
    __half (*Ks )[64][72] = (__half (*)[64][72])(smp + 4608);
    __half (*Vst)[64][72] = (__half (*)[64][72])(smp + 4608 * 3);
    __half* Ps = smp + 4608 * 5;                             // [64][72]

    const int qb = blockIdx.x, h = blockIdx.y, n = blockIdx.z;
    const int tid = threadIdx.x, warp = tid >> 5, lane = tid & 31;
    const int lr = lane >> 2, lc = lane & 3;

    const __half* Qbase = Qk + (size_t)(n * SEQ) * 2048 + h * 64;
    const __half* Kbase = Qbase + 1024;
    const __half* Vbase = Vt + (size_t)(h * 64) * NTOK + n * SEQ;

    const int ar  = warp * 16 + ((lane >> 3) & 1) * 8 + (lane & 7);
    const int ach = ((lane >> 4) & 1) * 8;
    const int br  = ((lane >> 4) & 1) * 8 + (lane & 7);
    const int bch = ((lane >> 3) & 1) * 8;

    auto prefetch_kv = [&](int t, int buf) {
        #pragma unroll
        for (int i = 0; i < 4; i++) {
            int idx = i * 128 + tid;
            int r = idx >> 3, c = idx & 7;
            cp16(smaddr(&Ks[buf][r][c * 8]),
                 Kbase + (size_t)(t * 64 + r) * 2048 + c * 8);
            cp16(smaddr(&Vst[buf][r][c * 8]),
                 Vbase + (size_t)r * NTOK + t * 64 + c * 8);
        }
        CP_COMMIT();
    };

    prefetch_kv(0, 0);
    // stage Q (already scaled by 0.125 in GEMM1 epilogue)
    #pragma unroll
    for (int i = 0; i < 4; i++) {
        int idx = i * 128 + tid;
        int r = idx >> 3, c = idx & 7;
        cp16(smaddr(&Qs[r * 72 + c * 8]),
             Qbase + (size_t)(qb * 64 + r) * 2048 + c * 8);
    }
    CP_COMMIT();
    CP_WAIT(0);
    __syncthreads();

    uint32_t aq[4][4];
    #pragma unroll
    for (int kt = 0; kt < 4; kt++)
        ldsm_x4(aq[kt], smaddr(&Qs[ar * 72 + kt * 16 + ach]));

    float o[8][4];
    #pragma unroll
    for (int nt = 0; nt < 8; nt++)
        #pragma unroll
        for (int r = 0; r < 4; r++) o[nt][r] = 0.f;
    float m0 = -1e30f, m1 = -1e30f, l0 = 0.f, l1 = 0.f;
    const int qr = warp * 16 + lr;

    const int NT = SEQ / 64;
    for (int t = 0; t < NT; t++) {
        int cur = t & 1;
        if (t + 1 < NT) { prefetch_kv(t + 1, cur ^ 1); CP_WAIT(1); }
        else            { CP_WAIT(0); }
        __syncthreads();

        // S = Q @ K^T
        float s[8][4];
        #pragma unroll
        for (int nt = 0; nt < 8; nt++)
            #pragma unroll
            for (int r = 0; r < 4; r++) s[nt][r] = 0.f;
        #pragma unroll
        for (int kt = 0; kt < 4; kt++) {
            uint32_t bb[8][2];
            #pragma unroll
            for (int ntp = 0; ntp < 4; ntp++) {
                uint32_t t4[4];
                ldsm_x4(t4, smaddr(&Ks[cur][br + ntp * 16][kt * 16 + bch]));
                bb[2 * ntp][0] = t4[0]; bb[2 * ntp][1] = t4[1];
                bb[2 * ntp + 1][0] = t4[2]; bb[2 * ntp + 1][1] = t4[3];
            }
            #pragma unroll
            for (int nt = 0; nt < 8; nt++)
                mma_f16(s[nt], aq[kt][0], aq[kt][1], aq[kt][2], aq[kt][3],
                        bb[nt][0], bb[nt][1]);
        }

        // online softmax (fp32)
        float mx0 = s[0][0], mx1 = s[0][2];
        #pragma unroll
        for (int nt = 0; nt < 8; nt++) {
            mx0 = fmaxf(mx0, fmaxf(s[nt][0], s[nt][1]));
            mx1 = fmaxf(mx1, fmaxf(s[nt][2], s[nt][3]));
        }
        mx0 = fmaxf(mx0, __shfl_xor_sync(0xffffffffu, mx0, 1));
        mx0 = fmaxf(mx0, __shfl_xor_sync(0xffffffffu, mx0, 2));
        mx1 = fmaxf(mx1, __shfl_xor_sync(0xffffffffu, mx1, 1));
        mx1 = fmaxf(mx1, __shfl_xor_sync(0xffffffffu, mx1, 2));
        float nm0 = fmaxf(m0, mx0), nm1 = fmaxf(m1, mx1);
        float al0 = __expf(m0 - nm0), al1 = __expf(m1 - nm1);
        m0 = nm0; m1 = nm1;
        float sum0 = 0.f, sum1 = 0.f;
        #pragma unroll
        for (int nt = 0; nt < 8; nt++) {
            s[nt][0] = __expf(s[nt][0] - m0);
            s[nt][1] = __expf(s[nt][1] - m0);
            s[nt][2] = __expf(s[nt][2] - m1);
            s[nt][3] = __expf(s[nt][3] - m1);
            sum0 += s[nt][0] + s[nt][1];
            sum1 += s[nt][2] + s[nt][3];
            o[nt][0] *= al0; o[nt][1] *= al0;
            o[nt][2] *= al1; o[nt][3] *= al1;
        }
        sum0 += __shfl_xor_sync(0xffffffffu, sum0, 1);
        sum0 += __shfl_xor_sync(0xffffffffu, sum0, 2);
        sum1 += __shfl_xor_sync(0xffffffffu, sum1, 1);
        sum1 += __shfl_xor_sync(0xffffffffu, sum1, 2);
        l0 = l0 * al0 + sum0;
        l1 = l1 * al1 + sum1;

        // P -> smem half (C-frag -> A-frag relayout)
        #pragma unroll
        for (int nt = 0; nt < 8; nt++) {
            int col = nt * 8 + 2 * lc;
            *(__half2*)&Ps[qr * 72 + col] =
                __floats2half2_rn(s[nt][0], s[nt][1]);
            *(__half2*)&Ps[(qr + 8) * 72 + col] =
                __floats2half2_rn(s[nt][2], s[nt][3]);
        }
        __syncwarp();

        // O += P @ V
        #pragma unroll
        for (int kt = 0; kt < 4; kt++) {
            uint32_t pa[4];
            ldsm_x4(pa, smaddr(&Ps[ar * 72 + kt * 16 + ach]));
            uint32_t bb[8][2];
            #pragma unroll
            for (int ntp = 0; ntp < 4; ntp++) {
                uint32_t t4[4];
                ldsm_x4(t4, smaddr(&Vst[cur][br + ntp * 16][kt * 16 + bch]));
                bb[2 * ntp][0] = t4[0]; bb[2 * ntp][1] = t4[1];
                bb[2 * ntp + 1][0] = t4[2]; bb[2 * ntp + 1][1] = t4[3];
            }
            #pragma unroll
            for (int nt = 0; nt < 8; nt++)
                mma_f16(o[nt], pa[0], pa[1], pa[2], pa[3], bb[nt][0], bb[nt][1]);
        }
        __syncthreads();
    }

    // epilogue -> half
    float inv0 = 1.f / l0, inv1 = 1.f / l1;
    __half* op0 = Out + (size_t)(n * SEQ + qb * 64 + qr) * EDIM + h * 64;
    __half* op1 = op0 + (size_t)8 * EDIM;
    #pragma unroll
    for (int nt = 0; nt < 8; nt++) {
        int col = nt * 8 + 2 * lc;
        *(__half2*)(op0 + col) = __floats2half2_rn(o[nt][0] * inv0, o[nt][1] * inv0);
        *(__half2*)(op1 + col) = __floats2half2_rn(o[nt][2] * inv1, o[nt][3] * inv1);
    }
}

// ---------------------------------------------------------------------------
extern "C" void kernel_launch(void* const* d_in, const int* in_sizes, int n_in,
                              void* d_out, int out_size)
{
    const float* x  = (const float*)d_in[0];
    const float* W1 = (const float*)d_in[1];
    const float* b1 = (const float*)d_in[2];
    const float* W2 = (const float*)d_in[3];
    const float* b2 = (const float*)d_in[4];
    float* out = (float*)d_out;

    __half *QKbuf, *VTbuf, *Abuf, *Xbuf, *W1Tbuf, *W2Tbuf;
    float* B1Pbuf;
    cudaGetSymbolAddress((void**)&QKbuf,  g_QK);
    cudaGetSymbolAddress((void**)&VTbuf,  g_VT);
    cudaGetSymbolAddress((void**)&Abuf,   g_ATT);
    cudaGetSymbolAddress((void**)&Xbuf,   g_X);
    cudaGetSymbolAddress((void**)&W1Tbuf, g_W1T);
    cudaGetSymbolAddress((void**)&W2Tbuf, g_W2T);
    cudaGetSymbolAddress((void**)&B1Pbuf, g_B1P);

    const int gemm_smem = 2 * 2 * 128 * 40 * 2;   // 40960 B
    const int attn_smem = 4608 * 6 * 2;           // 55296 B
    static bool attr_done = false;
    if (!attr_done) {
        cudaFuncSetAttribute(gemm_f16<0>,
                             cudaFuncAttributeMaxDynamicSharedMemorySize, gemm_smem);
        cudaFuncSetAttribute(gemm_f16<1>,
                             cudaFuncAttributeMaxDynamicSharedMemorySize, gemm_smem);
        cudaFuncSetAttribute(attn_f16,
                             cudaFuncAttributeMaxDynamicSharedMemorySize, attn_smem);
        attr_done = true;
    }

    // pre-pass: x -> half; W1 -> permuted transposed half; W2 -> transposed half
    cvt_half_k<<<(NTOK * EDIM / 4 + 255) / 256, 256>>>((const float4*)x,
                                                       (uint2*)Xbuf, NTOK * EDIM / 4);
    trans_half<true ><<<dim3(H3 / 32, EDIM / 32), dim3(32, 8)>>>(W1, W1Tbuf, EDIM, H3);
    trans_half<false><<<dim3(EDIM / 32, EDIM / 32), dim3(32, 8)>>>(W2, W2Tbuf, EDIM, EDIM);
    permute_b1<<<(H3 + 255) / 256, 256>>>(b1, B1Pbuf);

    // 1) QKV projection: Q(scaled)/K -> g_QK, V -> g_VT transposed
    gemm_f16<1><<<dim3(H3 / 128, NTOK / 128), 256, gemm_smem>>>(
        Xbuf, W1Tbuf, B1Pbuf, QKbuf, VTbuf, 2048, NTOK, 2048, EDIM);
    // 2) attention -> g_ATT (half)
    attn_f16<<<dim3(SEQ / 64, NH, NB), 128, attn_smem>>>(QKbuf, VTbuf, Abuf);
    // 3) output projection -> fp32 out
    gemm_f16<0><<<dim3(EDIM / 128, NTOK / 128), 256, gemm_smem>>>(
        Abuf, W2Tbuf, b2, out, nullptr, 1 << 30, NTOK, EDIM, EDIM);
}

// round 7
// speedup vs baseline: 7.6576x; 1.0272x over previous
#include <cuda_runtime.h>
#include <cuda_fp16.h>
#include <cstdint>

#define NB   4
#define SEQ  2048
#define EDIM 1024
#define H3   3072
#define NH   16
#define NTOK (NB*SEQ)

// Q pre-scale: (1/sqrt(64)) * log2(e)  -> scores land in log2 domain
#define QSCALE 0.180336880111120432f

// Scratch (device globals: allocation-free, graph-capture safe)
__device__ __half g_QK [(size_t)NTOK * 2048];  // [token][Qall(scaled)|Kall]
__device__ __half g_VT [(size_t)EDIM * NTOK];  // [h*64+d][token] (V transposed)
__device__ __half g_ATT[(size_t)NTOK * EDIM];  // attention out
__device__ __half g_X  [(size_t)NTOK * EDIM];  // x in half
__device__ __half g_W1T[(size_t)H3   * EDIM];  // W1^T, rows permuted [Q|K|V]
__device__ __half g_W2T[(size_t)EDIM * EDIM];  // W2^T

__device__ __forceinline__ void mma_f16(float d[4],
                                        uint32_t a0, uint32_t a1, uint32_t a2, uint32_t a3,
                                        uint32_t b0, uint32_t b1) {
    asm volatile(
        "mma.sync.aligned.m16n8k16.row.col.f32.f16.f16.f32 "
        "{%0,%1,%2,%3}, {%4,%5,%6,%7}, {%8,%9}, {%0,%1,%2,%3};"
        : "+f"(d[0]), "+f"(d[1]), "+f"(d[2]), "+f"(d[3])
        : "r"(a0), "r"(a1), "r"(a2), "r"(a3), "r"(b0), "r"(b1));
}
__device__ __forceinline__ uint32_t smaddr(const void* p) {
    return (uint32_t)__cvta_generic_to_shared(p);
}
__device__ __forceinline__ void ldsm_x4(uint32_t r[4], uint32_t addr) {
    asm volatile("ldmatrix.sync.aligned.m8n8.x4.shared.b16 {%0,%1,%2,%3}, [%4];"
                 : "=r"(r[0]), "=r"(r[1]), "=r"(r[2]), "=r"(r[3]) : "r"(addr));
}
__device__ __forceinline__ void cp16(uint32_t dst, const void* src) {
    asm volatile("cp.async.cg.shared.global [%0], [%1], 16;\n" :: "r"(dst), "l"(src));
}
#define CP_COMMIT()  asm volatile("cp.async.commit_group;\n" ::: "memory")
#define CP_WAIT(n)   asm volatile("cp.async.wait_group %0;\n" :: "n"(n) : "memory")

__device__ __forceinline__ float ex2(float x) {
    float y;
    asm("ex2.approx.ftz.f32 %0, %1;" : "=f"(y) : "f"(x));
    return y;
}
__device__ __forceinline__ uint32_t h2u(__half2 h) {
    union { __half2 h; uint32_t u; } c; c.h = h; return c.u;
}

// ---------------------------------------------------------------------------
// Pre-pass kernels
// ---------------------------------------------------------------------------
__global__ void cvt_half_k(const float4* __restrict__ in, uint2* __restrict__ out, int n4) {
    int i = blockIdx.x * blockDim.x + threadIdx.x;
    if (i < n4) {
        float4 v = in[i];
        uint2 o;
        o.x = h2u(__floats2half2_rn(v.x, v.y));
        o.y = h2u(__floats2half2_rn(v.z, v.w));
        out[i] = o;
    }
}

// W [K][NC] fp32 -> WT [NC][K] half. PERM: rows h*192+p*64+d -> p*1024+h*64+d
template<bool PERM>
__global__ void trans_half(const float* __restrict__ W, __half* __restrict__ WT,
                           int K, int NC)
{
    __shared__ float t[32][33];
    int c0 = blockIdx.x * 32, k0 = blockIdx.y * 32;
    #pragma unroll
    for (int i = 0; i < 32; i += 8)
        t[threadIdx.y + i][threadIdx.x] =
            W[(size_t)(k0 + threadIdx.y + i) * NC + c0 + threadIdx.x];
    __syncthreads();
    int cbase = PERM ? ((c0 % 192) / 64) * 1024 + (c0 / 192) * 64 + (c0 % 64) : c0;
    #pragma unroll
    for (int i = 0; i < 32; i += 8) {
        int j = threadIdx.y + i;
        WT[(size_t)(cbase + j) * K + k0 + threadIdx.x] = __float2half_rn(t[threadIdx.x][j]);
    }
}

// ---------------------------------------------------------------------------
// FP16 GEMM: C = A @ Bt^T + bias. A [M][K], Bt [N][K] half, row-major.
// MODE 0: fp32 C, direct bias.
// MODE 1: half C; bias read with inverse QKV permutation; Q cols (<1024)
//         scaled by QSCALE; cols >= nsplit stored transposed to Cvt (half).
// ---------------------------------------------------------------------------
template<int MODE>
__global__ __launch_bounds__(256, 2)
void gemm_f16(const __half* __restrict__ A, const __half* __restrict__ Bt,
              const float* __restrict__ bias, void* __restrict__ Cout,
              __half* __restrict__ Cvt, int nsplit,
              int M, int Nstride, int K)
{
    extern __shared__ __half sh[];
    __half (*As)[128][40] = (__half (*)[128][40])sh;
    __half (*Bs)[128][40] = (__half (*)[128][40])(sh + 2 * 128 * 40);

    const int tid  = threadIdx.x;
    const int bm   = blockIdx.y, bn = blockIdx.x;
    const int warp = tid >> 5, lane = tid & 31;
    const int wm   = (warp >> 2) * 64;
    const int wn   = (warp & 3) * 32;
    const int lr   = lane >> 2, lc = lane & 3;

    const int arow = wm + ((lane >> 3) & 1) * 8 + (lane & 7);
    const int ach  = ((lane >> 4) & 1) * 8;
    const int brow = wn + ((lane >> 4) & 1) * 8 + (lane & 7);
    const int bch  = ((lane >> 3) & 1) * 8;

    const int ntiles = K >> 5;

    float d[4][4][4];
    #pragma unroll
    for (int mt = 0; mt < 4; mt++)
        #pragma unroll
        for (int nt = 0; nt < 4; nt++)
            #pragma unroll
            for (int r = 0; r < 4; r++) d[mt][nt][r] = 0.f;

    auto prefetch = [&](int t, int buf) {
        int k0 = t << 5;
        #pragma unroll
        for (int i = 0; i < 2; i++) {
            int idx = i * 256 + tid;
            int r = idx >> 2, c = idx & 3;
            cp16(smaddr(&As[buf][r][c * 8]), A  + (size_t)(bm * 128 + r) * K + k0 + c * 8);
        }
        #pragma unroll
        for (int i = 0; i < 2; i++) {
            int idx = i * 256 + tid;
            int r = idx >> 2, c = idx & 3;
            cp16(smaddr(&Bs[buf][r][c * 8]), Bt + (size_t)(bn * 128 + r) * K + k0 + c * 8);
        }
        CP_COMMIT();
    };

    prefetch(0, 0);

    for (int t = 0; t < ntiles; t++) {
        int cur = t & 1;
        if (t + 1 < ntiles) { prefetch(t + 1, cur ^ 1); CP_WAIT(1); }
        else                { CP_WAIT(0); }
        __syncthreads();

        #pragma unroll
        for (int kt = 0; kt < 2; kt++) {
            uint32_t a[4][4], b[4][2];
            #pragma unroll
            for (int mt = 0; mt < 4; mt++)
                ldsm_x4(a[mt], smaddr(&As[cur][arow + mt * 16][kt * 16 + ach]));
            #pragma unroll
            for (int ntp = 0; ntp < 2; ntp++) {
                uint32_t t4[4];
                ldsm_x4(t4, smaddr(&Bs[cur][brow + ntp * 16][kt * 16 + bch]));
                b[2 * ntp][0] = t4[0]; b[2 * ntp][1] = t4[1];
                b[2 * ntp + 1][0] = t4[2]; b[2 * ntp + 1][1] = t4[3];
            }
            #pragma unroll
            for (int mt = 0; mt < 4; mt++)
                #pragma unroll
                for (int nt = 0; nt < 4; nt++)
                    mma_f16(d[mt][nt], a[mt][0], a[mt][1], a[mt][2], a[mt][3],
                            b[nt][0], b[nt][1]);
        }
        __syncthreads();
    }

    #pragma unroll
    for (int mt = 0; mt < 4; mt++) {
        #pragma unroll
        for (int nt = 0; nt < 4; nt++) {
            int row  = bm * 128 + wm + mt * 16 + lr;
            int colg = bn * 128 + wn + nt * 8 + 2 * lc;
            float2 bv;
            if (MODE == 1) {   // inverse QKV permutation of bias index
                int map = ((colg & 1023) >> 6) * 192 + (colg >> 10) * 64 + (colg & 63);
                bv = *(const float2*)(bias + map);
            } else {
                bv = *(const float2*)(bias + colg);
            }
            float e0 = d[mt][nt][0] + bv.x, e1 = d[mt][nt][1] + bv.y;
            float e2 = d[mt][nt][2] + bv.x, e3 = d[mt][nt][3] + bv.y;
            if (MODE == 0) {
                float* C = (float*)Cout;
                *(float2*)(C + (size_t)row * Nstride + colg)       = make_float2(e0, e1);
                *(float2*)(C + (size_t)(row + 8) * Nstride + colg) = make_float2(e2, e3);
            } else {
                if (colg >= nsplit) {   // V third -> transposed half
                    __half* p0 = Cvt + (size_t)(colg - nsplit) * M;
                    __half* p1 = p0 + M;
                    p0[row]     = __float2half_rn(e0);
                    p1[row]     = __float2half_rn(e1);
                    p0[row + 8] = __float2half_rn(e2);
                    p1[row + 8] = __float2half_rn(e3);
                } else {
                    float s = (colg < 1024) ? QSCALE : 1.0f;   // pre-scale Q (log2 domain)
                    __half* C = (__half*)Cout;
                    *(__half2*)(C + (size_t)row * Nstride + colg) =
                        __floats2half2_rn(e0 * s, e1 * s);
                    *(__half2*)(C + (size_t)(row + 8) * Nstride + colg) =
                        __floats2half2_rn(e2 * s, e3 * s);
                }
            }
        }
    }
}

// ---------------------------------------------------------------------------
// Flash attention, fp16 mma + ldmatrix, cp.async double-buffered K/V.
// Scores in log2 domain (Q pre-scaled). l accumulated via ones-row mma.
// grid=(SEQ/64, NH, NB), block=128 (4 warps x 16 q rows).
// smem halves: Qs[64][72] | Ks[2][64][72] | Vst[2][80][72] | Ps[64][72]
// ---------------------------------------------------------------------------
__global__ __launch_bounds__(128, 3)
void attn_f16(const __half* __restrict__ Qk, const __half* __restrict__ Vt,
              __half* __restrict__ Out)
{
    extern __shared__ __half smp[];
    __half* Qs = smp;                                        // [64][72]
    __half (*Ks )[64][72] = (__half (*)[64][72])(smp + 4608);
    __half (*Vst)[80][72] = (__half (*)[80][72])(smp + 4608 * 3);
    __half* Ps = smp + 4608 * 3 + 2 * 80 * 72;               // [64][72]

    const int qb = blockIdx.x, h = blockIdx.y, n = blockIdx.z;
    const int tid = threadIdx.x, warp = tid >> 5, lane = tid & 31;
    const int lr = lane >> 2, lc = lane & 3;

    const __half* Qbase = Qk + (size_t)(n * SEQ) * 2048 + h * 64;
    const __half* Kbase = Qbase + 1024;
    const __half* Vbase = Vt + (size_t)(h * 64) * NTOK + n * SEQ;

    const int ar  = warp * 16 + ((lane >> 3) & 1) * 8 + (lane & 7);
    const int ach = ((lane >> 4) & 1) * 8;
    const int br  = ((lane >> 4) & 1) * 8 + (lane & 7);
    const int bch = ((lane >> 3) & 1) * 8;

    auto prefetch_kv = [&](int t, int buf) {
        #pragma unroll
        for (int i = 0; i < 4; i++) {
            int idx = i * 128 + tid;
            int r = idx >> 3, c = idx & 7;
            cp16(smaddr(&Ks[buf][r][c * 8]),
                 Kbase + (size_t)(t * 64 + r) * 2048 + c * 8);
            cp16(smaddr(&Vst[buf][r][c * 8]),
                 Vbase + (size_t)r * NTOK + t * 64 + c * 8);
        }
        CP_COMMIT();
    };

    prefetch_kv(0, 0);
    // stage Q (already scaled by QSCALE in GEMM1)
    #pragma unroll
    for (int i = 0; i < 4; i++) {
        int idx = i * 128 + tid;
        int r = idx >> 3, c = idx & 7;
        cp16(smaddr(&Qs[r * 72 + c * 8]),
             Qbase + (size_t)(qb * 64 + r) * 2048 + c * 8);
    }
    CP_COMMIT();

    // static ones-row block: Vst rows 64..79 (row 64 = 1, rest 0), both buffers
    for (int i = tid; i < 2 * 16 * 72; i += 128) {
        int buf = i / (16 * 72);
        int rem = i - buf * (16 * 72);
        int r = rem / 72, c = rem - r * 72;
        Vst[buf][64 + r][c] = __float2half((r == 0) ? 1.f : 0.f);
    }

    CP_WAIT(0);
    __syncthreads();

    uint32_t aq[4][4];
    #pragma unroll
    for (int kt = 0; kt < 4; kt++)
        ldsm_x4(aq[kt], smaddr(&Qs[ar * 72 + kt * 16 + ach]));

    float o[9][4];
    #pragma unroll
    for (int nt = 0; nt < 9; nt++)
        #pragma unroll
        for (int r = 0; r < 4; r++) o[nt][r] = 0.f;
    float m0 = -1e30f, m1 = -1e30f;
    const int qr = warp * 16 + lr;

    const int NT = SEQ / 64;
    for (int t = 0; t < NT; t++) {
        int cur = t & 1;
        if (t + 1 < NT) { prefetch_kv(t + 1, cur ^ 1); CP_WAIT(1); }
        else            { CP_WAIT(0); }
        __syncthreads();

        // S = Q @ K^T  (log2 domain)
        float s[8][4];
        #pragma unroll
        for (int nt = 0; nt < 8; nt++)
            #pragma unroll
            for (int r = 0; r < 4; r++) s[nt][r] = 0.f;
        #pragma unroll
        for (int kt = 0; kt < 4; kt++) {
            uint32_t bb[8][2];
            #pragma unroll
            for (int ntp = 0; ntp < 4; ntp++) {
                uint32_t t4[4];
                ldsm_x4(t4, smaddr(&Ks[cur][br + ntp * 16][kt * 16 + bch]));
                bb[2 * ntp][0] = t4[0]; bb[2 * ntp][1] = t4[1];
                bb[2 * ntp + 1][0] = t4[2]; bb[2 * ntp + 1][1] = t4[3];
            }
            #pragma unroll
            for (int nt = 0; nt < 8; nt++)
                mma_f16(s[nt], aq[kt][0], aq[kt][1], aq[kt][2], aq[kt][3],
                        bb[nt][0], bb[nt][1]);
        }

        // online softmax (fp32 stats; exp2)
        float mx0 = s[0][0], mx1 = s[0][2];
        #pragma unroll
        for (int nt = 0; nt < 8; nt++) {
            mx0 = fmaxf(mx0, fmaxf(s[nt][0], s[nt][1]));
            mx1 = fmaxf(mx1, fmaxf(s[nt][2], s[nt][3]));
        }
        mx0 = fmaxf(mx0, __shfl_xor_sync(0xffffffffu, mx0, 1));
        mx0 = fmaxf(mx0, __shfl_xor_sync(0xffffffffu, mx0, 2));
        mx1 = fmaxf(mx1, __shfl_xor_sync(0xffffffffu, mx1, 1));
        mx1 = fmaxf(mx1, __shfl_xor_sync(0xffffffffu, mx1, 2));
        float nm0 = fmaxf(m0, mx0), nm1 = fmaxf(m1, mx1);
        float al0 = ex2(m0 - nm0), al1 = ex2(m1 - nm1);
        m0 = nm0; m1 = nm1;
        if (!__all_sync(0xffffffffu, (al0 == 1.f) && (al1 == 1.f))) {
            #pragma unroll
            for (int nt = 0; nt < 9; nt++) {
                o[nt][0] *= al0; o[nt][1] *= al0;
                o[nt][2] *= al1; o[nt][3] *= al1;
            }
        }

        // P = 2^(s-m) -> half, straight into Ps (A-frag layout)
        #pragma unroll
        for (int nt = 0; nt < 8; nt++) {
            int col = nt * 8 + 2 * lc;
            *(__half2*)&Ps[qr * 72 + col] =
                __floats2half2_rn(ex2(s[nt][0] - m0), ex2(s[nt][1] - m0));
            *(__half2*)&Ps[(qr + 8) * 72 + col] =
                __floats2half2_rn(ex2(s[nt][2] - m1), ex2(s[nt][3] - m1));
        }
        __syncwarp();

        // O += P @ [V ; ones-row]   (nt=8 accumulates l)
        #pragma unroll
        for (int kt = 0; kt < 4; kt++) {
            uint32_t pa[4];
            ldsm_x4(pa, smaddr(&Ps[ar * 72 + kt * 16 + ach]));
            uint32_t bb[10][2];
            #pragma unroll
            for (int ntp = 0; ntp < 5; ntp++) {
                uint32_t t4[4];
                ldsm_x4(t4, smaddr(&Vst[cur][br + ntp * 16][kt * 16 + bch]));
                bb[2 * ntp][0] = t4[0]; bb[2 * ntp][1] = t4[1];
                bb[2 * ntp + 1][0] = t4[2]; bb[2 * ntp + 1][1] = t4[3];
            }
            #pragma unroll
            for (int nt = 0; nt < 9; nt++)
                mma_f16(o[nt], pa[0], pa[1], pa[2], pa[3], bb[nt][0], bb[nt][1]);
        }
        __syncthreads();
    }

    // l lives in o[8][0]/o[8][2] of the lc==0 lane of each quad
    float l0 = __shfl_sync(0xffffffffu, o[8][0], lane & 28);
    float l1 = __shfl_sync(0xffffffffu, o[8][2], lane & 28);
    float inv0 = 1.f / l0, inv1 = 1.f / l1;
    __half* op0 = Out + (size_t)(n * SEQ + qb * 64 + qr) * EDIM + h * 64;
    __half* op1 = op0 + (size_t)8 * EDIM;
    #pragma unroll
    for (int nt = 0; nt < 8; nt++) {
        int col = nt * 8 + 2 * lc;
        *(__half2*)(op0 + col) = __floats2half2_rn(o[nt][0] * inv0, o[nt][1] * inv0);
        *(__half2*)(op1 + col) = __floats2half2_rn(o[nt][2] * inv1, o[nt][3] * inv1);
    }
}

// ---------------------------------------------------------------------------
extern "C" void kernel_launch(void* const* d_in, const int* in_sizes, int n_in,
                              void* d_out, int out_size)
{
    const float* x  = (const float*)d_in[0];
    const float* W1 = (const float*)d_in[1];
    const float* b1 = (const float*)d_in[2];
    const float* W2 = (const float*)d_in[3];
    const float* b2 = (const float*)d_in[4];
    float* out = (float*)d_out;

    __half *QKbuf, *VTbuf, *Abuf, *Xbuf, *W1Tbuf, *W2Tbuf;
    cudaGetSymbolAddress((void**)&QKbuf,  g_QK);
    cudaGetSymbolAddress((void**)&VTbuf,  g_VT);
    cudaGetSymbolAddress((void**)&Abuf,   g_ATT);
    cudaGetSymbolAddress((void**)&Xbuf,   g_X);
    cudaGetSymbolAddress((void**)&W1Tbuf, g_W1T);
    cudaGetSymbolAddress((void**)&W2Tbuf, g_W2T);

    const int gemm_smem = 2 * 2 * 128 * 40 * 2;              // 40960 B
    const int attn_smem = (4608 * 4 + 2 * 80 * 72) * 2;      // 59904 B
    static bool attr_done = false;
    if (!attr_done) {
        cudaFuncSetAttribute(gemm_f16<0>,
                             cudaFuncAttributeMaxDynamicSharedMemorySize, gemm_smem);
        cudaFuncSetAttribute(gemm_f16<1>,
                             cudaFuncAttributeMaxDynamicSharedMemorySize, gemm_smem);
        cudaFuncSetAttribute(attn_f16,
                             cudaFuncAttributeMaxDynamicSharedMemorySize, attn_smem);
        attr_done = true;
    }

    // pre-pass: x -> half; W1 -> permuted transposed half; W2 -> transposed half
    cvt_half_k<<<(NTOK * EDIM / 4 + 255) / 256, 256>>>((const float4*)x,
                                                       (uint2*)Xbuf, NTOK * EDIM / 4);
    trans_half<true ><<<dim3(H3 / 32, EDIM / 32), dim3(32, 8)>>>(W1, W1Tbuf, EDIM, H3);
    trans_half<false><<<dim3(EDIM / 32, EDIM / 32), dim3(32, 8)>>>(W2, W2Tbuf, EDIM, EDIM);

    // 1) QKV projection: Q(scaled)/K -> g_QK, V -> g_VT transposed
    gemm_f16<1><<<dim3(H3 / 128, NTOK / 128), 256, gemm_smem>>>(
        Xbuf, W1Tbuf, b1, QKbuf, VTbuf, 2048, NTOK, 2048, EDIM);
    // 2) attention -> g_ATT (half)
    attn_f16<<<dim3(SEQ / 64, NH, NB), 128, attn_smem>>>(QKbuf, VTbuf, Abuf);
    // 3) output projection -> fp32 out
    gemm_f16<0><<<dim3(EDIM / 128, NTOK / 128), 256, gemm_smem>>>(
        Abuf, W2Tbuf, b2, out, nullptr, 1 << 30, NTOK, EDIM, EDIM);
}

// round 8
// speedup vs baseline: 8.0386x; 1.0498x over previous
#include <cuda_runtime.h>
#include <cuda_fp16.h>
#include <cstdint>

#define NB   4
#define SEQ  2048
#define EDIM 1024
#define H3   3072
#define NH   16
#define NTOK (NB*SEQ)

// Q pre-scale: (1/sqrt(64)) * log2(e)  -> scores land in log2 domain
#define QSCALE 0.180336880111120432f

// Scratch (device globals: allocation-free, graph-capture safe)
__device__ __half g_QK [(size_t)NTOK * 2048];  // [token][Qall(scaled)|Kall]
__device__ __half g_VT [(size_t)EDIM * NTOK];  // [h*64+d][token] (V transposed)
__device__ __half g_ATT[(size_t)NTOK * EDIM];  // attention out
__device__ __half g_X  [(size_t)NTOK * EDIM];  // x in half
__device__ __half g_W1T[(size_t)H3   * EDIM];  // W1^T, rows permuted [Q|K|V]
__device__ __half g_W2T[(size_t)EDIM * EDIM];  // W2^T

__device__ __forceinline__ void mma_f16(float d[4],
                                        uint32_t a0, uint32_t a1, uint32_t a2, uint32_t a3,
                                        uint32_t b0, uint32_t b1) {
    asm volatile(
        "mma.sync.aligned.m16n8k16.row.col.f32.f16.f16.f32 "
        "{%0,%1,%2,%3}, {%4,%5,%6,%7}, {%8,%9}, {%0,%1,%2,%3};"
        : "+f"(d[0]), "+f"(d[1]), "+f"(d[2]), "+f"(d[3])
        : "r"(a0), "r"(a1), "r"(a2), "r"(a3), "r"(b0), "r"(b1));
}
__device__ __forceinline__ uint32_t smaddr(const void* p) {
    return (uint32_t)__cvta_generic_to_shared(p);
}
__device__ __forceinline__ void ldsm_x4(uint32_t r[4], uint32_t addr) {
    asm volatile("ldmatrix.sync.aligned.m8n8.x4.shared.b16 {%0,%1,%2,%3}, [%4];"
                 : "=r"(r[0]), "=r"(r[1]), "=r"(r[2]), "=r"(r[3]) : "r"(addr));
}
__device__ __forceinline__ void cp16(uint32_t dst, const void* src) {
    asm volatile("cp.async.cg.shared.global [%0], [%1], 16;\n" :: "r"(dst), "l"(src));
}
#define CP_COMMIT()  asm volatile("cp.async.commit_group;\n" ::: "memory")
#define CP_WAIT(n)   asm volatile("cp.async.wait_group %0;\n" :: "n"(n) : "memory")

__device__ __forceinline__ float ex2(float x) {
    float y;
    asm("ex2.approx.ftz.f32 %0, %1;" : "=f"(y) : "f"(x));
    return y;
}
// packed: returns half2 { lo = 2^lo_in, hi = 2^hi_in }
__device__ __forceinline__ uint32_t ex2_h2(float lo, float hi) {
    uint32_t c, r;
    asm("cvt.rn.f16x2.f32 %0, %1, %2;" : "=r"(c) : "f"(hi), "f"(lo));
    asm("ex2.approx.f16x2 %0, %1;" : "=r"(r) : "r"(c));
    return r;
}
__device__ __forceinline__ uint32_t h2u(__half2 h) {
    union { __half2 h; uint32_t u; } c; c.h = h; return c.u;
}

// ---------------------------------------------------------------------------
// Pre-pass kernels
// ---------------------------------------------------------------------------
__global__ void cvt_half_k(const float4* __restrict__ in, uint2* __restrict__ out, int n4) {
    int i = blockIdx.x * blockDim.x + threadIdx.x;
    if (i < n4) {
        float4 v = in[i];
        uint2 o;
        o.x = h2u(__floats2half2_rn(v.x, v.y));
        o.y = h2u(__floats2half2_rn(v.z, v.w));
        out[i] = o;
    }
}

// W [K][NC] fp32 -> WT [NC][K] half. PERM: rows h*192+p*64+d -> p*1024+h*64+d
template<bool PERM>
__global__ void trans_half(const float* __restrict__ W, __half* __restrict__ WT,
                           int K, int NC)
{
    __shared__ float t[32][33];
    int c0 = blockIdx.x * 32, k0 = blockIdx.y * 32;
    #pragma unroll
    for (int i = 0; i < 32; i += 8)
        t[threadIdx.y + i][threadIdx.x] =
            W[(size_t)(k0 + threadIdx.y + i) * NC + c0 + threadIdx.x];
    __syncthreads();
    int cbase = PERM ? ((c0 % 192) / 64) * 1024 + (c0 / 192) * 64 + (c0 % 64) : c0;
    #pragma unroll
    for (int i = 0; i < 32; i += 8) {
        int j = threadIdx.y + i;
        WT[(size_t)(cbase + j) * K + k0 + threadIdx.x] = __float2half_rn(t[threadIdx.x][j]);
    }
}

// ---------------------------------------------------------------------------
// FP16 GEMM: C = A @ Bt^T + bias. A [M][K], Bt [N][K] half, row-major.
// 128x128x32 tile, 256 thr, 3-stage cp.async (single sync/iter), ldmatrix.
// MODE 0: fp32 C, direct bias.
// MODE 1: half C; bias read with inverse QKV permutation; Q cols (<1024)
//         scaled by QSCALE; cols >= nsplit stored transposed to Cvt (half).
// ---------------------------------------------------------------------------
template<int MODE>
__global__ __launch_bounds__(256, 2)
void gemm_f16(const __half* __restrict__ A, const __half* __restrict__ Bt,
              const float* __restrict__ bias, void* __restrict__ Cout,
              __half* __restrict__ Cvt, int nsplit,
              int M, int Nstride, int K)
{
    extern __shared__ __half sh[];
    __half (*As)[128][40] = (__half (*)[128][40])sh;                 // 3 stages
    __half (*Bs)[128][40] = (__half (*)[128][40])(sh + 3 * 128 * 40);

    const int tid  = threadIdx.x;
    const int bm   = blockIdx.y, bn = blockIdx.x;
    const int warp = tid >> 5, lane = tid & 31;
    const int wm   = (warp >> 2) * 64;
    const int wn   = (warp & 3) * 32;
    const int lr   = lane >> 2, lc = lane & 3;

    const int arow = wm + ((lane >> 3) & 1) * 8 + (lane & 7);
    const int ach  = ((lane >> 4) & 1) * 8;
    const int brow = wn + ((lane >> 4) & 1) * 8 + (lane & 7);
    const int bch  = ((lane >> 3) & 1) * 8;

    const int ntiles = K >> 5;

    float d[4][4][4];
    #pragma unroll
    for (int mt = 0; mt < 4; mt++)
        #pragma unroll
        for (int nt = 0; nt < 4; nt++)
            #pragma unroll
            for (int r = 0; r < 4; r++) d[mt][nt][r] = 0.f;

    auto prefetch = [&](int t, int buf) {
        int k0 = t << 5;
        #pragma unroll
        for (int i = 0; i < 2; i++) {
            int idx = i * 256 + tid;
            int r = idx >> 2, c = idx & 3;
            cp16(smaddr(&As[buf][r][c * 8]), A  + (size_t)(bm * 128 + r) * K + k0 + c * 8);
        }
        #pragma unroll
        for (int i = 0; i < 2; i++) {
            int idx = i * 256 + tid;
            int r = idx >> 2, c = idx & 3;
            cp16(smaddr(&Bs[buf][r][c * 8]), Bt + (size_t)(bn * 128 + r) * K + k0 + c * 8);
        }
        CP_COMMIT();
    };

    prefetch(0, 0);
    prefetch(1, 1);

    for (int t = 0; t < ntiles; t++) {
        int cur = t % 3;
        if (t + 1 < ntiles) { CP_WAIT(1); } else { CP_WAIT(0); }
        __syncthreads();
        if (t + 2 < ntiles) prefetch(t + 2, (t + 2) % 3);

        #pragma unroll
        for (int kt = 0; kt < 2; kt++) {
            uint32_t a[4][4], b[4][2];
            #pragma unroll
            for (int mt = 0; mt < 4; mt++)
                ldsm_x4(a[mt], smaddr(&As[cur][arow + mt * 16][kt * 16 + ach]));
            #pragma unroll
            for (int ntp = 0; ntp < 2; ntp++) {
                uint32_t t4[4];
                ldsm_x4(t4, smaddr(&Bs[cur][brow + ntp * 16][kt * 16 + bch]));
                b[2 * ntp][0] = t4[0]; b[2 * ntp][1] = t4[1];
                b[2 * ntp + 1][0] = t4[2]; b[2 * ntp + 1][1] = t4[3];
            }
            #pragma unroll
            for (int mt = 0; mt < 4; mt++)
                #pragma unroll
                for (int nt = 0; nt < 4; nt++)
                    mma_f16(d[mt][nt], a[mt][0], a[mt][1], a[mt][2], a[mt][3],
                            b[nt][0], b[nt][1]);
        }
    }

    #pragma unroll
    for (int mt = 0; mt < 4; mt++) {
        #pragma unroll
        for (int nt = 0; nt < 4; nt++) {
            int row  = bm * 128 + wm + mt * 16 + lr;
            int colg = bn * 128 + wn + nt * 8 + 2 * lc;
            float2 bv;
            if (MODE == 1) {   // inverse QKV permutation of bias index
                int map = ((colg & 1023) >> 6) * 192 + (colg >> 10) * 64 + (colg & 63);
                bv = *(const float2*)(bias + map);
            } else {
                bv = *(const float2*)(bias + colg);
            }
            float e0 = d[mt][nt][0] + bv.x, e1 = d[mt][nt][1] + bv.y;
            float e2 = d[mt][nt][2] + bv.x, e3 = d[mt][nt][3] + bv.y;
            if (MODE == 0) {
                float* C = (float*)Cout;
                *(float2*)(C + (size_t)row * Nstride + colg)       = make_float2(e0, e1);
                *(float2*)(C + (size_t)(row + 8) * Nstride + colg) = make_float2(e2, e3);
            } else {
                if (colg >= nsplit) {   // V third -> transposed half
                    __half* p0 = Cvt + (size_t)(colg - nsplit) * M;
                    __half* p1 = p0 + M;
                    p0[row]     = __float2half_rn(e0);
                    p1[row]     = __float2half_rn(e1);
                    p0[row + 8] = __float2half_rn(e2);
                    p1[row + 8] = __float2half_rn(e3);
                } else {
                    float s = (colg < 1024) ? QSCALE : 1.0f;   // pre-scale Q (log2 domain)
                    __half* C = (__half*)Cout;
                    *(__half2*)(C + (size_t)row * Nstride + colg) =
                        __floats2half2_rn(e0 * s, e1 * s);
                    *(__half2*)(C + (size_t)(row + 8) * Nstride + colg) =
                        __floats2half2_rn(e2 * s, e3 * s);
                }
            }
        }
    }
}

// ---------------------------------------------------------------------------
// Flash attention, fp16 mma + ldmatrix, 3-stage cp.async (single sync/tile).
// Scores in log2 domain (Q pre-scaled). l via ones-row mma. P kept in
// registers (f16 C-frag == A-frag identity). ex2.approx.f16x2 for P.
// grid=(SEQ/64, NH, NB), block=128 (4 warps x 16 q rows).
// smem halves: Qs[64][72] | Ks[3][64][72] | Vst[3][80][72]  = 71424 B
// ---------------------------------------------------------------------------
__global__ __launch_bounds__(128, 3)
void attn_f16(const __half* __restrict__ Qk, const __half* __restrict__ Vt,
              __half* __restrict__ Out)
{
    extern __shared__ __half smp[];
    __half* Qs = smp;                                        // [64][72]
    __half (*Ks )[64][72] = (__half (*)[64][72])(smp + 4608);
    __half (*Vst)[80][72] = (__half (*)[80][72])(smp + 4608 + 3 * 64 * 72);

    const int qb = blockIdx.x, h = blockIdx.y, n = blockIdx.z;
    const int tid = threadIdx.x, warp = tid >> 5, lane = tid & 31;
    const int lr = lane >> 2, lc = lane & 3;

    const __half* Qbase = Qk + (size_t)(n * SEQ) * 2048 + h * 64;
    const __half* Kbase = Qbase + 1024;
    const __half* Vbase = Vt + (size_t)(h * 64) * NTOK + n * SEQ;

    const int ar  = warp * 16 + ((lane >> 3) & 1) * 8 + (lane & 7);
    const int ach = ((lane >> 4) & 1) * 8;
    const int br  = ((lane >> 4) & 1) * 8 + (lane & 7);
    const int bch = ((lane >> 3) & 1) * 8;

    auto prefetch_kv = [&](int t, int buf) {
        #pragma unroll
        for (int i = 0; i < 4; i++) {
            int idx = i * 128 + tid;
            int r = idx >> 3, c = idx & 7;
            cp16(smaddr(&Ks[buf][r][c * 8]),
                 Kbase + (size_t)(t * 64 + r) * 2048 + c * 8);
            cp16(smaddr(&Vst[buf][r][c * 8]),
                 Vbase + (size_t)r * NTOK + t * 64 + c * 8);
        }
        CP_COMMIT();
    };

    // group 0 = Q + kv tile 0 (shared commit), group 1 = kv tile 1
    #pragma unroll
    for (int i = 0; i < 4; i++) {
        int idx = i * 128 + tid;
        int r = idx >> 3, c = idx & 7;
        cp16(smaddr(&Qs[r * 72 + c * 8]),
             Qbase + (size_t)(qb * 64 + r) * 2048 + c * 8);
    }
    prefetch_kv(0, 0);     // commits Q copies + kv0 together
    prefetch_kv(1, 1);

    // static ones rows: Vst rows 64..79 (row 64 = 1), all 3 buffers
    for (int i = tid; i < 3 * 16 * 72; i += 128) {
        int buf = i / (16 * 72);
        int rem = i - buf * (16 * 72);
        int r = rem / 72, c = rem - r * 72;
        Vst[buf][64 + r][c] = __float2half((r == 0) ? 1.f : 0.f);
    }

    CP_WAIT(1);            // Q + kv0 ready
    __syncthreads();

    uint32_t aq[4][4];
    #pragma unroll
    for (int kt = 0; kt < 4; kt++)
        ldsm_x4(aq[kt], smaddr(&Qs[ar * 72 + kt * 16 + ach]));

    float o[9][4];
    #pragma unroll
    for (int nt = 0; nt < 9; nt++)
        #pragma unroll
        for (int r = 0; r < 4; r++) o[nt][r] = 0.f;
    float m0 = -1e30f, m1 = -1e30f;
    const int qr = warp * 16 + lr;

    const int NT = SEQ / 64;
    for (int t = 0; t < NT; t++) {
        int cur = t % 3;
        if (t > 0) {       // t==0 already waited+synced above
            if (t + 1 < NT) { CP_WAIT(1); } else { CP_WAIT(0); }
            __syncthreads();
        }
        if (t + 2 < NT) prefetch_kv(t + 2, (t + 2) % 3);

        // S = Q @ K^T  (log2 domain)
        float s[8][4];
        #pragma unroll
        for (int nt = 0; nt < 8; nt++)
            #pragma unroll
            for (int r = 0; r < 4; r++) s[nt][r] = 0.f;
        #pragma unroll
        for (int kt = 0; kt < 4; kt++) {
            uint32_t bb[8][2];
            #pragma unroll
            for (int ntp = 0; ntp < 4; ntp++) {
                uint32_t t4[4];
                ldsm_x4(t4, smaddr(&Ks[cur][br + ntp * 16][kt * 16 + bch]));
                bb[2 * ntp][0] = t4[0]; bb[2 * ntp][1] = t4[1];
                bb[2 * ntp + 1][0] = t4[2]; bb[2 * ntp + 1][1] = t4[3];
            }
            #pragma unroll
            for (int nt = 0; nt < 8; nt++)
                mma_f16(s[nt], aq[kt][0], aq[kt][1], aq[kt][2], aq[kt][3],
                        bb[nt][0], bb[nt][1]);
        }

        // online softmax (fp32 stats; exp2)
        float mx0 = s[0][0], mx1 = s[0][2];
        #pragma unroll
        for (int nt = 0; nt < 8; nt++) {
            mx0 = fmaxf(mx0, fmaxf(s[nt][0], s[nt][1]));
            mx1 = fmaxf(mx1, fmaxf(s[nt][2], s[nt][3]));
        }
        mx0 = fmaxf(mx0, __shfl_xor_sync(0xffffffffu, mx0, 1));
        mx0 = fmaxf(mx0, __shfl_xor_sync(0xffffffffu, mx0, 2));
        mx1 = fmaxf(mx1, __shfl_xor_sync(0xffffffffu, mx1, 1));
        mx1 = fmaxf(mx1, __shfl_xor_sync(0xffffffffu, mx1, 2));
        float nm0 = fmaxf(m0, mx0), nm1 = fmaxf(m1, mx1);
        float al0 = ex2(m0 - nm0), al1 = ex2(m1 - nm1);
        m0 = nm0; m1 = nm1;
        if (!__all_sync(0xffffffffu, (al0 == 1.f) && (al1 == 1.f))) {
            #pragma unroll
            for (int nt = 0; nt < 9; nt++) {
                o[nt][0] *= al0; o[nt][1] *= al0;
                o[nt][2] *= al1; o[nt][3] *= al1;
            }
        }

        // P = 2^(s-m), packed f16x2, kept in registers (C-frag == A-frag)
        uint32_t p01[8], p23[8];
        #pragma unroll
        for (int nt = 0; nt < 8; nt++) {
            p01[nt] = ex2_h2(s[nt][0] - m0, s[nt][1] - m0);
            p23[nt] = ex2_h2(s[nt][2] - m1, s[nt][3] - m1);
        }

        // O += P @ [V ; ones-row]   (nt=8 accumulates l)
        #pragma unroll
        for (int kt = 0; kt < 4; kt++) {
            uint32_t a0 = p01[2 * kt],     a1 = p23[2 * kt];
            uint32_t a2 = p01[2 * kt + 1], a3 = p23[2 * kt + 1];
            uint32_t bb[10][2];
            #pragma unroll
            for (int ntp = 0; ntp < 5; ntp++) {
                uint32_t t4[4];
                ldsm_x4(t4, smaddr(&Vst[cur][br + ntp * 16][kt * 16 + bch]));
                bb[2 * ntp][0] = t4[0]; bb[2 * ntp][1] = t4[1];
                bb[2 * ntp + 1][0] = t4[2]; bb[2 * ntp + 1][1] = t4[3];
            }
            #pragma unroll
            for (int nt = 0; nt < 9; nt++)
                mma_f16(o[nt], a0, a1, a2, a3, bb[nt][0], bb[nt][1]);
        }
    }

    // l lives in o[8][0]/o[8][2] of the lc==0 lane of each quad
    float l0 = __shfl_sync(0xffffffffu, o[8][0], lane & 28);
    float l1 = __shfl_sync(0xffffffffu, o[8][2], lane & 28);
    float inv0 = 1.f / l0, inv1 = 1.f / l1;
    __half* op0 = Out + (size_t)(n * SEQ + qb * 64 + qr) * EDIM + h * 64;
    __half* op1 = op0 + (size_t)8 * EDIM;
    #pragma unroll
    for (int nt = 0; nt < 8; nt++) {
        int col = nt * 8 + 2 * lc;
        *(__half2*)(op0 + col) = __floats2half2_rn(o[nt][0] * inv0, o[nt][1] * inv0);
        *(__half2*)(op1 + col) = __floats2half2_rn(o[nt][2] * inv1, o[nt][3] * inv1);
    }
}

// ---------------------------------------------------------------------------
extern "C" void kernel_launch(void* const* d_in, const int* in_sizes, int n_in,
                              void* d_out, int out_size)
{
    const float* x  = (const float*)d_in[0];
    const float* W1 = (const float*)d_in[1];
    const float* b1 = (const float*)d_in[2];
    const float* W2 = (const float*)d_in[3];
    const float* b2 = (const float*)d_in[4];
    float* out = (float*)d_out;

    __half *QKbuf, *VTbuf, *Abuf, *Xbuf, *W1Tbuf, *W2Tbuf;
    cudaGetSymbolAddress((void**)&QKbuf,  g_QK);
    cudaGetSymbolAddress((void**)&VTbuf,  g_VT);
    cudaGetSymbolAddress((void**)&Abuf,   g_ATT);
    cudaGetSymbolAddress((void**)&Xbuf,   g_X);
    cudaGetSymbolAddress((void**)&W1Tbuf, g_W1T);
    cudaGetSymbolAddress((void**)&W2Tbuf, g_W2T);

    const int gemm_smem = 3 * 2 * 128 * 40 * 2;                  // 61440 B
    const int attn_smem = (4608 + 3 * 64 * 72 + 3 * 80 * 72) * 2; // 71424 B
    static bool attr_done = false;
    if (!attr_done) {
        cudaFuncSetAttribute(gemm_f16<0>,
                             cudaFuncAttributeMaxDynamicSharedMemorySize, gemm_smem);
        cudaFuncSetAttribute(gemm_f16<1>,
                             cudaFuncAttributeMaxDynamicSharedMemorySize, gemm_smem);
        cudaFuncSetAttribute(attn_f16,
                             cudaFuncAttributeMaxDynamicSharedMemorySize, attn_smem);
        attr_done = true;
    }

    // pre-pass: x -> half; W1 -> permuted transposed half; W2 -> transposed half
    cvt_half_k<<<(NTOK * EDIM / 4 + 255) / 256, 256>>>((const float4*)x,
                                                       (uint2*)Xbuf, NTOK * EDIM / 4);
    trans_half<true ><<<dim3(H3 / 32, EDIM / 32), dim3(32, 8)>>>(W1, W1Tbuf, EDIM, H3);
    trans_half<false><<<dim3(EDIM / 32, EDIM / 32), dim3(32, 8)>>>(W2, W2Tbuf, EDIM, EDIM);

    // 1) QKV projection: Q(scaled)/K -> g_QK, V -> g_VT transposed
    gemm_f16<1><<<dim3(H3 / 128, NTOK / 128), 256, gemm_smem>>>(
        Xbuf, W1Tbuf, b1, QKbuf, VTbuf, 2048, NTOK, 2048, EDIM);
    // 2) attention -> g_ATT (half)
    attn_f16<<<dim3(SEQ / 64, NH, NB), 128, attn_smem>>>(QKbuf, VTbuf, Abuf);
    // 3) output projection -> fp32 out
    gemm_f16<0><<<dim3(EDIM / 128, NTOK / 128), 256, gemm_smem>>>(
        Abuf, W2Tbuf, b2, out, nullptr, 1 << 30, NTOK, EDIM, EDIM);
}

// round 9
// speedup vs baseline: 8.9431x; 1.1125x over previous
#include <cuda_runtime.h>
#include <cuda_fp16.h>
#include <cstdint>

#define NB   4
#define SEQ  2048
#define EDIM 1024
#define H3   3072
#define NH   16
#define NTOK (NB*SEQ)

// Q pre-scale: (1/sqrt(64)) * log2(e)  -> scores land in log2 domain
#define QSCALE 0.180336880111120432f

// Scratch (device globals: allocation-free, graph-capture safe)
__device__ __half g_QK [(size_t)NTOK * 2048];  // [token][Qall(scaled)|Kall]
__device__ __half g_VT [(size_t)EDIM * NTOK];  // [h*64+d][token] (V transposed)
__device__ __half g_ATT[(size_t)NTOK * EDIM];  // attention out
__device__ __half g_X  [(size_t)NTOK * EDIM];  // x in half
__device__ __half g_W1T[(size_t)H3   * EDIM];  // W1^T, rows permuted [Q|K|V]
__device__ __half g_W2T[(size_t)EDIM * EDIM];  // W2^T

__device__ __forceinline__ void mma_f16(float d[4],
                                        uint32_t a0, uint32_t a1, uint32_t a2, uint32_t a3,
                                        uint32_t b0, uint32_t b1) {
    asm volatile(
        "mma.sync.aligned.m16n8k16.row.col.f32.f16.f16.f32 "
        "{%0,%1,%2,%3}, {%4,%5,%6,%7}, {%8,%9}, {%0,%1,%2,%3};"
        : "+f"(d[0]), "+f"(d[1]), "+f"(d[2]), "+f"(d[3])
        : "r"(a0), "r"(a1), "r"(a2), "r"(a3), "r"(b0), "r"(b1));
}
__device__ __forceinline__ uint32_t smaddr(const void* p) {
    return (uint32_t)__cvta_generic_to_shared(p);
}
__device__ __forceinline__ void ldsm_x4(uint32_t r[4], uint32_t addr) {
    asm volatile("ldmatrix.sync.aligned.m8n8.x4.shared.b16 {%0,%1,%2,%3}, [%4];"
                 : "=r"(r[0]), "=r"(r[1]), "=r"(r[2]), "=r"(r[3]) : "r"(addr));
}
__device__ __forceinline__ void cp16(uint32_t dst, const void* src) {
    asm volatile("cp.async.cg.shared.global [%0], [%1], 16;\n" :: "r"(dst), "l"(src));
}
#define CP_COMMIT()  asm volatile("cp.async.commit_group;\n" ::: "memory")
#define CP_WAIT(n)   asm volatile("cp.async.wait_group %0;\n" :: "n"(n) : "memory")

__device__ __forceinline__ float ex2(float x) {
    float y;
    asm("ex2.approx.ftz.f32 %0, %1;" : "=f"(y) : "f"(x));
    return y;
}
// packed: returns half2 { lo = 2^lo_in, hi = 2^hi_in }
__device__ __forceinline__ uint32_t ex2_h2(float lo, float hi) {
    uint32_t c, r;
    asm("cvt.rn.f16x2.f32 %0, %1, %2;" : "=r"(c) : "f"(hi), "f"(lo));
    asm("ex2.approx.f16x2 %0, %1;" : "=r"(r) : "r"(c));
    return r;
}
__device__ __forceinline__ uint32_t h2u(__half2 h) {
    union { __half2 h; uint32_t u; } c; c.h = h; return c.u;
}

// ---------------------------------------------------------------------------
// Pre-pass kernels
// ---------------------------------------------------------------------------
__global__ void cvt_half_k(const float4* __restrict__ in, uint2* __restrict__ out, int n4) {
    int i = blockIdx.x * blockDim.x + threadIdx.x;
    if (i < n4) {
        float4 v = in[i];
        uint2 o;
        o.x = h2u(__floats2half2_rn(v.x, v.y));
        o.y = h2u(__floats2half2_rn(v.z, v.w));
        out[i] = o;
    }
}

// W [K][NC] fp32 -> WT [NC][K] half. PERM: rows h*192+p*64+d -> p*1024+h*64+d
template<bool PERM>
__global__ void trans_half(const float* __restrict__ W, __half* __restrict__ WT,
                           int K, int NC)
{
    __shared__ float t[32][33];
    int c0 = blockIdx.x * 32, k0 = blockIdx.y * 32;
    #pragma unroll
    for (int i = 0; i < 32; i += 8)
        t[threadIdx.y + i][threadIdx.x] =
            W[(size_t)(k0 + threadIdx.y + i) * NC + c0 + threadIdx.x];
    __syncthreads();
    int cbase = PERM ? ((c0 % 192) / 64) * 1024 + (c0 / 192) * 64 + (c0 % 64) : c0;
    #pragma unroll
    for (int i = 0; i < 32; i += 8) {
        int j = threadIdx.y + i;
        WT[(size_t)(cbase + j) * K + k0 + threadIdx.x] = __float2half_rn(t[threadIdx.x][j]);
    }
}

// ---------------------------------------------------------------------------
// FP16 GEMM: C = A @ Bt^T + bias. A [M][K], Bt [N][K] half, row-major.
// 128x128x32 CTA tile, 128 thr (4 warps, 64x64 warp tile), 3-stage cp.async.
// MODE 0: fp32 C, direct bias.
// MODE 1: half C; bias read with inverse QKV permutation; Q cols (<1024)
//         scaled by QSCALE; cols >= nsplit stored transposed to Cvt (half).
// ---------------------------------------------------------------------------
template<int MODE>
__global__ __launch_bounds__(128, 2)
void gemm_f16(const __half* __restrict__ A, const __half* __restrict__ Bt,
              const float* __restrict__ bias, void* __restrict__ Cout,
              __half* __restrict__ Cvt, int nsplit,
              int M, int Nstride, int K)
{
    extern __shared__ __half sh[];
    __half (*As)[128][40] = (__half (*)[128][40])sh;                 // 3 stages
    __half (*Bs)[128][40] = (__half (*)[128][40])(sh + 3 * 128 * 40);

    const int tid  = threadIdx.x;
    const int bm   = blockIdx.y, bn = blockIdx.x;
    const int warp = tid >> 5, lane = tid & 31;
    const int wm   = (warp >> 1) * 64;
    const int wn   = (warp & 1) * 64;
    const int lr   = lane >> 2, lc = lane & 3;

    const int arow = wm + ((lane >> 3) & 1) * 8 + (lane & 7);   // + mt*16
    const int ach  = ((lane >> 4) & 1) * 8;                     // + kt*16
    const int brow = wn + ((lane >> 4) & 1) * 8 + (lane & 7);   // + ntp*16
    const int bch  = ((lane >> 3) & 1) * 8;                     // + kt*16

    const int ntiles = K >> 5;

    float d[4][8][4];
    #pragma unroll
    for (int mt = 0; mt < 4; mt++)
        #pragma unroll
        for (int nt = 0; nt < 8; nt++)
            #pragma unroll
            for (int r = 0; r < 4; r++) d[mt][nt][r] = 0.f;

    auto prefetch = [&](int t, int buf) {
        int k0 = t << 5;
        #pragma unroll
        for (int i = 0; i < 4; i++) {
            int idx = i * 128 + tid;
            int r = idx >> 2, c = idx & 3;
            cp16(smaddr(&As[buf][r][c * 8]), A  + (size_t)(bm * 128 + r) * K + k0 + c * 8);
        }
        #pragma unroll
        for (int i = 0; i < 4; i++) {
            int idx = i * 128 + tid;
            int r = idx >> 2, c = idx & 3;
            cp16(smaddr(&Bs[buf][r][c * 8]), Bt + (size_t)(bn * 128 + r) * K + k0 + c * 8);
        }
        CP_COMMIT();
    };

    prefetch(0, 0);
    prefetch(1, 1);

    for (int t = 0; t < ntiles; t++) {
        int cur = t % 3;
        if (t + 1 < ntiles) { CP_WAIT(1); } else { CP_WAIT(0); }
        __syncthreads();
        if (t + 2 < ntiles) prefetch(t + 2, (t + 2) % 3);

        #pragma unroll
        for (int kt = 0; kt < 2; kt++) {
            uint32_t a[4][4], b[8][2];
            #pragma unroll
            for (int mt = 0; mt < 4; mt++)
                ldsm_x4(a[mt], smaddr(&As[cur][arow + mt * 16][kt * 16 + ach]));
            #pragma unroll
            for (int ntp = 0; ntp < 4; ntp++) {
                uint32_t t4[4];
                ldsm_x4(t4, smaddr(&Bs[cur][brow + ntp * 16][kt * 16 + bch]));
                b[2 * ntp][0] = t4[0]; b[2 * ntp][1] = t4[1];
                b[2 * ntp + 1][0] = t4[2]; b[2 * ntp + 1][1] = t4[3];
            }
            #pragma unroll
            for (int mt = 0; mt < 4; mt++)
                #pragma unroll
                for (int nt = 0; nt < 8; nt++)
                    mma_f16(d[mt][nt], a[mt][0], a[mt][1], a[mt][2], a[mt][3],
                            b[nt][0], b[nt][1]);
        }
    }

    #pragma unroll
    for (int mt = 0; mt < 4; mt++) {
        #pragma unroll
        for (int nt = 0; nt < 8; nt++) {
            int row  = bm * 128 + wm + mt * 16 + lr;
            int colg = bn * 128 + wn + nt * 8 + 2 * lc;
            float2 bv;
            if (MODE == 1) {   // inverse QKV permutation of bias index
                int map = ((colg & 1023) >> 6) * 192 + (colg >> 10) * 64 + (colg & 63);
                bv = *(const float2*)(bias + map);
            } else {
                bv = *(const float2*)(bias + colg);
            }
            float e0 = d[mt][nt][0] + bv.x, e1 = d[mt][nt][1] + bv.y;
            float e2 = d[mt][nt][2] + bv.x, e3 = d[mt][nt][3] + bv.y;
            if (MODE == 0) {
                float* C = (float*)Cout;
                *(float2*)(C + (size_t)row * Nstride + colg)       = make_float2(e0, e1);
                *(float2*)(C + (size_t)(row + 8) * Nstride + colg) = make_float2(e2, e3);
            } else {
                if (colg >= nsplit) {   // V third -> transposed half
                    __half* p0 = Cvt + (size_t)(colg - nsplit) * M;
                    __half* p1 = p0 + M;
                    p0[row]     = __float2half_rn(e0);
                    p1[row]     = __float2half_rn(e1);
                    p0[row + 8] = __float2half_rn(e2);
                    p1[row + 8] = __float2half_rn(e3);
                } else {
                    float s = (colg < 1024) ? QSCALE : 1.0f;   // pre-scale Q (log2 domain)
                    __half* C = (__half*)Cout;
                    *(__half2*)(C + (size_t)row * Nstride + colg) =
                        __floats2half2_rn(e0 * s, e1 * s);
                    *(__half2*)(C + (size_t)(row + 8) * Nstride + colg) =
                        __floats2half2_rn(e2 * s, e3 * s);
                }
            }
        }
    }
}

// ---------------------------------------------------------------------------
// Flash attention, fp16 mma + ldmatrix, 3-stage cp.async, 1 sync/tile.
// CTA: 128 q-rows, 4 warps (32 q-rows/warp = 2 m-tiles). Scores log2-domain.
// l via ones-row mma. P register-resident (C-frag == A-frag identity).
// grid=(SEQ/128, NH, NB), block=128.
// smem: Qs[128][72] | Ks[3][64][72] | Vst[3][80][72]  = 80640 B
// ---------------------------------------------------------------------------
__global__ __launch_bounds__(128, 2)
void attn_f16(const __half* __restrict__ Qk, const __half* __restrict__ Vt,
              __half* __restrict__ Out)
{
    extern __shared__ __half smp[];
    __half* Qs = smp;                                        // [128][72]
    __half (*Ks )[64][72] = (__half (*)[64][72])(smp + 128 * 72);
    __half (*Vst)[80][72] = (__half (*)[80][72])(smp + 128 * 72 + 3 * 64 * 72);

    const int qb = blockIdx.x, h = blockIdx.y, n = blockIdx.z;
    const int tid = threadIdx.x, warp = tid >> 5, lane = tid & 31;
    const int lr = lane >> 2, lc = lane & 3;

    const __half* Qbase = Qk + (size_t)(n * SEQ) * 2048 + h * 64;
    const __half* Kbase = Qbase + 1024;
    const __half* Vbase = Vt + (size_t)(h * 64) * NTOK + n * SEQ;

    const int ar  = warp * 32 + ((lane >> 3) & 1) * 8 + (lane & 7);  // + mi*16
    const int ach = ((lane >> 4) & 1) * 8;
    const int br  = ((lane >> 4) & 1) * 8 + (lane & 7);              // + ntp*16
    const int bch = ((lane >> 3) & 1) * 8;

    auto prefetch_kv = [&](int t, int buf) {
        #pragma unroll
        for (int i = 0; i < 4; i++) {
            int idx = i * 128 + tid;
            int r = idx >> 3, c = idx & 7;
            cp16(smaddr(&Ks[buf][r][c * 8]),
                 Kbase + (size_t)(t * 64 + r) * 2048 + c * 8);
            cp16(smaddr(&Vst[buf][r][c * 8]),
                 Vbase + (size_t)r * NTOK + t * 64 + c * 8);
        }
        CP_COMMIT();
    };

    // stage Q (128 rows) then kv0 in the same commit group; kv1 separate
    #pragma unroll
    for (int i = 0; i < 8; i++) {
        int idx = i * 128 + tid;
        int r = idx >> 3, c = idx & 7;
        cp16(smaddr(&Qs[r * 72 + c * 8]),
             Qbase + (size_t)(qb * 128 + r) * 2048 + c * 8);
    }
    prefetch_kv(0, 0);
    prefetch_kv(1, 1);

    // static ones rows: Vst rows 64..79 (row 64 = 1), all 3 buffers
    for (int i = tid; i < 3 * 16 * 72; i += 128) {
        int buf = i / (16 * 72);
        int rem = i - buf * (16 * 72);
        int r = rem / 72, c = rem - r * 72;
        Vst[buf][64 + r][c] = __float2half((r == 0) ? 1.f : 0.f);
    }

    CP_WAIT(1);            // Q + kv0 ready
    __syncthreads();

    uint32_t aq[4][2][4];  // [kt][mi]
    #pragma unroll
    for (int kt = 0; kt < 4; kt++)
        #pragma unroll
        for (int mi = 0; mi < 2; mi++)
            ldsm_x4(aq[kt][mi], smaddr(&Qs[(ar + mi * 16) * 72 + kt * 16 + ach]));

    float o[2][9][4];
    #pragma unroll
    for (int mi = 0; mi < 2; mi++)
        #pragma unroll
        for (int nt = 0; nt < 9; nt++)
            #pragma unroll
            for (int r = 0; r < 4; r++) o[mi][nt][r] = 0.f;
    float mm[2][2] = {{-1e30f, -1e30f}, {-1e30f, -1e30f}};

    const int NT = SEQ / 64;
    for (int t = 0; t < NT; t++) {
        int cur = t % 3;
        if (t > 0) {
            if (t + 1 < NT) { CP_WAIT(1); } else { CP_WAIT(0); }
            __syncthreads();
        }
        if (t + 2 < NT) prefetch_kv(t + 2, (t + 2) % 3);

        // S = Q @ K^T  (log2 domain), both m-tiles share K fragments
        float s[2][8][4];
        #pragma unroll
        for (int mi = 0; mi < 2; mi++)
            #pragma unroll
            for (int nt = 0; nt < 8; nt++)
                #pragma unroll
                for (int r = 0; r < 4; r++) s[mi][nt][r] = 0.f;
        #pragma unroll
        for (int kt = 0; kt < 4; kt++) {
            uint32_t bb[8][2];
            #pragma unroll
            for (int ntp = 0; ntp < 4; ntp++) {
                uint32_t t4[4];
                ldsm_x4(t4, smaddr(&Ks[cur][br + ntp * 16][kt * 16 + bch]));
                bb[2 * ntp][0] = t4[0]; bb[2 * ntp][1] = t4[1];
                bb[2 * ntp + 1][0] = t4[2]; bb[2 * ntp + 1][1] = t4[3];
            }
            #pragma unroll
            for (int mi = 0; mi < 2; mi++)
                #pragma unroll
                for (int nt = 0; nt < 8; nt++)
                    mma_f16(s[mi][nt], aq[kt][mi][0], aq[kt][mi][1],
                            aq[kt][mi][2], aq[kt][mi][3], bb[nt][0], bb[nt][1]);
        }

        // online softmax (fp32 stats; exp2) per m-tile
        float al[2][2];
        #pragma unroll
        for (int mi = 0; mi < 2; mi++) {
            float mx0 = s[mi][0][0], mx1 = s[mi][0][2];
            #pragma unroll
            for (int nt = 0; nt < 8; nt++) {
                mx0 = fmaxf(mx0, fmaxf(s[mi][nt][0], s[mi][nt][1]));
                mx1 = fmaxf(mx1, fmaxf(s[mi][nt][2], s[mi][nt][3]));
            }
            mx0 = fmaxf(mx0, __shfl_xor_sync(0xffffffffu, mx0, 1));
            mx0 = fmaxf(mx0, __shfl_xor_sync(0xffffffffu, mx0, 2));
            mx1 = fmaxf(mx1, __shfl_xor_sync(0xffffffffu, mx1, 1));
            mx1 = fmaxf(mx1, __shfl_xor_sync(0xffffffffu, mx1, 2));
            float nm0 = fmaxf(mm[mi][0], mx0), nm1 = fmaxf(mm[mi][1], mx1);
            al[mi][0] = ex2(mm[mi][0] - nm0);
            al[mi][1] = ex2(mm[mi][1] - nm1);
            mm[mi][0] = nm0; mm[mi][1] = nm1;
        }
        if (!__all_sync(0xffffffffu,
                        (al[0][0] == 1.f) && (al[0][1] == 1.f) &&
                        (al[1][0] == 1.f) && (al[1][1] == 1.f))) {
            #pragma unroll
            for (int mi = 0; mi < 2; mi++)
                #pragma unroll
                for (int nt = 0; nt < 9; nt++) {
                    o[mi][nt][0] *= al[mi][0]; o[mi][nt][1] *= al[mi][0];
                    o[mi][nt][2] *= al[mi][1]; o[mi][nt][3] *= al[mi][1];
                }
        }

        // P = 2^(s-m), packed f16x2, register-resident
        uint32_t p01[2][8], p23[2][8];
        #pragma unroll
        for (int mi = 0; mi < 2; mi++)
            #pragma unroll
            for (int nt = 0; nt < 8; nt++) {
                p01[mi][nt] = ex2_h2(s[mi][nt][0] - mm[mi][0], s[mi][nt][1] - mm[mi][0]);
                p23[mi][nt] = ex2_h2(s[mi][nt][2] - mm[mi][1], s[mi][nt][3] - mm[mi][1]);
            }

        // O += P @ [V ; ones-row]   (nt=8 accumulates l); V frags shared
        #pragma unroll
        for (int kt = 0; kt < 4; kt++) {
            uint32_t bb[10][2];
            #pragma unroll
            for (int ntp = 0; ntp < 5; ntp++) {
                uint32_t t4[4];
                ldsm_x4(t4, smaddr(&Vst[cur][br + ntp * 16][kt * 16 + bch]));
                bb[2 * ntp][0] = t4[0]; bb[2 * ntp][1] = t4[1];
                bb[2 * ntp + 1][0] = t4[2]; bb[2 * ntp + 1][1] = t4[3];
            }
            #pragma unroll
            for (int mi = 0; mi < 2; mi++) {
                uint32_t a0 = p01[mi][2 * kt],     a1 = p23[mi][2 * kt];
                uint32_t a2 = p01[mi][2 * kt + 1], a3 = p23[mi][2 * kt + 1];
                #pragma unroll
                for (int nt = 0; nt < 9; nt++)
                    mma_f16(o[mi][nt], a0, a1, a2, a3, bb[nt][0], bb[nt][1]);
            }
        }
    }

    // epilogue: l in o[mi][8][0]/[2] of lc==0 lanes
    #pragma unroll
    for (int mi = 0; mi < 2; mi++) {
        float l0 = __shfl_sync(0xffffffffu, o[mi][8][0], lane & 28);
        float l1 = __shfl_sync(0xffffffffu, o[mi][8][2], lane & 28);
        float inv0 = 1.f / l0, inv1 = 1.f / l1;
        int row0 = qb * 128 + warp * 32 + mi * 16 + lr;
        __half* op0 = Out + (size_t)(n * SEQ + row0) * EDIM + h * 64;
        __half* op1 = op0 + (size_t)8 * EDIM;
        #pragma unroll
        for (int nt = 0; nt < 8; nt++) {
            int col = nt * 8 + 2 * lc;
            *(__half2*)(op0 + col) = __floats2half2_rn(o[mi][nt][0] * inv0,
                                                       o[mi][nt][1] * inv0);
            *(__half2*)(op1 + col) = __floats2half2_rn(o[mi][nt][2] * inv1,
                                                       o[mi][nt][3] * inv1);
        }
    }
}

// ---------------------------------------------------------------------------
extern "C" void kernel_launch(void* const* d_in, const int* in_sizes, int n_in,
                              void* d_out, int out_size)
{
    const float* x  = (const float*)d_in[0];
    const float* W1 = (const float*)d_in[1];
    const float* b1 = (const float*)d_in[2];
    const float* W2 = (const float*)d_in[3];
    const float* b2 = (const float*)d_in[4];
    float* out = (float*)d_out;

    __half *QKbuf, *VTbuf, *Abuf, *Xbuf, *W1Tbuf, *W2Tbuf;
    cudaGetSymbolAddress((void**)&QKbuf,  g_QK);
    cudaGetSymbolAddress((void**)&VTbuf,  g_VT);
    cudaGetSymbolAddress((void**)&Abuf,   g_ATT);
    cudaGetSymbolAddress((void**)&Xbuf,   g_X);
    cudaGetSymbolAddress((void**)&W1Tbuf, g_W1T);
    cudaGetSymbolAddress((void**)&W2Tbuf, g_W2T);

    const int gemm_smem = 3 * 2 * 128 * 40 * 2;                       // 61440 B
    const int attn_smem = (128 * 72 + 3 * 64 * 72 + 3 * 80 * 72) * 2; // 80640 B
    static bool attr_done = false;
    if (!attr_done) {
        cudaFuncSetAttribute(gemm_f16<0>,
                             cudaFuncAttributeMaxDynamicSharedMemorySize, gemm_smem);
        cudaFuncSetAttribute(gemm_f16<1>,
                             cudaFuncAttributeMaxDynamicSharedMemorySize, gemm_smem);
        cudaFuncSetAttribute(attn_f16,
                             cudaFuncAttributeMaxDynamicSharedMemorySize, attn_smem);
        attr_done = true;
    }

    // pre-pass: x -> half; W1 -> permuted transposed half; W2 -> transposed half
    cvt_half_k<<<(NTOK * EDIM / 4 + 255) / 256, 256>>>((const float4*)x,
                                                       (uint2*)Xbuf, NTOK * EDIM / 4);
    trans_half<true ><<<dim3(H3 / 32, EDIM / 32), dim3(32, 8)>>>(W1, W1Tbuf, EDIM, H3);
    trans_half<false><<<dim3(EDIM / 32, EDIM / 32), dim3(32, 8)>>>(W2, W2Tbuf, EDIM, EDIM);

    // 1) QKV projection: Q(scaled)/K -> g_QK, V -> g_VT transposed
    gemm_f16<1><<<dim3(H3 / 128, NTOK / 128), 128, gemm_smem>>>(
        Xbuf, W1Tbuf, b1, QKbuf, VTbuf, 2048, NTOK, 2048, EDIM);
    // 2) attention -> g_ATT (half)
    attn_f16<<<dim3(SEQ / 128, NH, NB), 128, attn_smem>>>(QKbuf, VTbuf, Abuf);
    // 3) output projection -> fp32 out
    gemm_f16<0><<<dim3(EDIM / 128, NTOK / 128), 128, gemm_smem>>>(
        Abuf, W2Tbuf, b2, out, nullptr, 1 << 30, NTOK, EDIM, EDIM);
}

// round 10
// speedup vs baseline: 9.1589x; 1.0241x over previous
#include <cuda_runtime.h>
#include <cuda_fp16.h>
#include <cstdint>

#define NB   4
#define SEQ  2048
#define EDIM 1024
#define H3   3072
#define NH   16
#define NTOK (NB*SEQ)

// Q pre-scale: (1/sqrt(64)) * log2(e)  -> scores land in log2 domain
#define QSCALE 0.180336880111120432f

// Scratch (device globals: allocation-free, graph-capture safe)
__device__ __half g_QK [(size_t)NTOK * 2048];  // [token][Qall(scaled)|Kall]
__device__ __half g_VT [(size_t)EDIM * NTOK];  // [h*64+d][token] (V transposed)
__device__ __half g_ATT[(size_t)NTOK * EDIM];  // attention out
__device__ __half g_X  [(size_t)NTOK * EDIM];  // x in half
__device__ __half g_W1T[(size_t)H3   * EDIM];  // W1^T, rows permuted [Q|K|V]
__device__ __half g_W2T[(size_t)EDIM * EDIM];  // W2^T

__device__ __forceinline__ void mma_f16(float d[4],
                                        uint32_t a0, uint32_t a1, uint32_t a2, uint32_t a3,
                                        uint32_t b0, uint32_t b1) {
    asm volatile(
        "mma.sync.aligned.m16n8k16.row.col.f32.f16.f16.f32 "
        "{%0,%1,%2,%3}, {%4,%5,%6,%7}, {%8,%9}, {%0,%1,%2,%3};"
        : "+f"(d[0]), "+f"(d[1]), "+f"(d[2]), "+f"(d[3])
        : "r"(a0), "r"(a1), "r"(a2), "r"(a3), "r"(b0), "r"(b1));
}
__device__ __forceinline__ uint32_t smaddr(const void* p) {
    return (uint32_t)__cvta_generic_to_shared(p);
}
__device__ __forceinline__ void ldsm_x4(uint32_t r[4], uint32_t addr) {
    asm volatile("ldmatrix.sync.aligned.m8n8.x4.shared.b16 {%0,%1,%2,%3}, [%4];"
                 : "=r"(r[0]), "=r"(r[1]), "=r"(r[2]), "=r"(r[3]) : "r"(addr));
}
__device__ __forceinline__ void cp16(uint32_t dst, const void* src) {
    asm volatile("cp.async.cg.shared.global [%0], [%1], 16;\n" :: "r"(dst), "l"(src));
}
#define CP_COMMIT()  asm volatile("cp.async.commit_group;\n" ::: "memory")
#define CP_WAIT(n)   asm volatile("cp.async.wait_group %0;\n" :: "n"(n) : "memory")

__device__ __forceinline__ float ex2(float x) {
    float y;
    asm("ex2.approx.ftz.f32 %0, %1;" : "=f"(y) : "f"(x));
    return y;
}
// packed: returns half2 { lo = 2^lo_in, hi = 2^hi_in }
__device__ __forceinline__ uint32_t ex2_h2(float lo, float hi) {
    uint32_t c, r;
    asm("cvt.rn.f16x2.f32 %0, %1, %2;" : "=r"(c) : "f"(hi), "f"(lo));
    asm("ex2.approx.f16x2 %0, %1;" : "=r"(r) : "r"(c));
    return r;
}
__device__ __forceinline__ uint32_t h2u(__half2 h) {
    union { __half2 h; uint32_t u; } c; c.h = h; return c.u;
}

// ---------------------------------------------------------------------------
// Pre-pass kernels
// ---------------------------------------------------------------------------
__global__ void cvt_half_k(const float4* __restrict__ in, uint2* __restrict__ out, int n4) {
    int i = blockIdx.x * blockDim.x + threadIdx.x;
    if (i < n4) {
        float4 v = in[i];
        uint2 o;
        o.x = h2u(__floats2half2_rn(v.x, v.y));
        o.y = h2u(__floats2half2_rn(v.z, v.w));
        out[i] = o;
    }
}

// W [K][NC] fp32 -> WT [NC][K] half. PERM: rows h*192+p*64+d -> p*1024+h*64+d
template<bool PERM>
__global__ void trans_half(const float* __restrict__ W, __half* __restrict__ WT,
                           int K, int NC)
{
    __shared__ float t[32][33];
    int c0 = blockIdx.x * 32, k0 = blockIdx.y * 32;
    #pragma unroll
    for (int i = 0; i < 32; i += 8)
        t[threadIdx.y + i][threadIdx.x] =
            W[(size_t)(k0 + threadIdx.y + i) * NC + c0 + threadIdx.x];
    __syncthreads();
    int cbase = PERM ? ((c0 % 192) / 64) * 1024 + (c0 / 192) * 64 + (c0 % 64) : c0;
    #pragma unroll
    for (int i = 0; i < 32; i += 8) {
        int j = threadIdx.y + i;
        WT[(size_t)(cbase + j) * K + k0 + threadIdx.x] = __float2half_rn(t[threadIdx.x][j]);
    }
}

// ---------------------------------------------------------------------------
// FP16 GEMM: C = A @ Bt^T + bias. A [M][K], Bt [N][K] half, row-major.
// 128x128x64 CTA tile, 128 thr (4 warps, 64x64 warp tile), 3-stage cp.async,
// software-pipelined (double-buffered) ldmatrix fragments.
// MODE 0: fp32 C, direct bias.
// MODE 1: half C; bias read with inverse QKV permutation; Q cols (<1024)
//         scaled by QSCALE; cols >= nsplit stored transposed to Cvt (half).
// ---------------------------------------------------------------------------
template<int MODE>
__global__ __launch_bounds__(128, 2)
void gemm_f16(const __half* __restrict__ A, const __half* __restrict__ Bt,
              const float* __restrict__ bias, void* __restrict__ Cout,
              __half* __restrict__ Cvt, int nsplit,
              int M, int Nstride, int K)
{
    extern __shared__ __half sh[];
    __half (*As)[128][72] = (__half (*)[128][72])sh;                 // 3 stages
    __half (*Bs)[128][72] = (__half (*)[128][72])(sh + 3 * 128 * 72);

    const int tid  = threadIdx.x;
    const int bm   = blockIdx.y, bn = blockIdx.x;
    const int warp = tid >> 5, lane = tid & 31;
    const int wm   = (warp >> 1) * 64;
    const int wn   = (warp & 1) * 64;
    const int lr   = lane >> 2, lc = lane & 3;

    const int arow = wm + ((lane >> 3) & 1) * 8 + (lane & 7);   // + mt*16
    const int ach  = ((lane >> 4) & 1) * 8;                     // + kt*16
    const int brow = wn + ((lane >> 4) & 1) * 8 + (lane & 7);   // + ntp*16
    const int bch  = ((lane >> 3) & 1) * 8;                     // + kt*16

    const int ntiles = K >> 6;

    float d[4][8][4];
    #pragma unroll
    for (int mt = 0; mt < 4; mt++)
        #pragma unroll
        for (int nt = 0; nt < 8; nt++)
            #pragma unroll
            for (int r = 0; r < 4; r++) d[mt][nt][r] = 0.f;

    auto prefetch = [&](int t, int buf) {
        int k0 = t << 6;
        #pragma unroll
        for (int i = 0; i < 8; i++) {
            int idx = i * 128 + tid;
            int r = idx >> 3, c = idx & 7;
            cp16(smaddr(&As[buf][r][c * 8]), A  + (size_t)(bm * 128 + r) * K + k0 + c * 8);
        }
        #pragma unroll
        for (int i = 0; i < 8; i++) {
            int idx = i * 128 + tid;
            int r = idx >> 3, c = idx & 7;
            cp16(smaddr(&Bs[buf][r][c * 8]), Bt + (size_t)(bn * 128 + r) * K + k0 + c * 8);
        }
        CP_COMMIT();
    };

    auto load_frags = [&](int cur, int kt, uint32_t (&a)[4][4], uint32_t (&b)[8][2]) {
        #pragma unroll
        for (int mt = 0; mt < 4; mt++)
            ldsm_x4(a[mt], smaddr(&As[cur][arow + mt * 16][kt * 16 + ach]));
        #pragma unroll
        for (int ntp = 0; ntp < 4; ntp++) {
            uint32_t t4[4];
            ldsm_x4(t4, smaddr(&Bs[cur][brow + ntp * 16][kt * 16 + bch]));
            b[2 * ntp][0] = t4[0]; b[2 * ntp][1] = t4[1];
            b[2 * ntp + 1][0] = t4[2]; b[2 * ntp + 1][1] = t4[3];
        }
    };

    prefetch(0, 0);
    prefetch(1, 1);

    for (int t = 0; t < ntiles; t++) {
        int cur = t % 3;
        if (t + 1 < ntiles) { CP_WAIT(1); } else { CP_WAIT(0); }
        __syncthreads();
        if (t + 2 < ntiles) prefetch(t + 2, (t + 2) % 3);

        uint32_t a[2][4][4], b[2][8][2];
        load_frags(cur, 0, a[0], b[0]);
        #pragma unroll
        for (int kt = 0; kt < 4; kt++) {
            int cf = kt & 1;
            if (kt < 3) load_frags(cur, kt + 1, a[cf ^ 1], b[cf ^ 1]);
            #pragma unroll
            for (int mt = 0; mt < 4; mt++)
                #pragma unroll
                for (int nt = 0; nt < 8; nt++)
                    mma_f16(d[mt][nt], a[cf][mt][0], a[cf][mt][1],
                            a[cf][mt][2], a[cf][mt][3], b[cf][nt][0], b[cf][nt][1]);
        }
    }

    #pragma unroll
    for (int mt = 0; mt < 4; mt++) {
        #pragma unroll
        for (int nt = 0; nt < 8; nt++) {
            int row  = bm * 128 + wm + mt * 16 + lr;
            int colg = bn * 128 + wn + nt * 8 + 2 * lc;
            float2 bv;
            if (MODE == 1) {   // inverse QKV permutation of bias index
                int map = ((colg & 1023) >> 6) * 192 + (colg >> 10) * 64 + (colg & 63);
                bv = *(const float2*)(bias + map);
            } else {
                bv = *(const float2*)(bias + colg);
            }
            float e0 = d[mt][nt][0] + bv.x, e1 = d[mt][nt][1] + bv.y;
            float e2 = d[mt][nt][2] + bv.x, e3 = d[mt][nt][3] + bv.y;
            if (MODE == 0) {
                float* C = (float*)Cout;
                *(float2*)(C + (size_t)row * Nstride + colg)       = make_float2(e0, e1);
                *(float2*)(C + (size_t)(row + 8) * Nstride + colg) = make_float2(e2, e3);
            } else {
                if (colg >= nsplit) {   // V third -> transposed half
                    __half* p0 = Cvt + (size_t)(colg - nsplit) * M;
                    __half* p1 = p0 + M;
                    p0[row]     = __float2half_rn(e0);
                    p1[row]     = __float2half_rn(e1);
                    p0[row + 8] = __float2half_rn(e2);
                    p1[row + 8] = __float2half_rn(e3);
                } else {
                    float s = (colg < 1024) ? QSCALE : 1.0f;   // pre-scale Q (log2 domain)
                    __half* C = (__half*)Cout;
                    *(__half2*)(C + (size_t)row * Nstride + colg) =
                        __floats2half2_rn(e0 * s, e1 * s);
                    *(__half2*)(C + (size_t)(row + 8) * Nstride + colg) =
                        __floats2half2_rn(e2 * s, e3 * s);
                }
            }
        }
    }
}

// ---------------------------------------------------------------------------
// Flash attention, fp16 mma + ldmatrix, 3-stage cp.async, 1 sync/tile.
// CTA: 128 q-rows, 4 warps (32 q-rows/warp). Scores log2-domain. l via
// ones-row mma. P register-resident. PV V-fragments double-buffered.
// grid=(SEQ/128, NH, NB), block=128.
// smem: Qs[128][72] | Ks[3][64][72] | Vst[3][80][72]  = 80640 B
// ---------------------------------------------------------------------------
__global__ __launch_bounds__(128, 2)
void attn_f16(const __half* __restrict__ Qk, const __half* __restrict__ Vt,
              __half* __restrict__ Out)
{
    extern __shared__ __half smp[];
    __half* Qs = smp;                                        // [128][72]
    __half (*Ks )[64][72] = (__half (*)[64][72])(smp + 128 * 72);
    __half (*Vst)[80][72] = (__half (*)[80][72])(smp + 128 * 72 + 3 * 64 * 72);

    const int qb = blockIdx.x, h = blockIdx.y, n = blockIdx.z;
    const int tid = threadIdx.x, warp = tid >> 5, lane = tid & 31;
    const int lr = lane >> 2, lc = lane & 3;

    const __half* Qbase = Qk + (size_t)(n * SEQ) * 2048 + h * 64;
    const __half* Kbase = Qbase + 1024;
    const __half* Vbase = Vt + (size_t)(h * 64) * NTOK + n * SEQ;

    const int ar  = warp * 32 + ((lane >> 3) & 1) * 8 + (lane & 7);  // + mi*16
    const int ach = ((lane >> 4) & 1) * 8;
    const int br  = ((lane >> 4) & 1) * 8 + (lane & 7);              // + ntp*16
    const int bch = ((lane >> 3) & 1) * 8;

    auto prefetch_kv = [&](int t, int buf) {
        #pragma unroll
        for (int i = 0; i < 4; i++) {
            int idx = i * 128 + tid;
            int r = idx >> 3, c = idx & 7;
            cp16(smaddr(&Ks[buf][r][c * 8]),
                 Kbase + (size_t)(t * 64 + r) * 2048 + c * 8);
            cp16(smaddr(&Vst[buf][r][c * 8]),
                 Vbase + (size_t)r * NTOK + t * 64 + c * 8);
        }
        CP_COMMIT();
    };

    auto load_vfrags = [&](int cur, int kt, uint32_t (&bb)[10][2]) {
        #pragma unroll
        for (int ntp = 0; ntp < 5; ntp++) {
            uint32_t t4[4];
            ldsm_x4(t4, smaddr(&Vst[cur][br + ntp * 16][kt * 16 + bch]));
            bb[2 * ntp][0] = t4[0]; bb[2 * ntp][1] = t4[1];
            bb[2 * ntp + 1][0] = t4[2]; bb[2 * ntp + 1][1] = t4[3];
        }
    };

    // stage Q (128 rows) then kv0 in the same commit group; kv1 separate
    #pragma unroll
    for (int i = 0; i < 8; i++) {
        int idx = i * 128 + tid;
        int r = idx >> 3, c = idx & 7;
        cp16(smaddr(&Qs[r * 72 + c * 8]),
             Qbase + (size_t)(qb * 128 + r) * 2048 + c * 8);
    }
    prefetch_kv(0, 0);
    prefetch_kv(1, 1);

    // static ones rows: Vst rows 64..79 (row 64 = 1), all 3 buffers
    for (int i = tid; i < 3 * 16 * 72; i += 128) {
        int buf = i / (16 * 72);
        int rem = i - buf * (16 * 72);
        int r = rem / 72, c = rem - r * 72;
        Vst[buf][64 + r][c] = __float2half((r == 0) ? 1.f : 0.f);
    }

    CP_WAIT(1);            // Q + kv0 ready
    __syncthreads();

    uint32_t aq[4][2][4];  // [kt][mi]
    #pragma unroll
    for (int kt = 0; kt < 4; kt++)
        #pragma unroll
        for (int mi = 0; mi < 2; mi++)
            ldsm_x4(aq[kt][mi], smaddr(&Qs[(ar + mi * 16) * 72 + kt * 16 + ach]));

    float o[2][9][4];
    #pragma unroll
    for (int mi = 0; mi < 2; mi++)
        #pragma unroll
        for (int nt = 0; nt < 9; nt++)
            #pragma unroll
            for (int r = 0; r < 4; r++) o[mi][nt][r] = 0.f;
    float mm[2][2] = {{-1e30f, -1e30f}, {-1e30f, -1e30f}};

    const int NT = SEQ / 64;
    for (int t = 0; t < NT; t++) {
        int cur = t % 3;
        if (t > 0) {
            if (t + 1 < NT) { CP_WAIT(1); } else { CP_WAIT(0); }
            __syncthreads();
        }
        if (t + 2 < NT) prefetch_kv(t + 2, (t + 2) % 3);

        // S = Q @ K^T  (log2 domain), both m-tiles share K fragments
        float s[2][8][4];
        #pragma unroll
        for (int mi = 0; mi < 2; mi++)
            #pragma unroll
            for (int nt = 0; nt < 8; nt++)
                #pragma unroll
                for (int r = 0; r < 4; r++) s[mi][nt][r] = 0.f;
        #pragma unroll
        for (int kt = 0; kt < 4; kt++) {
            uint32_t bb[8][2];
            #pragma unroll
            for (int ntp = 0; ntp < 4; ntp++) {
                uint32_t t4[4];
                ldsm_x4(t4, smaddr(&Ks[cur][br + ntp * 16][kt * 16 + bch]));
                bb[2 * ntp][0] = t4[0]; bb[2 * ntp][1] = t4[1];
                bb[2 * ntp + 1][0] = t4[2]; bb[2 * ntp + 1][1] = t4[3];
            }
            #pragma unroll
            for (int mi = 0; mi < 2; mi++)
                #pragma unroll
                for (int nt = 0; nt < 8; nt++)
                    mma_f16(s[mi][nt], aq[kt][mi][0], aq[kt][mi][1],
                            aq[kt][mi][2], aq[kt][mi][3], bb[nt][0], bb[nt][1]);
        }

        // online softmax (fp32 stats; exp2) per m-tile
        float al[2][2];
        #pragma unroll
        for (int mi = 0; mi < 2; mi++) {
            float mx0 = s[mi][0][0], mx1 = s[mi][0][2];
            #pragma unroll
            for (int nt = 0; nt < 8; nt++) {
                mx0 = fmaxf(mx0, fmaxf(s[mi][nt][0], s[mi][nt][1]));
                mx1 = fmaxf(mx1, fmaxf(s[mi][nt][2], s[mi][nt][3]));
            }
            mx0 = fmaxf(mx0, __shfl_xor_sync(0xffffffffu, mx0, 1));
            mx0 = fmaxf(mx0, __shfl_xor_sync(0xffffffffu, mx0, 2));
            mx1 = fmaxf(mx1, __shfl_xor_sync(0xffffffffu, mx1, 1));
            mx1 = fmaxf(mx1, __shfl_xor_sync(0xffffffffu, mx1, 2));
            float nm0 = fmaxf(mm[mi][0], mx0), nm1 = fmaxf(mm[mi][1], mx1);
            al[mi][0] = ex2(mm[mi][0] - nm0);
            al[mi][1] = ex2(mm[mi][1] - nm1);
            mm[mi][0] = nm0; mm[mi][1] = nm1;
        }
        if (!__all_sync(0xffffffffu,
                        (al[0][0] == 1.f) && (al[0][1] == 1.f) &&
                        (al[1][0] == 1.f) && (al[1][1] == 1.f))) {
            #pragma unroll
            for (int mi = 0; mi < 2; mi++)
                #pragma unroll
                for (int nt = 0; nt < 9; nt++) {
                    o[mi][nt][0] *= al[mi][0]; o[mi][nt][1] *= al[mi][0];
                    o[mi][nt][2] *= al[mi][1]; o[mi][nt][3] *= al[mi][1];
                }
        }

        // P = 2^(s-m), packed f16x2, register-resident
        uint32_t p01[2][8], p23[2][8];
        #pragma unroll
        for (int mi = 0; mi < 2; mi++)
            #pragma unroll
            for (int nt = 0; nt < 8; nt++) {
                p01[mi][nt] = ex2_h2(s[mi][nt][0] - mm[mi][0], s[mi][nt][1] - mm[mi][0]);
                p23[mi][nt] = ex2_h2(s[mi][nt][2] - mm[mi][1], s[mi][nt][3] - mm[mi][1]);
            }

        // O += P @ [V ; ones-row]  (nt=8 = l); V frags double-buffered
        uint32_t bb[2][10][2];
        load_vfrags(cur, 0, bb[0]);
        #pragma unroll
        for (int kt = 0; kt < 4; kt++) {
            int cf = kt & 1;
            if (kt < 3) load_vfrags(cur, kt + 1, bb[cf ^ 1]);
            #pragma unroll
            for (int mi = 0; mi < 2; mi++) {
                uint32_t a0 = p01[mi][2 * kt],     a1 = p23[mi][2 * kt];
                uint32_t a2 = p01[mi][2 * kt + 1], a3 = p23[mi][2 * kt + 1];
                #pragma unroll
                for (int nt = 0; nt < 9; nt++)
                    mma_f16(o[mi][nt], a0, a1, a2, a3, bb[cf][nt][0], bb[cf][nt][1]);
            }
        }
    }

    // epilogue: l in o[mi][8][0]/[2] of lc==0 lanes
    #pragma unroll
    for (int mi = 0; mi < 2; mi++) {
        float l0 = __shfl_sync(0xffffffffu, o[mi][8][0], lane & 28);
        float l1 = __shfl_sync(0xffffffffu, o[mi][8][2], lane & 28);
        float inv0 = 1.f / l0, inv1 = 1.f / l1;
        int row0 = qb * 128 + warp * 32 + mi * 16 + lr;
        __half* op0 = Out + (size_t)(n * SEQ + row0) * EDIM + h * 64;
        __half* op1 = op0 + (size_t)8 * EDIM;
        #pragma unroll
        for (int nt = 0; nt < 8; nt++) {
            int col = nt * 8 + 2 * lc;
            *(__half2*)(op0 + col) = __floats2half2_rn(o[mi][nt][0] * inv0,
                                                       o[mi][nt][1] * inv0);
            *(__half2*)(op1 + col) = __floats2half2_rn(o[mi][nt][2] * inv1,
                                                       o[mi][nt][3] * inv1);
        }
    }
}

// ---------------------------------------------------------------------------
extern "C" void kernel_launch(void* const* d_in, const int* in_sizes, int n_in,
                              void* d_out, int out_size)
{
    const float* x  = (const float*)d_in[0];
    const float* W1 = (const float*)d_in[1];
    const float* b1 = (const float*)d_in[2];
    const float* W2 = (const float*)d_in[3];
    const float* b2 = (const float*)d_in[4];
    float* out = (float*)d_out;

    __half *QKbuf, *VTbuf, *Abuf, *Xbuf, *W1Tbuf, *W2Tbuf;
    cudaGetSymbolAddress((void**)&QKbuf,  g_QK);
    cudaGetSymbolAddress((void**)&VTbuf,  g_VT);
    cudaGetSymbolAddress((void**)&Abuf,   g_ATT);
    cudaGetSymbolAddress((void**)&Xbuf,   g_X);
    cudaGetSymbolAddress((void**)&W1Tbuf, g_W1T);
    cudaGetSymbolAddress((void**)&W2Tbuf, g_W2T);

    const int gemm_smem = 3 * 2 * 128 * 72 * 2;                       // 110592 B
    const int attn_smem = (128 * 72 + 3 * 64 * 72 + 3 * 80 * 72) * 2; // 80640 B
    static bool attr_done = false;
    if (!attr_done) {
        cudaFuncSetAttribute(gemm_f16<0>,
                             cudaFuncAttributeMaxDynamicSharedMemorySize, gemm_smem);
        cudaFuncSetAttribute(gemm_f16<1>,
                             cudaFuncAttributeMaxDynamicSharedMemorySize, gemm_smem);
        cudaFuncSetAttribute(attn_f16,
                             cudaFuncAttributeMaxDynamicSharedMemorySize, attn_smem);
        attr_done = true;
    }

    // pre-pass: x -> half; W1 -> permuted transposed half; W2 -> transposed half
    cvt_half_k<<<(NTOK * EDIM / 4 + 255) / 256, 256>>>((const float4*)x,
                                                       (uint2*)Xbuf, NTOK * EDIM / 4);
    trans_half<true ><<<dim3(H3 / 32, EDIM / 32), dim3(32, 8)>>>(W1, W1Tbuf, EDIM, H3);
    trans_half<false><<<dim3(EDIM / 32, EDIM / 32), dim3(32, 8)>>>(W2, W2Tbuf, EDIM, EDIM);

    // 1) QKV projection: Q(scaled)/K -> g_QK, V -> g_VT transposed
    gemm_f16<1><<<dim3(H3 / 128, NTOK / 128), 128, gemm_smem>>>(
        Xbuf, W1Tbuf, b1, QKbuf, VTbuf, 2048, NTOK, 2048, EDIM);
    // 2) attention -> g_ATT (half)
    attn_f16<<<dim3(SEQ / 128, NH, NB), 128, attn_smem>>>(QKbuf, VTbuf, Abuf);
    // 3) output projection -> fp32 out
    gemm_f16<0><<<dim3(EDIM / 128, NTOK / 128), 128, gemm_smem>>>(
        Abuf, W2Tbuf, b2, out, nullptr, 1 << 30, NTOK, EDIM, EDIM);
}

// round 12
// speedup vs baseline: 9.3253x; 1.0182x over previous
#include <cuda_runtime.h>
#include <cuda_fp16.h>
#include <cstdint>

#define NB   4
#define SEQ  2048
#define EDIM 1024
#define H3   3072
#define NH   16
#define NTOK (NB*SEQ)

// Q pre-scale: (1/sqrt(64)) * log2(e)  -> scores land in log2 domain
#define QSCALE 0.180336880111120432f

// Scratch (device globals: allocation-free, graph-capture safe)
__device__ __half g_QK [(size_t)NTOK * 2048];  // [token][Qall(scaled)|Kall]
__device__ __half g_VT [(size_t)EDIM * NTOK];  // [h*64+d][token] (V transposed)
__device__ __half g_ATT[(size_t)NTOK * EDIM];  // attention out
__device__ __half g_X  [(size_t)NTOK * EDIM];  // x in half
__device__ __half g_W1T[(size_t)H3   * EDIM];  // W1^T, rows permuted [Q|K|V]
__device__ __half g_W2T[(size_t)EDIM * EDIM];  // W2^T

__device__ __forceinline__ void mma_f16(float d[4],
                                        uint32_t a0, uint32_t a1, uint32_t a2, uint32_t a3,
                                        uint32_t b0, uint32_t b1) {
    asm volatile(
        "mma.sync.aligned.m16n8k16.row.col.f32.f16.f16.f32 "
        "{%0,%1,%2,%3}, {%4,%5,%6,%7}, {%8,%9}, {%0,%1,%2,%3};"
        : "+f"(d[0]), "+f"(d[1]), "+f"(d[2]), "+f"(d[3])
        : "r"(a0), "r"(a1), "r"(a2), "r"(a3), "r"(b0), "r"(b1));
}
__device__ __forceinline__ uint32_t smaddr(const void* p) {
    return (uint32_t)__cvta_generic_to_shared(p);
}
__device__ __forceinline__ void ldsm_x4(uint32_t r[4], uint32_t addr) {
    asm volatile("ldmatrix.sync.aligned.m8n8.x4.shared.b16 {%0,%1,%2,%3}, [%4];"
                 : "=r"(r[0]), "=r"(r[1]), "=r"(r[2]), "=r"(r[3]) : "r"(addr));
}
__device__ __forceinline__ void cp16(uint32_t dst, const void* src) {
    asm volatile("cp.async.cg.shared.global [%0], [%1], 16;\n" :: "r"(dst), "l"(src));
}
#define CP_COMMIT()  asm volatile("cp.async.commit_group;\n" ::: "memory")
#define CP_WAIT(n)   asm volatile("cp.async.wait_group %0;\n" :: "n"(n) : "memory")

__device__ __forceinline__ float ex2(float x) {
    float y;
    asm("ex2.approx.ftz.f32 %0, %1;" : "=f"(y) : "f"(x));
    return y;
}
// packed: returns half2 { lo = 2^lo_in, hi = 2^hi_in }
__device__ __forceinline__ uint32_t ex2_h2(float lo, float hi) {
    uint32_t c, r;
    asm("cvt.rn.f16x2.f32 %0, %1, %2;" : "=r"(c) : "f"(hi), "f"(lo));
    asm("ex2.approx.f16x2 %0, %1;" : "=r"(r) : "r"(c));
    return r;
}
__device__ __forceinline__ uint32_t h2u(__half2 h) {
    union { __half2 h; uint32_t u; } c; c.h = h; return c.u;
}

// ---------------------------------------------------------------------------
// Pre-pass kernels
// ---------------------------------------------------------------------------
__global__ void cvt_half_k(const float4* __restrict__ in, uint2* __restrict__ out, int n4) {
    int i = blockIdx.x * blockDim.x + threadIdx.x;
    if (i < n4) {
        float4 v = in[i];
        uint2 o;
        o.x = h2u(__floats2half2_rn(v.x, v.y));
        o.y = h2u(__floats2half2_rn(v.z, v.w));
        out[i] = o;
    }
}

// W [K][NC] fp32 -> WT [NC][K] half. PERM: rows h*192+p*64+d -> p*1024+h*64+d
template<bool PERM>
__global__ void trans_half(const float* __restrict__ W, __half* __restrict__ WT,
                           int K, int NC)
{
    __shared__ float t[32][33];
    int c0 = blockIdx.x * 32, k0 = blockIdx.y * 32;
    #pragma unroll
    for (int i = 0; i < 32; i += 8)
        t[threadIdx.y + i][threadIdx.x] =
            W[(size_t)(k0 + threadIdx.y + i) * NC + c0 + threadIdx.x];
    __syncthreads();
    int cbase = PERM ? ((c0 % 192) / 64) * 1024 + (c0 / 192) * 64 + (c0 % 64) : c0;
    #pragma unroll
    for (int i = 0; i < 32; i += 8) {
        int j = threadIdx.y + i;
        WT[(size_t)(cbase + j) * K + k0 + threadIdx.x] = __float2half_rn(t[threadIdx.x][j]);
    }
}

// ---------------------------------------------------------------------------
// FP16 GEMM: C = A @ Bt^T + bias. A [M][K], Bt [N][K] half, row-major.
// 128x128x64 CTA tile, 128 thr (4 warps, 64x64 warp tile), 3-stage cp.async,
// software-pipelined (double-buffered) ldmatrix fragments.
// MODE 0: fp32 C, direct bias.
// MODE 1: half C; bias read with inverse QKV permutation; Q cols (<1024)
//         scaled by QSCALE; cols >= nsplit stored transposed to Cvt (half).
// ---------------------------------------------------------------------------
template<int MODE>
__global__ __launch_bounds__(128, 2)
void gemm_f16(const __half* __restrict__ A, const __half* __restrict__ Bt,
              const float* __restrict__ bias, void* __restrict__ Cout,
              __half* __restrict__ Cvt, int nsplit,
              int M, int Nstride, int K)
{
    extern __shared__ __half sh[];
    __half (*As)[128][72] = (__half (*)[128][72])sh;                 // 3 stages
    __half (*Bs)[128][72] = (__half (*)[128][72])(sh + 3 * 128 * 72);

    const int tid  = threadIdx.x;
    const int bm   = blockIdx.y, bn = blockIdx.x;
    const int warp = tid >> 5, lane = tid & 31;
    const int wm   = (warp >> 1) * 64;
    const int wn   = (warp & 1) * 64;
    const int lr   = lane >> 2, lc = lane & 3;

    const int arow = wm + ((lane >> 3) & 1) * 8 + (lane & 7);   // + mt*16
    const int ach  = ((lane >> 4) & 1) * 8;                     // + kt*16
    const int brow = wn + ((lane >> 4) & 1) * 8 + (lane & 7);   // + ntp*16
    const int bch  = ((lane >> 3) & 1) * 8;                     // + kt*16

    const int ntiles = K >> 6;

    float d[4][8][4];
    #pragma unroll
    for (int mt = 0; mt < 4; mt++)
        #pragma unroll
        for (int nt = 0; nt < 8; nt++)
            #pragma unroll
            for (int r = 0; r < 4; r++) d[mt][nt][r] = 0.f;

    auto prefetch = [&](int t, int buf) {
        int k0 = t << 6;
        #pragma unroll
        for (int i = 0; i < 8; i++) {
            int idx = i * 128 + tid;
            int r = idx >> 3, c = idx & 7;
            cp16(smaddr(&As[buf][r][c * 8]), A  + (size_t)(bm * 128 + r) * K + k0 + c * 8);
        }
        #pragma unroll
        for (int i = 0; i < 8; i++) {
            int idx = i * 128 + tid;
            int r = idx >> 3, c = idx & 7;
            cp16(smaddr(&Bs[buf][r][c * 8]), Bt + (size_t)(bn * 128 + r) * K + k0 + c * 8);
        }
        CP_COMMIT();
    };

    auto load_frags = [&](int cur, int kt, uint32_t (&a)[4][4], uint32_t (&b)[8][2]) {
        #pragma unroll
        for (int mt = 0; mt < 4; mt++)
            ldsm_x4(a[mt], smaddr(&As[cur][arow + mt * 16][kt * 16 + ach]));
        #pragma unroll
        for (int ntp = 0; ntp < 4; ntp++) {
            uint32_t t4[4];
            ldsm_x4(t4, smaddr(&Bs[cur][brow + ntp * 16][kt * 16 + bch]));
            b[2 * ntp][0] = t4[0]; b[2 * ntp][1] = t4[1];
            b[2 * ntp + 1][0] = t4[2]; b[2 * ntp + 1][1] = t4[3];
        }
    };

    prefetch(0, 0);
    prefetch(1, 1);

    for (int t = 0; t < ntiles; t++) {
        int cur = t % 3;
        if (t + 1 < ntiles) { CP_WAIT(1); } else { CP_WAIT(0); }
        __syncthreads();
        if (t + 2 < ntiles) prefetch(t + 2, (t + 2) % 3);

        uint32_t a[2][4][4], b[2][8][2];
        load_frags(cur, 0, a[0], b[0]);
        #pragma unroll
        for (int kt = 0; kt < 4; kt++) {
            int cf = kt & 1;
            if (kt < 3) load_frags(cur, kt + 1, a[cf ^ 1], b[cf ^ 1]);
            #pragma unroll
            for (int mt = 0; mt < 4; mt++)
                #pragma unroll
                for (int nt = 0; nt < 8; nt++)
                    mma_f16(d[mt][nt], a[cf][mt][0], a[cf][mt][1],
                            a[cf][mt][2], a[cf][mt][3], b[cf][nt][0], b[cf][nt][1]);
        }
    }

    #pragma unroll
    for (int mt = 0; mt < 4; mt++) {
        #pragma unroll
        for (int nt = 0; nt < 8; nt++) {
            int row  = bm * 128 + wm + mt * 16 + lr;
            int colg = bn * 128 + wn + nt * 8 + 2 * lc;
            float2 bv;
            if (MODE == 1) {   // inverse QKV permutation of bias index
                int map = ((colg & 1023) >> 6) * 192 + (colg >> 10) * 64 + (colg & 63);
                bv = *(const float2*)(bias + map);
            } else {
                bv = *(const float2*)(bias + colg);
            }
            float e0 = d[mt][nt][0] + bv.x, e1 = d[mt][nt][1] + bv.y;
            float e2 = d[mt][nt][2] + bv.x, e3 = d[mt][nt][3] + bv.y;
            if (MODE == 0) {
                float* C = (float*)Cout;
                *(float2*)(C + (size_t)row * Nstride + colg)       = make_float2(e0, e1);
                *(float2*)(C + (size_t)(row + 8) * Nstride + colg) = make_float2(e2, e3);
            } else {
                if (colg >= nsplit) {   // V third -> transposed half
                    __half* p0 = Cvt + (size_t)(colg - nsplit) * M;
                    __half* p1 = p0 + M;
                    p0[row]     = __float2half_rn(e0);
                    p1[row]     = __float2half_rn(e1);
                    p0[row + 8] = __float2half_rn(e2);
                    p1[row + 8] = __float2half_rn(e3);
                } else {
                    float s = (colg < 1024) ? QSCALE : 1.0f;   // pre-scale Q (log2 domain)
                    __half* C = (__half*)Cout;
                    *(__half2*)(C + (size_t)row * Nstride + colg) =
                        __floats2half2_rn(e0 * s, e1 * s);
                    *(__half2*)(C + (size_t)(row + 8) * Nstride + colg) =
                        __floats2half2_rn(e2 * s, e3 * s);
                }
            }
        }
    }
}

// ---------------------------------------------------------------------------
// Flash attention, fp16 mma + ldmatrix. ONLINE softmax (per-row running max,
// rescale-skip heuristic), l via ones-row mma, P register-resident.
// 128-key stages (2 x 64-key sub-blocks), 2-stage cp.async: one sync and
// one prefetch per 128 keys.
// grid=(SEQ/128, NH, NB), block=128 (4 warps x 32 q-rows).
// smem: Qs[128][72] | Ks[2][128][72] | Vst[2][80][136]  = 98816 B
// ---------------------------------------------------------------------------
__global__ __launch_bounds__(128, 2)
void attn_f16(const __half* __restrict__ Qk, const __half* __restrict__ Vt,
              __half* __restrict__ Out)
{
    extern __shared__ __half smp[];
    __half* Qs = smp;                                          // [128][72]
    __half (*Ks )[128][72]  = (__half (*)[128][72])(smp + 128 * 72);
    __half (*Vst)[80][136]  = (__half (*)[80][136])(smp + 128 * 72 + 2 * 128 * 72);

    const int qb = blockIdx.x, h = blockIdx.y, n = blockIdx.z;
    const int tid = threadIdx.x, warp = tid >> 5, lane = tid & 31;
    const int lr = lane >> 2, lc = lane & 3;

    const __half* Qbase = Qk + (size_t)(n * SEQ) * 2048 + h * 64;
    const __half* Kbase = Qbase + 1024;
    const __half* Vbase = Vt + (size_t)(h * 64) * NTOK + n * SEQ;

    const int ar  = warp * 32 + ((lane >> 3) & 1) * 8 + (lane & 7);  // + mi*16
    const int ach = ((lane >> 4) & 1) * 8;
    const int br  = ((lane >> 4) & 1) * 8 + (lane & 7);              // + ntp*16
    const int bch = ((lane >> 3) & 1) * 8;

    // one stage = 128 keys of K (rows) and V ([d][key], 128 key cols)
    auto prefetch_kv = [&](int t, int buf) {
        #pragma unroll
        for (int i = 0; i < 8; i++) {
            int idx = i * 128 + tid;
            int r = idx >> 3, c = idx & 7;          // K: 128 rows x 64 halves
            cp16(smaddr(&Ks[buf][r][c * 8]),
                 Kbase + (size_t)(t * 128 + r) * 2048 + c * 8);
        }
        #pragma unroll
        for (int i = 0; i < 8; i++) {
            int idx = i * 128 + tid;
            int r = idx >> 4, c = idx & 15;         // V: 64 d-rows x 128 keys
            cp16(smaddr(&Vst[buf][r][c * 8]),
                 Vbase + (size_t)r * NTOK + t * 128 + c * 8);
        }
        CP_COMMIT();
    };

    auto load_vfrags = [&](int cur, int j, int kt, uint32_t (&bb)[10][2]) {
        #pragma unroll
        for (int ntp = 0; ntp < 5; ntp++) {
            uint32_t t4[4];
            ldsm_x4(t4, smaddr(&Vst[cur][br + ntp * 16][j * 64 + kt * 16 + bch]));
            bb[2 * ntp][0] = t4[0]; bb[2 * ntp][1] = t4[1];
            bb[2 * ntp + 1][0] = t4[2]; bb[2 * ntp + 1][1] = t4[3];
        }
    };

    // stage Q (128 rows) + kv stage 0 in one commit group
    #pragma unroll
    for (int i = 0; i < 8; i++) {
        int idx = i * 128 + tid;
        int r = idx >> 3, c = idx & 7;
        cp16(smaddr(&Qs[r * 72 + c * 8]),
             Qbase + (size_t)(qb * 128 + r) * 2048 + c * 8);
    }
    prefetch_kv(0, 0);

    // static ones rows: Vst rows 64..79 (row 64 = 1), both buffers
    for (int i = tid; i < 2 * 16 * 136; i += 128) {
        int buf = i / (16 * 136);
        int rem = i - buf * (16 * 136);
        int r = rem / 136, c = rem - r * 136;
        Vst[buf][64 + r][c] = __float2half((r == 0) ? 1.f : 0.f);
    }

    CP_WAIT(0);
    __syncthreads();

    uint32_t aq[4][2][4];  // [kt][mi]
    #pragma unroll
    for (int kt = 0; kt < 4; kt++)
        #pragma unroll
        for (int mi = 0; mi < 2; mi++)
            ldsm_x4(aq[kt][mi], smaddr(&Qs[(ar + mi * 16) * 72 + kt * 16 + ach]));

    float o[2][9][4];
    #pragma unroll
    for (int mi = 0; mi < 2; mi++)
        #pragma unroll
        for (int nt = 0; nt < 9; nt++)
            #pragma unroll
            for (int r = 0; r < 4; r++) o[mi][nt][r] = 0.f;
    float mm[2][2] = {{-1e30f, -1e30f}, {-1e30f, -1e30f}};

    const int NT = SEQ / 128;
    for (int t = 0; t < NT; t++) {
        int cur = t & 1;
        if (t > 0) {
            CP_WAIT(0);
            __syncthreads();
        }
        if (t + 1 < NT) prefetch_kv(t + 1, cur ^ 1);

        #pragma unroll
        for (int j = 0; j < 2; j++) {   // two 64-key sub-blocks
            // S = Q @ K^T  (log2 domain)
            float s[2][8][4];
            #pragma unroll
            for (int mi = 0; mi < 2; mi++)
                #pragma unroll
                for (int nt = 0; nt < 8; nt++)
                    #pragma unroll
                    for (int r = 0; r < 4; r++) s[mi][nt][r] = 0.f;
            #pragma unroll
            for (int kt = 0; kt < 4; kt++) {
                uint32_t bb[8][2];
                #pragma unroll
                for (int ntp = 0; ntp < 4; ntp++) {
                    uint32_t t4[4];
                    ldsm_x4(t4, smaddr(&Ks[cur][j * 64 + br + ntp * 16][kt * 16 + bch]));
                    bb[2 * ntp][0] = t4[0]; bb[2 * ntp][1] = t4[1];
                    bb[2 * ntp + 1][0] = t4[2]; bb[2 * ntp + 1][1] = t4[3];
                }
                #pragma unroll
                for (int mi = 0; mi < 2; mi++)
                    #pragma unroll
                    for (int nt = 0; nt < 8; nt++)
                        mma_f16(s[mi][nt], aq[kt][mi][0], aq[kt][mi][1],
                                aq[kt][mi][2], aq[kt][mi][3], bb[nt][0], bb[nt][1]);
            }

            // online softmax (fp32 stats; exp2) per m-tile
            float al[2][2];
            #pragma unroll
            for (int mi = 0; mi < 2; mi++) {
                float mx0 = s[mi][0][0], mx1 = s[mi][0][2];
                #pragma unroll
                for (int nt = 0; nt < 8; nt++) {
                    mx0 = fmaxf(mx0, fmaxf(s[mi][nt][0], s[mi][nt][1]));
                    mx1 = fmaxf(mx1, fmaxf(s[mi][nt][2], s[mi][nt][3]));
                }
                mx0 = fmaxf(mx0, __shfl_xor_sync(0xffffffffu, mx0, 1));
                mx0 = fmaxf(mx0, __shfl_xor_sync(0xffffffffu, mx0, 2));
                mx1 = fmaxf(mx1, __shfl_xor_sync(0xffffffffu, mx1, 1));
                mx1 = fmaxf(mx1, __shfl_xor_sync(0xffffffffu, mx1, 2));
                float nm0 = fmaxf(mm[mi][0], mx0), nm1 = fmaxf(mm[mi][1], mx1);
                al[mi][0] = ex2(mm[mi][0] - nm0);
                al[mi][1] = ex2(mm[mi][1] - nm1);
                mm[mi][0] = nm0; mm[mi][1] = nm1;
            }
            if (!__all_sync(0xffffffffu,
                            (al[0][0] == 1.f) && (al[0][1] == 1.f) &&
                            (al[1][0] == 1.f) && (al[1][1] == 1.f))) {
                #pragma unroll
                for (int mi = 0; mi < 2; mi++)
                    #pragma unroll
                    for (int nt = 0; nt < 9; nt++) {
                        o[mi][nt][0] *= al[mi][0]; o[mi][nt][1] *= al[mi][0];
                        o[mi][nt][2] *= al[mi][1]; o[mi][nt][3] *= al[mi][1];
                    }
            }

            // P = 2^(s-m), packed f16x2, register-resident
            uint32_t p01[2][8], p23[2][8];
            #pragma unroll
            for (int mi = 0; mi < 2; mi++)
                #pragma unroll
                for (int nt = 0; nt < 8; nt++) {
                    p01[mi][nt] = ex2_h2(s[mi][nt][0] - mm[mi][0],
                                         s[mi][nt][1] - mm[mi][0]);
                    p23[mi][nt] = ex2_h2(s[mi][nt][2] - mm[mi][1],
                                         s[mi][nt][3] - mm[mi][1]);
                }

            // O += P @ [V ; ones-row]  (nt=8 = l); V frags double-buffered
            uint32_t bb[2][10][2];
            load_vfrags(cur, j, 0, bb[0]);
            #pragma unroll
            for (int kt = 0; kt < 4; kt++) {
                int cf = kt & 1;
                if (kt < 3) load_vfrags(cur, j, kt + 1, bb[cf ^ 1]);
                #pragma unroll
                for (int mi = 0; mi < 2; mi++) {
                    uint32_t a0 = p01[mi][2 * kt],     a1 = p23[mi][2 * kt];
                    uint32_t a2 = p01[mi][2 * kt + 1], a3 = p23[mi][2 * kt + 1];
                    #pragma unroll
                    for (int nt = 0; nt < 9; nt++)
                        mma_f16(o[mi][nt], a0, a1, a2, a3, bb[cf][nt][0], bb[cf][nt][1]);
                }
            }
        }
    }

    // epilogue: l in o[mi][8][0]/[2] of lc==0 lanes
    #pragma unroll
    for (int mi = 0; mi < 2; mi++) {
        float l0 = __shfl_sync(0xffffffffu, o[mi][8][0], lane & 28);
        float l1 = __shfl_sync(0xffffffffu, o[mi][8][2], lane & 28);
        float inv0 = 1.f / l0, inv1 = 1.f / l1;
        int row0 = qb * 128 + warp * 32 + mi * 16 + lr;
        __half* op0 = Out + (size_t)(n * SEQ + row0) * EDIM + h * 64;
        __half* op1 = op0 + (size_t)8 * EDIM;
        #pragma unroll
        for (int nt = 0; nt < 8; nt++) {
            int col = nt * 8 + 2 * lc;
            *(__half2*)(op0 + col) = __floats2half2_rn(o[mi][nt][0] * inv0,
                                                       o[mi][nt][1] * inv0);
            *(__half2*)(op1 + col) = __floats2half2_rn(o[mi][nt][2] * inv1,
                                                       o[mi][nt][3] * inv1);
        }
    }
}

// ---------------------------------------------------------------------------
extern "C" void kernel_launch(void* const* d_in, const int* in_sizes, int n_in,
                              void* d_out, int out_size)
{
    const float* x  = (const float*)d_in[0];
    const float* W1 = (const float*)d_in[1];
    const float* b1 = (const float*)d_in[2];
    const float* W2 = (const float*)d_in[3];
    const float* b2 = (const float*)d_in[4];
    float* out = (float*)d_out;

    __half *QKbuf, *VTbuf, *Abuf, *Xbuf, *W1Tbuf, *W2Tbuf;
    cudaGetSymbolAddress((void**)&QKbuf,  g_QK);
    cudaGetSymbolAddress((void**)&VTbuf,  g_VT);
    cudaGetSymbolAddress((void**)&Abuf,   g_ATT);
    cudaGetSymbolAddress((void**)&Xbuf,   g_X);
    cudaGetSymbolAddress((void**)&W1Tbuf, g_W1T);
    cudaGetSymbolAddress((void**)&W2Tbuf, g_W2T);

    const int gemm_smem = 3 * 2 * 128 * 72 * 2;                         // 110592 B
    const int attn_smem = (128 * 72 + 2 * 128 * 72 + 2 * 80 * 136) * 2; // 98816 B
    static bool attr_done = false;
    if (!attr_done) {
        cudaFuncSetAttribute(gemm_f16<0>,
                             cudaFuncAttributeMaxDynamicSharedMemorySize, gemm_smem);
        cudaFuncSetAttribute(gemm_f16<1>,
                             cudaFuncAttributeMaxDynamicSharedMemorySize, gemm_smem);
        cudaFuncSetAttribute(attn_f16,
                             cudaFuncAttributeMaxDynamicSharedMemorySize, attn_smem);
        attr_done = true;
    }

    // pre-pass: x -> half; W1 -> permuted transposed half; W2 -> transposed half
    cvt_half_k<<<(NTOK * EDIM / 4 + 255) / 256, 256>>>((const float4*)x,
                                                       (uint2*)Xbuf, NTOK * EDIM / 4);
    trans_half<true ><<<dim3(H3 / 32, EDIM / 32), dim3(32, 8)>>>(W1, W1Tbuf, EDIM, H3);
    trans_half<false><<<dim3(EDIM / 32, EDIM / 32), dim3(32, 8)>>>(W2, W2Tbuf, EDIM, EDIM);

    // 1) QKV projection: Q(scaled)/K -> g_QK, V -> g_VT transposed
    gemm_f16<1><<<dim3(H3 / 128, NTOK / 128), 128, gemm_smem>>>(
        Xbuf, W1Tbuf, b1, QKbuf, VTbuf, 2048, NTOK, 2048, EDIM);
    // 2) attention -> g_ATT (half)
    attn_f16<<<dim3(SEQ / 128, NH, NB), 128, attn_smem>>>(QKbuf, VTbuf, Abuf);
    // 3) output projection -> fp32 out
    gemm_f16<0><<<dim3(EDIM / 128, NTOK / 128), 128, gemm_smem>>>(
        Abuf, W2Tbuf, b2, out, nullptr, 1 << 30, NTOK, EDIM, EDIM);
}

// round 13
// speedup vs baseline: 9.3303x; 1.0005x over previous
#include <cuda_runtime.h>
#include <cuda_fp16.h>
#include <cstdint>

#define NB   4
#define SEQ  2048
#define EDIM 1024
#define H3   3072
#define NH   16
#define NTOK (NB*SEQ)

// Q pre-scale: (1/sqrt(64)) * log2(e)  -> scores land in log2 domain
#define QSCALE 0.180336880111120432f

// Scratch (device globals: allocation-free, graph-capture safe)
__device__ __half g_QKV[(size_t)NTOK * H3];    // [token][Qall(scaled)|Kall|Vall]
__device__ __half g_ATT[(size_t)NTOK * EDIM];  // attention out
__device__ __half g_X  [(size_t)NTOK * EDIM];  // x in half
__device__ __half g_W1T[(size_t)H3   * EDIM];  // W1^T, rows permuted [Q|K|V]
__device__ __half g_W2T[(size_t)EDIM * EDIM];  // W2^T

__device__ __forceinline__ void mma_f16(float d[4],
                                        uint32_t a0, uint32_t a1, uint32_t a2, uint32_t a3,
                                        uint32_t b0, uint32_t b1) {
    asm volatile(
        "mma.sync.aligned.m16n8k16.row.col.f32.f16.f16.f32 "
        "{%0,%1,%2,%3}, {%4,%5,%6,%7}, {%8,%9}, {%0,%1,%2,%3};"
        : "+f"(d[0]), "+f"(d[1]), "+f"(d[2]), "+f"(d[3])
        : "r"(a0), "r"(a1), "r"(a2), "r"(a3), "r"(b0), "r"(b1));
}
__device__ __forceinline__ uint32_t smaddr(const void* p) {
    return (uint32_t)__cvta_generic_to_shared(p);
}
__device__ __forceinline__ void ldsm_x4(uint32_t r[4], uint32_t addr) {
    asm volatile("ldmatrix.sync.aligned.m8n8.x4.shared.b16 {%0,%1,%2,%3}, [%4];"
                 : "=r"(r[0]), "=r"(r[1]), "=r"(r[2]), "=r"(r[3]) : "r"(addr));
}
__device__ __forceinline__ void ldsm_x4_t(uint32_t r[4], uint32_t addr) {
    asm volatile("ldmatrix.sync.aligned.m8n8.x4.trans.shared.b16 {%0,%1,%2,%3}, [%4];"
                 : "=r"(r[0]), "=r"(r[1]), "=r"(r[2]), "=r"(r[3]) : "r"(addr));
}
__device__ __forceinline__ void cp16(uint32_t dst, const void* src) {
    asm volatile("cp.async.cg.shared.global [%0], [%1], 16;\n" :: "r"(dst), "l"(src));
}
#define CP_COMMIT()  asm volatile("cp.async.commit_group;\n" ::: "memory")
#define CP_WAIT(n)   asm volatile("cp.async.wait_group %0;\n" :: "n"(n) : "memory")

__device__ __forceinline__ float ex2(float x) {
    float y;
    asm("ex2.approx.ftz.f32 %0, %1;" : "=f"(y) : "f"(x));
    return y;
}
// packed: returns half2 { lo = 2^lo_in, hi = 2^hi_in }
__device__ __forceinline__ uint32_t ex2_h2(float lo, float hi) {
    uint32_t c, r;
    asm("cvt.rn.f16x2.f32 %0, %1, %2;" : "=r"(c) : "f"(hi), "f"(lo));
    asm("ex2.approx.f16x2 %0, %1;" : "=r"(r) : "r"(c));
    return r;
}
__device__ __forceinline__ uint32_t h2u(__half2 h) {
    union { __half2 h; uint32_t u; } c; c.h = h; return c.u;
}

// ---------------------------------------------------------------------------
// Pre-pass kernels
// ---------------------------------------------------------------------------
__global__ void cvt_half_k(const float4* __restrict__ in, uint2* __restrict__ out, int n4) {
    int i = blockIdx.x * blockDim.x + threadIdx.x;
    if (i < n4) {
        float4 v = in[i];
        uint2 o;
        o.x = h2u(__floats2half2_rn(v.x, v.y));
        o.y = h2u(__floats2half2_rn(v.z, v.w));
        out[i] = o;
    }
}

// W [K][NC] fp32 -> WT [NC][K] half. PERM: rows h*192+p*64+d -> p*1024+h*64+d
template<bool PERM>
__global__ void trans_half(const float* __restrict__ W, __half* __restrict__ WT,
                           int K, int NC)
{
    __shared__ float t[32][33];
    int c0 = blockIdx.x * 32, k0 = blockIdx.y * 32;
    #pragma unroll
    for (int i = 0; i < 32; i += 8)
        t[threadIdx.y + i][threadIdx.x] =
            W[(size_t)(k0 + threadIdx.y + i) * NC + c0 + threadIdx.x];
    __syncthreads();
    int cbase = PERM ? ((c0 % 192) / 64) * 1024 + (c0 / 192) * 64 + (c0 % 64) : c0;
    #pragma unroll
    for (int i = 0; i < 32; i += 8) {
        int j = threadIdx.y + i;
        WT[(size_t)(cbase + j) * K + k0 + threadIdx.x] = __float2half_rn(t[threadIdx.x][j]);
    }
}

// ---------------------------------------------------------------------------
// FP16 GEMM: C = A @ Bt^T + bias. A [M][K], Bt [N][K] half, row-major.
// 128x128x64 CTA tile, 128 thr (4 warps, 64x64 warp tile), 3-stage cp.async,
// software-pipelined (double-buffered) ldmatrix fragments.
// MODE 0: fp32 C, direct bias.
// MODE 1: half C; bias read with inverse QKV permutation; Q cols (<1024)
//         scaled by QSCALE.
// ---------------------------------------------------------------------------
template<int MODE>
__global__ __launch_bounds__(128, 2)
void gemm_f16(const __half* __restrict__ A, const __half* __restrict__ Bt,
              const float* __restrict__ bias, void* __restrict__ Cout,
              int M, int Nstride, int K)
{
    extern __shared__ __half sh[];
    __half (*As)[128][72] = (__half (*)[128][72])sh;                 // 3 stages
    __half (*Bs)[128][72] = (__half (*)[128][72])(sh + 3 * 128 * 72);

    const int tid  = threadIdx.x;
    const int bm   = blockIdx.y, bn = blockIdx.x;
    const int warp = tid >> 5, lane = tid & 31;
    const int wm   = (warp >> 1) * 64;
    const int wn   = (warp & 1) * 64;
    const int lr   = lane >> 2, lc = lane & 3;

    const int arow = wm + ((lane >> 3) & 1) * 8 + (lane & 7);   // + mt*16
    const int ach  = ((lane >> 4) & 1) * 8;                     // + kt*16
    const int brow = wn + ((lane >> 4) & 1) * 8 + (lane & 7);   // + ntp*16
    const int bch  = ((lane >> 3) & 1) * 8;                     // + kt*16

    const int ntiles = K >> 6;

    float d[4][8][4];
    #pragma unroll
    for (int mt = 0; mt < 4; mt++)
        #pragma unroll
        for (int nt = 0; nt < 8; nt++)
            #pragma unroll
            for (int r = 0; r < 4; r++) d[mt][nt][r] = 0.f;

    auto prefetch = [&](int t, int buf) {
        int k0 = t << 6;
        #pragma unroll
        for (int i = 0; i < 8; i++) {
            int idx = i * 128 + tid;
            int r = idx >> 3, c = idx & 7;
            cp16(smaddr(&As[buf][r][c * 8]), A  + (size_t)(bm * 128 + r) * K + k0 + c * 8);
        }
        #pragma unroll
        for (int i = 0; i < 8; i++) {
            int idx = i * 128 + tid;
            int r = idx >> 3, c = idx & 7;
            cp16(smaddr(&Bs[buf][r][c * 8]), Bt + (size_t)(bn * 128 + r) * K + k0 + c * 8);
        }
        CP_COMMIT();
    };

    auto load_frags = [&](int cur, int kt, uint32_t (&a)[4][4], uint32_t (&b)[8][2]) {
        #pragma unroll
        for (int mt = 0; mt < 4; mt++)
            ldsm_x4(a[mt], smaddr(&As[cur][arow + mt * 16][kt * 16 + ach]));
        #pragma unroll
        for (int ntp = 0; ntp < 4; ntp++) {
            uint32_t t4[4];
            ldsm_x4(t4, smaddr(&Bs[cur][brow + ntp * 16][kt * 16 + bch]));
            b[2 * ntp][0] = t4[0]; b[2 * ntp][1] = t4[1];
            b[2 * ntp + 1][0] = t4[2]; b[2 * ntp + 1][1] = t4[3];
        }
    };

    prefetch(0, 0);
    prefetch(1, 1);

    for (int t = 0; t < ntiles; t++) {
        int cur = t % 3;
        if (t + 1 < ntiles) { CP_WAIT(1); } else { CP_WAIT(0); }
        __syncthreads();
        if (t + 2 < ntiles) prefetch(t + 2, (t + 2) % 3);

        uint32_t a[2][4][4], b[2][8][2];
        load_frags(cur, 0, a[0], b[0]);
        #pragma unroll
        for (int kt = 0; kt < 4; kt++) {
            int cf = kt & 1;
            if (kt < 3) load_frags(cur, kt + 1, a[cf ^ 1], b[cf ^ 1]);
            #pragma unroll
            for (int mt = 0; mt < 4; mt++)
                #pragma unroll
                for (int nt = 0; nt < 8; nt++)
                    mma_f16(d[mt][nt], a[cf][mt][0], a[cf][mt][1],
                            a[cf][mt][2], a[cf][mt][3], b[cf][nt][0], b[cf][nt][1]);
        }
    }

    #pragma unroll
    for (int mt = 0; mt < 4; mt++) {
        #pragma unroll
        for (int nt = 0; nt < 8; nt++) {
            int row  = bm * 128 + wm + mt * 16 + lr;
            int colg = bn * 128 + wn + nt * 8 + 2 * lc;
            float2 bv;
            if (MODE == 1) {   // inverse QKV permutation of bias index
                int map = ((colg & 1023) >> 6) * 192 + (colg >> 10) * 64 + (colg & 63);
                bv = *(const float2*)(bias + map);
            } else {
                bv = *(const float2*)(bias + colg);
            }
            float e0 = d[mt][nt][0] + bv.x, e1 = d[mt][nt][1] + bv.y;
            float e2 = d[mt][nt][2] + bv.x, e3 = d[mt][nt][3] + bv.y;
            if (MODE == 0) {
                float* C = (float*)Cout;
                *(float2*)(C + (size_t)row * Nstride + colg)       = make_float2(e0, e1);
                *(float2*)(C + (size_t)(row + 8) * Nstride + colg) = make_float2(e2, e3);
            } else {
                float s = (colg < 1024) ? QSCALE : 1.0f;   // pre-scale Q (log2 domain)
                __half* C = (__half*)Cout;
                *(__half2*)(C + (size_t)row * Nstride + colg) =
                    __floats2half2_rn(e0 * s, e1 * s);
                *(__half2*)(C + (size_t)(row + 8) * Nstride + colg) =
                    __floats2half2_rn(e2 * s, e3 * s);
            }
        }
    }
}

// ---------------------------------------------------------------------------
// Flash attention, fp16 mma + ldmatrix. ONLINE softmax, l via ones-COLUMN
// mma (V padded d-col 64 = 1), P register-resident. V staged natural
// [key][d] and loaded with ldmatrix.trans (no pre-transposed V buffer).
// 128-key stages (2 x 64-key sub-blocks), 2-stage cp.async.
// grid=(SEQ/128, NH, NB), block=128 (4 warps x 32 q-rows).
// smem: Qs[128][72] | Ks[2][128][72] | Vs[2][128][88]  = 100352 B
// ---------------------------------------------------------------------------
__global__ __launch_bounds__(128, 2)
void attn_f16(const __half* __restrict__ Qkv, __half* __restrict__ Out)
{
    extern __shared__ __half smp[];
    __half* Qs = smp;                                          // [128][72]
    __half (*Ks)[128][72] = (__half (*)[128][72])(smp + 128 * 72);
    __half (*Vs)[128][88] = (__half (*)[128][88])(smp + 128 * 72 + 2 * 128 * 72);

    const int qb = blockIdx.x, h = blockIdx.y, n = blockIdx.z;
    const int tid = threadIdx.x, warp = tid >> 5, lane = tid & 31;
    const int lr = lane >> 2, lc = lane & 3;

    const __half* Qbase = Qkv + (size_t)(n * SEQ) * H3 + h * 64;
    const __half* Kbase = Qbase + 1024;
    const __half* Vbase = Qbase + 2048;

    const int ar  = warp * 32 + ((lane >> 3) & 1) * 8 + (lane & 7);  // + mi*16
    const int ach = ((lane >> 4) & 1) * 8;
    const int br  = ((lane >> 4) & 1) * 8 + (lane & 7);              // K frag row
    const int bch = ((lane >> 3) & 1) * 8;
    const int vtr = ((lane >> 3) & 1) * 8 + (lane & 7);              // V trans row (k)
    const int vtc = ((lane >> 4) & 1) * 8;                           // V trans col (n)

    // one stage = 128 keys of K rows and V rows (both [key][d])
    auto prefetch_kv = [&](int t, int buf) {
        #pragma unroll
        for (int i = 0; i < 8; i++) {
            int idx = i * 128 + tid;
            int r = idx >> 3, c = idx & 7;
            cp16(smaddr(&Ks[buf][r][c * 8]),
                 Kbase + (size_t)(t * 128 + r) * H3 + c * 8);
            cp16(smaddr(&Vs[buf][r][c * 8]),
                 Vbase + (size_t)(t * 128 + r) * H3 + c * 8);
        }
        CP_COMMIT();
    };

    // V B-fragments via ldmatrix.trans from [key][d] rows.
    // ntp 0..3 = d 0..63; ntp 4 = l-block (cols 64..79, col 64 = ones).
    auto load_vfrags = [&](int cur, int j, int kt, uint32_t (&bb)[10][2]) {
        #pragma unroll
        for (int ntp = 0; ntp < 5; ntp++) {
            uint32_t t4[4];
            ldsm_x4_t(t4, smaddr(&Vs[cur][j * 64 + kt * 16 + vtr][ntp * 16 + vtc]));
            bb[2 * ntp][0] = t4[0]; bb[2 * ntp][1] = t4[1];
            bb[2 * ntp + 1][0] = t4[2]; bb[2 * ntp + 1][1] = t4[3];
        }
    };

    // stage Q (128 rows) + kv stage 0 in one commit group
    #pragma unroll
    for (int i = 0; i < 8; i++) {
        int idx = i * 128 + tid;
        int r = idx >> 3, c = idx & 7;
        cp16(smaddr(&Qs[r * 72 + c * 8]),
             Qbase + (size_t)(qb * 128 + r) * H3 + c * 8);
    }
    prefetch_kv(0, 0);

    // static ones-column block: Vs cols 64..79 (col 64 = 1), all rows, both bufs
    for (int i = tid; i < 2 * 128 * 16; i += 128) {
        int buf = i >> 11;            // /(128*16)
        int rem = i & 2047;
        int r = rem >> 4, c = rem & 15;
        Vs[buf][r][64 + c] = __float2half((c == 0) ? 1.f : 0.f);
    }

    CP_WAIT(0);
    __syncthreads();

    uint32_t aq[4][2][4];  // [kt][mi]
    #pragma unroll
    for (int kt = 0; kt < 4; kt++)
        #pragma unroll
        for (int mi = 0; mi < 2; mi++)
            ldsm_x4(aq[kt][mi], smaddr(&Qs[(ar + mi * 16) * 72 + kt * 16 + ach]));

    float o[2][9][4];
    #pragma unroll
    for (int mi = 0; mi < 2; mi++)
        #pragma unroll
        for (int nt = 0; nt < 9; nt++)
            #pragma unroll
            for (int r = 0; r < 4; r++) o[mi][nt][r] = 0.f;
    float mm[2][2] = {{-1e30f, -1e30f}, {-1e30f, -1e30f}};

    const int NT = SEQ / 128;
    for (int t = 0; t < NT; t++) {
        int cur = t & 1;
        if (t > 0) {
            CP_WAIT(0);
            __syncthreads();
        }
        if (t + 1 < NT) prefetch_kv(t + 1, cur ^ 1);

        #pragma unroll
        for (int j = 0; j < 2; j++) {   // two 64-key sub-blocks
            // S = Q @ K^T (log2 domain); K fragments double-buffered
            float s[2][8][4];
            #pragma unroll
            for (int mi = 0; mi < 2; mi++)
                #pragma unroll
                for (int nt = 0; nt < 8; nt++)
                    #pragma unroll
                    for (int r = 0; r < 4; r++) s[mi][nt][r] = 0.f;
            uint32_t kb[2][8][2];
            {
                uint32_t t4[4];
                #pragma unroll
                for (int ntp = 0; ntp < 4; ntp++) {
                    ldsm_x4(t4, smaddr(&Ks[cur][j * 64 + br + ntp * 16][bch]));
                    kb[0][2 * ntp][0] = t4[0]; kb[0][2 * ntp][1] = t4[1];
                    kb[0][2 * ntp + 1][0] = t4[2]; kb[0][2 * ntp + 1][1] = t4[3];
                }
            }
            #pragma unroll
            for (int kt = 0; kt < 4; kt++) {
                int cf = kt & 1;
                if (kt < 3) {
                    uint32_t t4[4];
                    #pragma unroll
                    for (int ntp = 0; ntp < 4; ntp++) {
                        ldsm_x4(t4, smaddr(&Ks[cur][j * 64 + br + ntp * 16]
                                                   [(kt + 1) * 16 + bch]));
                        kb[cf ^ 1][2 * ntp][0] = t4[0];
                        kb[cf ^ 1][2 * ntp][1] = t4[1];
                        kb[cf ^ 1][2 * ntp + 1][0] = t4[2];
                        kb[cf ^ 1][2 * ntp + 1][1] = t4[3];
                    }
                }
                #pragma unroll
                for (int mi = 0; mi < 2; mi++)
                    #pragma unroll
                    for (int nt = 0; nt < 8; nt++)
                        mma_f16(s[mi][nt], aq[kt][mi][0], aq[kt][mi][1],
                                aq[kt][mi][2], aq[kt][mi][3],
                                kb[cf][nt][0], kb[cf][nt][1]);
            }

            // online softmax (fp32 stats; exp2) per m-tile
            float al[2][2];
            #pragma unroll
            for (int mi = 0; mi < 2; mi++) {
                float mx0 = s[mi][0][0], mx1 = s[mi][0][2];
                #pragma unroll
                for (int nt = 0; nt < 8; nt++) {
                    mx0 = fmaxf(mx0, fmaxf(s[mi][nt][0], s[mi][nt][1]));
                    mx1 = fmaxf(mx1, fmaxf(s[mi][nt][2], s[mi][nt][3]));
                }
                mx0 = fmaxf(mx0, __shfl_xor_sync(0xffffffffu, mx0, 1));
                mx0 = fmaxf(mx0, __shfl_xor_sync(0xffffffffu, mx0, 2));
                mx1 = fmaxf(mx1, __shfl_xor_sync(0xffffffffu, mx1, 1));
                mx1 = fmaxf(mx1, __shfl_xor_sync(0xffffffffu, mx1, 2));
                float nm0 = fmaxf(mm[mi][0], mx0), nm1 = fmaxf(mm[mi][1], mx1);
                al[mi][0] = ex2(mm[mi][0] - nm0);
                al[mi][1] = ex2(mm[mi][1] - nm1);
                mm[mi][0] = nm0; mm[mi][1] = nm1;
            }
            if (!__all_sync(0xffffffffu,
                            (al[0][0] == 1.f) && (al[0][1] == 1.f) &&
                            (al[1][0] == 1.f) && (al[1][1] == 1.f))) {
                #pragma unroll
                for (int mi = 0; mi < 2; mi++)
                    #pragma unroll
                    for (int nt = 0; nt < 9; nt++) {
                        o[mi][nt][0] *= al[mi][0]; o[mi][nt][1] *= al[mi][0];
                        o[mi][nt][2] *= al[mi][1]; o[mi][nt][3] *= al[mi][1];
                    }
            }

            // P = 2^(s-m), packed f16x2, register-resident
            uint32_t p01[2][8], p23[2][8];
            #pragma unroll
            for (int mi = 0; mi < 2; mi++)
                #pragma unroll
                for (int nt = 0; nt < 8; nt++) {
                    p01[mi][nt] = ex2_h2(s[mi][nt][0] - mm[mi][0],
                                         s[mi][nt][1] - mm[mi][0]);
                    p23[mi][nt] = ex2_h2(s[mi][nt][2] - mm[mi][1],
                                         s[mi][nt][3] - mm[mi][1]);
                }

            // O += P @ [V | ones-col]  (nt=8 = l); V frags double-buffered
            uint32_t bb[2][10][2];
            load_vfrags(cur, j, 0, bb[0]);
            #pragma unroll
            for (int kt = 0; kt < 4; kt++) {
                int cf = kt & 1;
                if (kt < 3) load_vfrags(cur, j, kt + 1, bb[cf ^ 1]);
                #pragma unroll
                for (int mi = 0; mi < 2; mi++) {
                    uint32_t a0 = p01[mi][2 * kt],     a1 = p23[mi][2 * kt];
                    uint32_t a2 = p01[mi][2 * kt + 1], a3 = p23[mi][2 * kt + 1];
                    #pragma unroll
                    for (int nt = 0; nt < 9; nt++)
                        mma_f16(o[mi][nt], a0, a1, a2, a3, bb[cf][nt][0], bb[cf][nt][1]);
                }
            }
        }
    }

    // epilogue: l in o[mi][8][0]/[2] of lc==0 lanes
    #pragma unroll
    for (int mi = 0; mi < 2; mi++) {
        float l0 = __shfl_sync(0xffffffffu, o[mi][8][0], lane & 28);
        float l1 = __shfl_sync(0xffffffffu, o[mi][8][2], lane & 28);
        float inv0 = 1.f / l0, inv1 = 1.f / l1;
        int row0 = qb * 128 + warp * 32 + mi * 16 + lr;
        __half* op0 = Out + (size_t)(n * SEQ + row0) * EDIM + h * 64;
        __half* op1 = op0 + (size_t)8 * EDIM;
        #pragma unroll
        for (int nt = 0; nt < 8; nt++) {
            int col = nt * 8 + 2 * lc;
            *(__half2*)(op0 + col) = __floats2half2_rn(o[mi][nt][0] * inv0,
                                                       o[mi][nt][1] * inv0);
            *(__half2*)(op1 + col) = __floats2half2_rn(o[mi][nt][2] * inv1,
                                                       o[mi][nt][3] * inv1);
        }
    }
}

// ---------------------------------------------------------------------------
extern "C" void kernel_launch(void* const* d_in, const int* in_sizes, int n_in,
                              void* d_out, int out_size)
{
    const float* x  = (const float*)d_in[0];
    const float* W1 = (const float*)d_in[1];
    const float* b1 = (const float*)d_in[2];
    const float* W2 = (const float*)d_in[3];
    const float* b2 = (const float*)d_in[4];
    float* out = (float*)d_out;

    __half *QKVbuf, *Abuf, *Xbuf, *W1Tbuf, *W2Tbuf;
    cudaGetSymbolAddress((void**)&QKVbuf, g_QKV);
    cudaGetSymbolAddress((void**)&Abuf,   g_ATT);
    cudaGetSymbolAddress((void**)&Xbuf,   g_X);
    cudaGetSymbolAddress((void**)&W1Tbuf, g_W1T);
    cudaGetSymbolAddress((void**)&W2Tbuf, g_W2T);

    const int gemm_smem = 3 * 2 * 128 * 72 * 2;                        // 110592 B
    const int attn_smem = (128 * 72 + 2 * 128 * 72 + 2 * 128 * 88) * 2; // 100352 B
    static bool attr_done = false;
    if (!attr_done) {
        cudaFuncSetAttribute(gemm_f16<0>,
                             cudaFuncAttributeMaxDynamicSharedMemorySize, gemm_smem);
        cudaFuncSetAttribute(gemm_f16<1>,
                             cudaFuncAttributeMaxDynamicSharedMemorySize, gemm_smem);
        cudaFuncSetAttribute(attn_f16,
                             cudaFuncAttributeMaxDynamicSharedMemorySize, attn_smem);
        attr_done = true;
    }

    // pre-pass: x -> half; W1 -> permuted transposed half; W2 -> transposed half
    cvt_half_k<<<(NTOK * EDIM / 4 + 255) / 256, 256>>>((const float4*)x,
                                                       (uint2*)Xbuf, NTOK * EDIM / 4);
    trans_half<true ><<<dim3(H3 / 32, EDIM / 32), dim3(32, 8)>>>(W1, W1Tbuf, EDIM, H3);
    trans_half<false><<<dim3(EDIM / 32, EDIM / 32), dim3(32, 8)>>>(W2, W2Tbuf, EDIM, EDIM);

    // 1) QKV projection: Q(scaled)|K|V rows -> g_QKV
    gemm_f16<1><<<dim3(H3 / 128, NTOK / 128), 128, gemm_smem>>>(
        Xbuf, W1Tbuf, b1, QKVbuf, NTOK, H3, EDIM);
    // 2) attention -> g_ATT (half)
    attn_f16<<<dim3(SEQ / 128, NH, NB), 128, attn_smem>>>(QKVbuf, Abuf);
    // 3) output projection -> fp32 out
    gemm_f16<0><<<dim3(EDIM / 128, NTOK / 128), 128, gemm_smem>>>(
        Abuf, W2Tbuf, b2, out, NTOK, EDIM, EDIM);
}

// round 14
// speedup vs baseline: 9.5304x; 1.0214x over previous
#include <cuda_runtime.h>
#include <cuda_fp16.h>
#include <cstdint>

#define NB   4
#define SEQ  2048
#define EDIM 1024
#define H3   3072
#define NH   16
#define NTOK (NB*SEQ)

// Q pre-scale: (1/sqrt(64)) * log2(e)  -> scores land in log2 domain
#define QSCALE 0.180336880111120432f

// Scratch (device globals: allocation-free, graph-capture safe)
__device__ __half g_QKV[(size_t)NTOK * H3];    // [token][Qall(scaled)|Kall|Vall]
__device__ __half g_ATT[(size_t)NTOK * EDIM];  // attention out
__device__ __half g_X  [(size_t)NTOK * EDIM];  // x in half
__device__ __half g_W1T[(size_t)H3   * EDIM];  // W1^T, rows permuted [Q|K|V]
__device__ __half g_W2T[(size_t)EDIM * EDIM];  // W2^T

__device__ __forceinline__ void mma_f16(float d[4],
                                        uint32_t a0, uint32_t a1, uint32_t a2, uint32_t a3,
                                        uint32_t b0, uint32_t b1) {
    asm volatile(
        "mma.sync.aligned.m16n8k16.row.col.f32.f16.f16.f32 "
        "{%0,%1,%2,%3}, {%4,%5,%6,%7}, {%8,%9}, {%0,%1,%2,%3};"
        : "+f"(d[0]), "+f"(d[1]), "+f"(d[2]), "+f"(d[3])
        : "r"(a0), "r"(a1), "r"(a2), "r"(a3), "r"(b0), "r"(b1));
}
__device__ __forceinline__ uint32_t smaddr(const void* p) {
    return (uint32_t)__cvta_generic_to_shared(p);
}
__device__ __forceinline__ void ldsm_x4(uint32_t r[4], uint32_t addr) {
    asm volatile("ldmatrix.sync.aligned.m8n8.x4.shared.b16 {%0,%1,%2,%3}, [%4];"
                 : "=r"(r[0]), "=r"(r[1]), "=r"(r[2]), "=r"(r[3]) : "r"(addr));
}
__device__ __forceinline__ void ldsm_x4_t(uint32_t r[4], uint32_t addr) {
    asm volatile("ldmatrix.sync.aligned.m8n8.x4.trans.shared.b16 {%0,%1,%2,%3}, [%4];"
                 : "=r"(r[0]), "=r"(r[1]), "=r"(r[2]), "=r"(r[3]) : "r"(addr));
}
__device__ __forceinline__ void cp16(uint32_t dst, const void* src) {
    asm volatile("cp.async.cg.shared.global [%0], [%1], 16;\n" :: "r"(dst), "l"(src));
}
#define CP_COMMIT()  asm volatile("cp.async.commit_group;\n" ::: "memory")
#define CP_WAIT(n)   asm volatile("cp.async.wait_group %0;\n" :: "n"(n) : "memory")

__device__ __forceinline__ float ex2(float x) {
    float y;
    asm("ex2.approx.ftz.f32 %0, %1;" : "=f"(y) : "f"(x));
    return y;
}
// packed: returns half2 { lo = 2^lo_in, hi = 2^hi_in }
__device__ __forceinline__ uint32_t ex2_h2(float lo, float hi) {
    uint32_t c, r;
    asm("cvt.rn.f16x2.f32 %0, %1, %2;" : "=r"(c) : "f"(hi), "f"(lo));
    asm("ex2.approx.f16x2 %0, %1;" : "=r"(r) : "r"(c));
    return r;
}
__device__ __forceinline__ uint32_t h2u(__half2 h) {
    union { __half2 h; uint32_t u; } c; c.h = h; return c.u;
}

// ---------------------------------------------------------------------------
// Merged pre-pass: block ranges dispatch x-convert / W1 trans / W2 trans.
//   blocks [0, XB)            : x fp32 -> half (float4 granularity)
//   blocks [XB, XB+W1B)       : W1 [1024][3072] -> W1T permuted [3072][1024]
//   blocks [XB+W1B, +W2B)     : W2 [1024][1024] -> W2T [1024][1024]
// ---------------------------------------------------------------------------
#define XB   (NTOK * EDIM / 4 / 256)        // 8192
#define W1B  ((H3 / 32) * (EDIM / 32))      // 3072
#define W2B  ((EDIM / 32) * (EDIM / 32))    // 1024

__global__ __launch_bounds__(256)
void prepass(const float* __restrict__ x, const float* __restrict__ W1,
             const float* __restrict__ W2, __half* __restrict__ Xh,
             __half* __restrict__ W1T, __half* __restrict__ W2T)
{
    __shared__ float t[32][33];
    int bid = blockIdx.x;
    if (bid < XB) {
        int i = bid * 256 + threadIdx.x;
        float4 v = ((const float4*)x)[i];
        uint2 o;
        o.x = h2u(__floats2half2_rn(v.x, v.y));
        o.y = h2u(__floats2half2_rn(v.z, v.w));
        ((uint2*)Xh)[i] = o;
        return;
    }
    // transpose jobs: 256 threads act as (32, 8)
    const float* W;
    __half* WT;
    int NC, K = EDIM;
    bool perm;
    int idx;
    if (bid < XB + W1B) {
        idx = bid - XB; W = W1; WT = W1T; NC = H3; perm = true;
        // grid (H3/32, EDIM/32): bx fastest
    } else {
        idx = bid - XB - W1B; W = W2; WT = W2T; NC = EDIM; perm = false;
    }
    int nbx = NC / 32;
    int bx = idx % nbx, by = idx / nbx;
    int tx = threadIdx.x & 31, ty = threadIdx.x >> 5;
    int c0 = bx * 32, k0 = by * 32;
    #pragma unroll
    for (int i = 0; i < 32; i += 8)
        t[ty + i][tx] = W[(size_t)(k0 + ty + i) * NC + c0 + tx];
    __syncthreads();
    int cbase = perm ? ((c0 % 192) / 64) * 1024 + (c0 / 192) * 64 + (c0 % 64) : c0;
    #pragma unroll
    for (int i = 0; i < 32; i += 8) {
        int j = ty + i;
        WT[(size_t)(cbase + j) * K + k0 + tx] = __float2half_rn(t[tx][j]);
    }
}

// ---------------------------------------------------------------------------
// FP16 GEMM: C = A @ Bt^T + bias. A [M][K], Bt [N][K] half, row-major.
// 128x128x64 CTA tile, 128 thr (4 warps, 64x64 warp tile), 3-stage cp.async,
// software-pipelined (double-buffered) ldmatrix fragments.
// MODE 0: fp32 C, direct bias.
// MODE 1: half C; bias read with inverse QKV permutation; Q cols (<1024)
//         scaled by QSCALE.
// ---------------------------------------------------------------------------
template<int MODE>
__global__ __launch_bounds__(128, 2)
void gemm_f16(const __half* __restrict__ A, const __half* __restrict__ Bt,
              const float* __restrict__ bias, void* __restrict__ Cout,
              int M, int Nstride, int K)
{
    extern __shared__ __half sh[];
    __half (*As)[128][72] = (__half (*)[128][72])sh;                 // 3 stages
    __half (*Bs)[128][72] = (__half (*)[128][72])(sh + 3 * 128 * 72);

    const int tid  = threadIdx.x;
    const int bm   = blockIdx.y, bn = blockIdx.x;
    const int warp = tid >> 5, lane = tid & 31;
    const int wm   = (warp >> 1) * 64;
    const int wn   = (warp & 1) * 64;
    const int lr   = lane >> 2, lc = lane & 3;

    const int arow = wm + ((lane >> 3) & 1) * 8 + (lane & 7);   // + mt*16
    const int ach  = ((lane >> 4) & 1) * 8;                     // + kt*16
    const int brow = wn + ((lane >> 4) & 1) * 8 + (lane & 7);   // + ntp*16
    const int bch  = ((lane >> 3) & 1) * 8;                     // + kt*16

    const int ntiles = K >> 6;

    float d[4][8][4];
    #pragma unroll
    for (int mt = 0; mt < 4; mt++)
        #pragma unroll
        for (int nt = 0; nt < 8; nt++)
            #pragma unroll
            for (int r = 0; r < 4; r++) d[mt][nt][r] = 0.f;

    auto prefetch = [&](int t, int buf) {
        int k0 = t << 6;
        #pragma unroll
        for (int i = 0; i < 8; i++) {
            int idx = i * 128 + tid;
            int r = idx >> 3, c = idx & 7;
            cp16(smaddr(&As[buf][r][c * 8]), A  + (size_t)(bm * 128 + r) * K + k0 + c * 8);
        }
        #pragma unroll
        for (int i = 0; i < 8; i++) {
            int idx = i * 128 + tid;
            int r = idx >> 3, c = idx & 7;
            cp16(smaddr(&Bs[buf][r][c * 8]), Bt + (size_t)(bn * 128 + r) * K + k0 + c * 8);
        }
        CP_COMMIT();
    };

    auto load_frags = [&](int cur, int kt, uint32_t (&a)[4][4], uint32_t (&b)[8][2]) {
        #pragma unroll
        for (int mt = 0; mt < 4; mt++)
            ldsm_x4(a[mt], smaddr(&As[cur][arow + mt * 16][kt * 16 + ach]));
        #pragma unroll
        for (int ntp = 0; ntp < 4; ntp++) {
            uint32_t t4[4];
            ldsm_x4(t4, smaddr(&Bs[cur][brow + ntp * 16][kt * 16 + bch]));
            b[2 * ntp][0] = t4[0]; b[2 * ntp][1] = t4[1];
            b[2 * ntp + 1][0] = t4[2]; b[2 * ntp + 1][1] = t4[3];
        }
    };

    prefetch(0, 0);
    prefetch(1, 1);

    for (int t = 0; t < ntiles; t++) {
        int cur = t % 3;
        if (t + 1 < ntiles) { CP_WAIT(1); } else { CP_WAIT(0); }
        __syncthreads();
        if (t + 2 < ntiles) prefetch(t + 2, (t + 2) % 3);

        uint32_t a[2][4][4], b[2][8][2];
        load_frags(cur, 0, a[0], b[0]);
        #pragma unroll
        for (int kt = 0; kt < 4; kt++) {
            int cf = kt & 1;
            if (kt < 3) load_frags(cur, kt + 1, a[cf ^ 1], b[cf ^ 1]);
            #pragma unroll
            for (int mt = 0; mt < 4; mt++)
                #pragma unroll
                for (int nt = 0; nt < 8; nt++)
                    mma_f16(d[mt][nt], a[cf][mt][0], a[cf][mt][1],
                            a[cf][mt][2], a[cf][mt][3], b[cf][nt][0], b[cf][nt][1]);
        }
    }

    #pragma unroll
    for (int mt = 0; mt < 4; mt++) {
        #pragma unroll
        for (int nt = 0; nt < 8; nt++) {
            int row  = bm * 128 + wm + mt * 16 + lr;
            int colg = bn * 128 + wn + nt * 8 + 2 * lc;
            float2 bv;
            if (MODE == 1) {   // inverse QKV permutation of bias index
                int map = ((colg & 1023) >> 6) * 192 + (colg >> 10) * 64 + (colg & 63);
                bv = *(const float2*)(bias + map);
            } else {
                bv = *(const float2*)(bias + colg);
            }
            float e0 = d[mt][nt][0] + bv.x, e1 = d[mt][nt][1] + bv.y;
            float e2 = d[mt][nt][2] + bv.x, e3 = d[mt][nt][3] + bv.y;
            if (MODE == 0) {
                float* C = (float*)Cout;
                *(float2*)(C + (size_t)row * Nstride + colg)       = make_float2(e0, e1);
                *(float2*)(C + (size_t)(row + 8) * Nstride + colg) = make_float2(e2, e3);
            } else {
                float s = (colg < 1024) ? QSCALE : 1.0f;   // pre-scale Q (log2 domain)
                __half* C = (__half*)Cout;
                *(__half2*)(C + (size_t)row * Nstride + colg) =
                    __floats2half2_rn(e0 * s, e1 * s);
                *(__half2*)(C + (size_t)(row + 8) * Nstride + colg) =
                    __floats2half2_rn(e2 * s, e3 * s);
            }
        }
    }
}

// ---------------------------------------------------------------------------
// Flash attention, fp16 mma + ldmatrix. ONLINE softmax, l via ones-column
// mma with COMPILE-TIME-CONSTANT B fragments (no smem ones region, no 5th
// LDSM). V staged natural [key][d], B-frags via ldmatrix.trans.
// 128-key stages (2 x 64-key sub-blocks), 2-stage cp.async.
// grid=(SEQ/128, NH, NB), block=128 (4 warps x 32 q-rows).
// smem: Qs[128][72] | Ks[2][128][72] | Vs[2][128][72]  = 92160 B
// ---------------------------------------------------------------------------
__global__ __launch_bounds__(128, 2)
void attn_f16(const __half* __restrict__ Qkv, __half* __restrict__ Out)
{
    extern __shared__ __half smp[];
    __half* Qs = smp;                                          // [128][72]
    __half (*Ks)[128][72] = (__half (*)[128][72])(smp + 128 * 72);
    __half (*Vs)[128][72] = (__half (*)[128][72])(smp + 128 * 72 + 2 * 128 * 72);

    const int qb = blockIdx.x, h = blockIdx.y, n = blockIdx.z;
    const int tid = threadIdx.x, warp = tid >> 5, lane = tid & 31;
    const int lr = lane >> 2, lc = lane & 3;

    const __half* Qbase = Qkv + (size_t)(n * SEQ) * H3 + h * 64;
    const __half* Kbase = Qbase + 1024;
    const __half* Vbase = Qbase + 2048;

    const int ar  = warp * 32 + ((lane >> 3) & 1) * 8 + (lane & 7);  // + mi*16
    const int ach = ((lane >> 4) & 1) * 8;
    const int br  = ((lane >> 4) & 1) * 8 + (lane & 7);              // K frag row
    const int bch = ((lane >> 3) & 1) * 8;
    const int vtr = ((lane >> 3) & 1) * 8 + (lane & 7);              // V trans row (k)
    const int vtc = ((lane >> 4) & 1) * 8;                           // V trans col (n)

    // constant l-fragment: B[k][64]=1, else 0 -> b0=b1=(lr==0)?(1,1):(0,0)
    const uint32_t lfrag = (lr == 0) ? 0x3C003C00u : 0u;

    // one stage = 128 keys of K rows and V rows (both [key][d])
    auto prefetch_kv = [&](int t, int buf) {
        #pragma unroll
        for (int i = 0; i < 8; i++) {
            int idx = i * 128 + tid;
            int r = idx >> 3, c = idx & 7;
            cp16(smaddr(&Ks[buf][r][c * 8]),
                 Kbase + (size_t)(t * 128 + r) * H3 + c * 8);
            cp16(smaddr(&Vs[buf][r][c * 8]),
                 Vbase + (size_t)(t * 128 + r) * H3 + c * 8);
        }
        CP_COMMIT();
    };

    // V B-fragments via ldmatrix.trans from [key][d] rows (d 0..63 only)
    auto load_vfrags = [&](int cur, int j, int kt, uint32_t (&bb)[8][2]) {
        #pragma unroll
        for (int ntp = 0; ntp < 4; ntp++) {
            uint32_t t4[4];
            ldsm_x4_t(t4, smaddr(&Vs[cur][j * 64 + kt * 16 + vtr][ntp * 16 + vtc]));
            bb[2 * ntp][0] = t4[0]; bb[2 * ntp][1] = t4[1];
            bb[2 * ntp + 1][0] = t4[2]; bb[2 * ntp + 1][1] = t4[3];
        }
    };

    // stage Q (128 rows) + kv stage 0 in one commit group
    #pragma unroll
    for (int i = 0; i < 8; i++) {
        int idx = i * 128 + tid;
        int r = idx >> 3, c = idx & 7;
        cp16(smaddr(&Qs[r * 72 + c * 8]),
             Qbase + (size_t)(qb * 128 + r) * H3 + c * 8);
    }
    prefetch_kv(0, 0);

    CP_WAIT(0);
    __syncthreads();

    uint32_t aq[4][2][4];  // [kt][mi]
    #pragma unroll
    for (int kt = 0; kt < 4; kt++)
        #pragma unroll
        for (int mi = 0; mi < 2; mi++)
            ldsm_x4(aq[kt][mi], smaddr(&Qs[(ar + mi * 16) * 72 + kt * 16 + ach]));

    float o[2][9][4];
    #pragma unroll
    for (int mi = 0; mi < 2; mi++)
        #pragma unroll
        for (int nt = 0; nt < 9; nt++)
            #pragma unroll
            for (int r = 0; r < 4; r++) o[mi][nt][r] = 0.f;
    float mm[2][2] = {{-1e30f, -1e30f}, {-1e30f, -1e30f}};

    const int NT = SEQ / 128;
    for (int t = 0; t < NT; t++) {
        int cur = t & 1;
        if (t > 0) {
            CP_WAIT(0);
            __syncthreads();
        }
        if (t + 1 < NT) prefetch_kv(t + 1, cur ^ 1);

        #pragma unroll
        for (int j = 0; j < 2; j++) {   // two 64-key sub-blocks
            // S = Q @ K^T (log2 domain); K fragments double-buffered
            float s[2][8][4];
            #pragma unroll
            for (int mi = 0; mi < 2; mi++)
                #pragma unroll
                for (int nt = 0; nt < 8; nt++)
                    #pragma unroll
                    for (int r = 0; r < 4; r++) s[mi][nt][r] = 0.f;
            uint32_t kb[2][8][2];
            {
                uint32_t t4[4];
                #pragma unroll
                for (int ntp = 0; ntp < 4; ntp++) {
                    ldsm_x4(t4, smaddr(&Ks[cur][j * 64 + br + ntp * 16][bch]));
                    kb[0][2 * ntp][0] = t4[0]; kb[0][2 * ntp][1] = t4[1];
                    kb[0][2 * ntp + 1][0] = t4[2]; kb[0][2 * ntp + 1][1] = t4[3];
                }
            }
            #pragma unroll
            for (int kt = 0; kt < 4; kt++) {
                int cf = kt & 1;
                if (kt < 3) {
                    uint32_t t4[4];
                    #pragma unroll
                    for (int ntp = 0; ntp < 4; ntp++) {
                        ldsm_x4(t4, smaddr(&Ks[cur][j * 64 + br + ntp * 16]
                                                   [(kt + 1) * 16 + bch]));
                        kb[cf ^ 1][2 * ntp][0] = t4[0];
                        kb[cf ^ 1][2 * ntp][1] = t4[1];
                        kb[cf ^ 1][2 * ntp + 1][0] = t4[2];
                        kb[cf ^ 1][2 * ntp + 1][1] = t4[3];
                    }
                }
                #pragma unroll
                for (int mi = 0; mi < 2; mi++)
                    #pragma unroll
                    for (int nt = 0; nt < 8; nt++)
                        mma_f16(s[mi][nt], aq[kt][mi][0], aq[kt][mi][1],
                                aq[kt][mi][2], aq[kt][mi][3],
                                kb[cf][nt][0], kb[cf][nt][1]);
            }

            // online softmax (fp32 stats; exp2) per m-tile
            float al[2][2];
            #pragma unroll
            for (int mi = 0; mi < 2; mi++) {
                float mx0 = s[mi][0][0], mx1 = s[mi][0][2];
                #pragma unroll
                for (int nt = 0; nt < 8; nt++) {
                    mx0 = fmaxf(mx0, fmaxf(s[mi][nt][0], s[mi][nt][1]));
                    mx1 = fmaxf(mx1, fmaxf(s[mi][nt][2], s[mi][nt][3]));
                }
                mx0 = fmaxf(mx0, __shfl_xor_sync(0xffffffffu, mx0, 1));
                mx0 = fmaxf(mx0, __shfl_xor_sync(0xffffffffu, mx0, 2));
                mx1 = fmaxf(mx1, __shfl_xor_sync(0xffffffffu, mx1, 1));
                mx1 = fmaxf(mx1, __shfl_xor_sync(0xffffffffu, mx1, 2));
                float nm0 = fmaxf(mm[mi][0], mx0), nm1 = fmaxf(mm[mi][1], mx1);
                al[mi][0] = ex2(mm[mi][0] - nm0);
                al[mi][1] = ex2(mm[mi][1] - nm1);
                mm[mi][0] = nm0; mm[mi][1] = nm1;
            }
            if (!__all_sync(0xffffffffu,
                            (al[0][0] == 1.f) && (al[0][1] == 1.f) &&
                            (al[1][0] == 1.f) && (al[1][1] == 1.f))) {
                #pragma unroll
                for (int mi = 0; mi < 2; mi++)
                    #pragma unroll
                    for (int nt = 0; nt < 9; nt++) {
                        o[mi][nt][0] *= al[mi][0]; o[mi][nt][1] *= al[mi][0];
                        o[mi][nt][2] *= al[mi][1]; o[mi][nt][3] *= al[mi][1];
                    }
            }

            // P = 2^(s-m), packed f16x2, register-resident
            uint32_t p01[2][8], p23[2][8];
            #pragma unroll
            for (int mi = 0; mi < 2; mi++)
                #pragma unroll
                for (int nt = 0; nt < 8; nt++) {
                    p01[mi][nt] = ex2_h2(s[mi][nt][0] - mm[mi][0],
                                         s[mi][nt][1] - mm[mi][0]);
                    p23[mi][nt] = ex2_h2(s[mi][nt][2] - mm[mi][1],
                                         s[mi][nt][3] - mm[mi][1]);
                }

            // O += P @ V ; l via constant ones-fragment (nt=8)
            uint32_t bb[2][8][2];
            load_vfrags(cur, j, 0, bb[0]);
            #pragma unroll
            for (int kt = 0; kt < 4; kt++) {
                int cf = kt & 1;
                if (kt < 3) load_vfrags(cur, j, kt + 1, bb[cf ^ 1]);
                #pragma unroll
                for (int mi = 0; mi < 2; mi++) {
                    uint32_t a0 = p01[mi][2 * kt],     a1 = p23[mi][2 * kt];
                    uint32_t a2 = p01[mi][2 * kt + 1], a3 = p23[mi][2 * kt + 1];
                    #pragma unroll
                    for (int nt = 0; nt < 8; nt++)
                        mma_f16(o[mi][nt], a0, a1, a2, a3, bb[cf][nt][0], bb[cf][nt][1]);
                    mma_f16(o[mi][8], a0, a1, a2, a3, lfrag, lfrag);
                }
            }
        }
    }

    // epilogue: l in o[mi][8][0]/[2] of lc==0 lanes
    #pragma unroll
    for (int mi = 0; mi < 2; mi++) {
        float l0 = __shfl_sync(0xffffffffu, o[mi][8][0], lane & 28);
        float l1 = __shfl_sync(0xffffffffu, o[mi][8][2], lane & 28);
        float inv0 = 1.f / l0, inv1 = 1.f / l1;
        int row0 = qb * 128 + warp * 32 + mi * 16 + lr;
        __half* op0 = Out + (size_t)(n * SEQ + row0) * EDIM + h * 64;
        __half* op1 = op0 + (size_t)8 * EDIM;
        #pragma unroll
        for (int nt = 0; nt < 8; nt++) {
            int col = nt * 8 + 2 * lc;
            *(__half2*)(op0 + col) = __floats2half2_rn(o[mi][nt][0] * inv0,
                                                       o[mi][nt][1] * inv0);
            *(__half2*)(op1 + col) = __floats2half2_rn(o[mi][nt][2] * inv1,
                                                       o[mi][nt][3] * inv1);
        }
    }
}

// ---------------------------------------------------------------------------
extern "C" void kernel_launch(void* const* d_in, const int* in_sizes, int n_in,
                              void* d_out, int out_size)
{
    const float* x  = (const float*)d_in[0];
    const float* W1 = (const float*)d_in[1];
    const float* b1 = (const float*)d_in[2];
    const float* W2 = (const float*)d_in[3];
    const float* b2 = (const float*)d_in[4];
    float* out = (float*)d_out;

    __half *QKVbuf, *Abuf, *Xbuf, *W1Tbuf, *W2Tbuf;
    cudaGetSymbolAddress((void**)&QKVbuf, g_QKV);
    cudaGetSymbolAddress((void**)&Abuf,   g_ATT);
    cudaGetSymbolAddress((void**)&Xbuf,   g_X);
    cudaGetSymbolAddress((void**)&W1Tbuf, g_W1T);
    cudaGetSymbolAddress((void**)&W2Tbuf, g_W2T);

    const int gemm_smem = 3 * 2 * 128 * 72 * 2;          // 110592 B
    const int attn_smem = 5 * 128 * 72 * 2;              // 92160 B
    static bool attr_done = false;
    if (!attr_done) {
        cudaFuncSetAttribute(gemm_f16<0>,
                             cudaFuncAttributeMaxDynamicSharedMemorySize, gemm_smem);
        cudaFuncSetAttribute(gemm_f16<1>,
                             cudaFuncAttributeMaxDynamicSharedMemorySize, gemm_smem);
        cudaFuncSetAttribute(attn_f16,
                             cudaFuncAttributeMaxDynamicSharedMemorySize, attn_smem);
        attr_done = true;
    }

    // merged pre-pass: x -> half; W1 -> permuted W1T; W2 -> W2T
    prepass<<<XB + W1B + W2B, 256>>>(x, W1, W2, Xbuf, W1Tbuf, W2Tbuf);

    // 1) QKV projection: Q(scaled)|K|V rows -> g_QKV
    gemm_f16<1><<<dim3(H3 / 128, NTOK / 128), 128, gemm_smem>>>(
        Xbuf, W1Tbuf, b1, QKVbuf, NTOK, H3, EDIM);
    // 2) attention -> g_ATT (half)
    attn_f16<<<dim3(SEQ / 128, NH, NB), 128, attn_smem>>>(QKVbuf, Abuf);
    // 3) output projection -> fp32 out
    gemm_f16<0><<<dim3(EDIM / 128, NTOK / 128), 128, gemm_smem>>>(
        Abuf, W2Tbuf, b2, out, NTOK, EDIM, EDIM);
}